// round 1
// baseline (speedup 1.0000x reference)
#include <cuda_runtime.h>
#include <math.h>

// ---------------- problem constants ----------------
#define BATCH 64
#define SEQ   197
#define DMODEL 768
#define NBLK  12
#define NHEAD 12
#define DHEAD 64
#define FFDIM 3072
#define NOUT  1000
#define NTOK  196          // patches per image
#define M_ALL (BATCH*SEQ)  // 12608
#define M_PAT (BATCH*NTOK) // 12544

// ---------------- device scratch (static, allocation-free) ----------------
__device__ float g_patches[(size_t)M_PAT * DMODEL];
__device__ float g_tok    [(size_t)M_PAT * DMODEL];
__device__ float g_x      [(size_t)M_ALL * DMODEL];
__device__ float g_h      [(size_t)M_ALL * DMODEL];
__device__ float g_qkv    [(size_t)M_ALL * 3 * DMODEL];
__device__ float g_y      [(size_t)M_ALL * DMODEL];
__device__ float g_ff     [(size_t)M_ALL * FFDIM];
__device__ float g_logits [(size_t)BATCH * NOUT];

// ---------------- patch extraction ----------------
__global__ __launch_bounds__(256) void patch_kernel(const float* __restrict__ img,
                                                    float* __restrict__ out) {
    int idx = blockIdx.x * 256 + threadIdx.x;
    if (idx >= M_PAT * DMODEL) return;
    int i   = idx % DMODEL;        // c*256 + iy*16 + ix
    int row = idx / DMODEL;        // b*196 + p
    int p   = row % NTOK;
    int b   = row / NTOK;
    int c   = i >> 8;
    int rem = i & 255;
    int iy  = rem >> 4;
    int ix  = rem & 15;
    int py  = p / 14, px = p % 14;
    out[idx] = img[(((size_t)(b * 3 + c) * 224) + py * 16 + iy) * 224 + px * 16 + ix];
}

// ---------------- generic SGEMM: C = act(A@B + bias) (+res) ----------------
// A: MxK row-major, B: KxN row-major, bias: N, res: MxN (optional), C: MxN
// act: 0 = none, 1 = gelu(tanh approx)
__global__ __launch_bounds__(256) void sgemm_kernel(
    const float* __restrict__ A, const float* __restrict__ B,
    const float* __restrict__ bias, const float* __restrict__ res,
    float* __restrict__ C, int M, int N, int K, int act)
{
    __shared__ float As[8][128];
    __shared__ float Bs[8][128];
    int tid = threadIdx.x;
    int tx = tid & 15, ty = tid >> 4;          // 16x16 thread grid, 8x8 per thread
    int rowStart = blockIdx.y * 128;
    int colStart = blockIdx.x * 128;

    float acc[8][8];
#pragma unroll
    for (int i = 0; i < 8; i++)
#pragma unroll
        for (int j = 0; j < 8; j++) acc[i][j] = 0.0f;

    int arow = tid >> 1,  acol = (tid & 1) * 4;   // A tile 128x8 via float4
    int brow = tid >> 5,  bcol = (tid & 31) * 4;  // B tile 8x128 via float4

    for (int k0 = 0; k0 < K; k0 += 8) {
        float4 a4 = make_float4(0.f, 0.f, 0.f, 0.f);
        if (rowStart + arow < M)
            a4 = *reinterpret_cast<const float4*>(A + (size_t)(rowStart + arow) * K + k0 + acol);
        As[acol + 0][arow] = a4.x;
        As[acol + 1][arow] = a4.y;
        As[acol + 2][arow] = a4.z;
        As[acol + 3][arow] = a4.w;

        float4 b4 = *reinterpret_cast<const float4*>(B + (size_t)(k0 + brow) * N + colStart + bcol);
        *reinterpret_cast<float4*>(&Bs[brow][bcol]) = b4;
        __syncthreads();

#pragma unroll
        for (int kk = 0; kk < 8; kk++) {
            float ar[8], br[8];
            *reinterpret_cast<float4*>(&ar[0]) = *reinterpret_cast<const float4*>(&As[kk][ty * 8]);
            *reinterpret_cast<float4*>(&ar[4]) = *reinterpret_cast<const float4*>(&As[kk][ty * 8 + 4]);
            *reinterpret_cast<float4*>(&br[0]) = *reinterpret_cast<const float4*>(&Bs[kk][tx * 8]);
            *reinterpret_cast<float4*>(&br[4]) = *reinterpret_cast<const float4*>(&Bs[kk][tx * 8 + 4]);
#pragma unroll
            for (int i = 0; i < 8; i++)
#pragma unroll
                for (int j = 0; j < 8; j++) acc[i][j] = fmaf(ar[i], br[j], acc[i][j]);
        }
        __syncthreads();
    }

#pragma unroll
    for (int i = 0; i < 8; i++) {
        int row = rowStart + ty * 8 + i;
        if (row >= M) continue;
#pragma unroll
        for (int j = 0; j < 8; j++) {
            int col = colStart + tx * 8 + j;
            if (col >= N) continue;
            float v = acc[i][j] + bias[col];
            if (act == 1) {
                float u = v;
                float inner = 0.7978845608028654f * (u + 0.044715f * u * u * u);
                v = 0.5f * u * (1.0f + tanhf(inner));
            }
            if (res) v += res[(size_t)row * N + col];
            C[(size_t)row * N + col] = v;
        }
    }
}

// ---------------- embed: concat(cls, tokens) + sinusoidal pos ----------------
__global__ __launch_bounds__(256) void embed_kernel(const float* __restrict__ tok,
                                                    const float* __restrict__ v_class,
                                                    float* __restrict__ x) {
    int idx = blockIdx.x * 256 + threadIdx.x;
    if (idx >= M_ALL * DMODEL) return;
    int d = idx % DMODEL;
    int r = idx / DMODEL;
    int s = r % SEQ;
    int b = r / SEQ;
    float t = (s == 0) ? v_class[d] : tok[(size_t)(b * NTOK + s - 1) * DMODEL + d];
    float expo = (float)d / (float)DMODEL;
    float ang = (float)s / powf(10000.0f, expo);
    float pe = ((d & 1) == 0) ? sinf(ang) : cosf(ang);
    x[idx] = t + pe;
}

// ---------------- LayerNorm (two-pass, per row) ----------------
__global__ __launch_bounds__(256) void ln_kernel(const float* __restrict__ x,
                                                 const float* __restrict__ gamma,
                                                 const float* __restrict__ beta,
                                                 float* __restrict__ out) {
    int row = blockIdx.x;
    int tid = threadIdx.x;
    const float* xr = x + (size_t)row * DMODEL;
    float v0 = xr[tid], v1 = xr[tid + 256], v2 = xr[tid + 512];

    __shared__ float red[256];
    red[tid] = v0 + v1 + v2;
    __syncthreads();
    for (int off = 128; off > 0; off >>= 1) {
        if (tid < off) red[tid] += red[tid + off];
        __syncthreads();
    }
    float mean = red[0] * (1.0f / DMODEL);
    __syncthreads();

    float d0 = v0 - mean, d1 = v1 - mean, d2 = v2 - mean;
    red[tid] = d0 * d0 + d1 * d1 + d2 * d2;
    __syncthreads();
    for (int off = 128; off > 0; off >>= 1) {
        if (tid < off) red[tid] += red[tid + off];
        __syncthreads();
    }
    float var = red[0] * (1.0f / DMODEL);
    float rstd = rsqrtf(var + 1e-5f);

    float* orow = out + (size_t)row * DMODEL;
    orow[tid]       = d0 * rstd * gamma[tid]       + beta[tid];
    orow[tid + 256] = d1 * rstd * gamma[tid + 256] + beta[tid + 256];
    orow[tid + 512] = d2 * rstd * gamma[tid + 512] + beta[tid + 512];
}

// ---------------- fused attention per (b,h) ----------------
// smem: K[197][65], V[197][65], P[8][197], Q[8][64]
#define ATTN_SMEM ((2 * 197 * 65 + 8 * 197 + 8 * 64) * sizeof(float))
__global__ __launch_bounds__(256) void attn_kernel(const float* __restrict__ qkv,
                                                   float* __restrict__ y) {
    extern __shared__ float sm[];
    float* Ks = sm;                     // 197*65
    float* Vs = Ks + 197 * 65;          // 197*65
    float* Ps = Vs + 197 * 65;          // 8*197
    float* Qs = Ps + 8 * 197;           // 8*64

    int h = blockIdx.x;
    int b = blockIdx.y;
    int tid = threadIdx.x;

    // stage K and V for this (b,h)
    for (int idx = tid; idx < SEQ * DHEAD; idx += 256) {
        int t = idx >> 6, d = idx & 63;
        const float* base = qkv + (size_t)(b * SEQ + t) * (3 * DMODEL) + h * DHEAD + d;
        Ks[t * 65 + d] = base[DMODEL];       // K at offset 768
        Vs[t * 65 + d] = base[2 * DMODEL];   // V at offset 1536
    }
    __syncthreads();

    int warp = tid >> 5, lane = tid & 31;
    const float scale = 0.125f; // 1/sqrt(64)

    for (int s = warp; s < SEQ; s += 8) {
        // stage Q row
        const float* qp = qkv + (size_t)(b * SEQ + s) * (3 * DMODEL) + h * DHEAD;
        Qs[warp * 64 + lane]      = qp[lane];
        Qs[warp * 64 + lane + 32] = qp[lane + 32];
        __syncwarp();

        // scores for t = lane + 32j
        float sc[7];
        float m = -1e30f;
#pragma unroll
        for (int j = 0; j < 7; j++) {
            int t = lane + 32 * j;
            if (t < SEQ) {
                float a = 0.0f;
#pragma unroll
                for (int d = 0; d < 64; d++) a = fmaf(Qs[warp * 64 + d], Ks[t * 65 + d], a);
                sc[j] = a * scale;
                m = fmaxf(m, sc[j]);
            } else {
                sc[j] = -1e30f;
            }
        }
#pragma unroll
        for (int off = 16; off > 0; off >>= 1) m = fmaxf(m, __shfl_xor_sync(0xffffffffu, m, off));

        float sum = 0.0f;
#pragma unroll
        for (int j = 0; j < 7; j++) {
            int t = lane + 32 * j;
            if (t < SEQ) {
                float e = expf(sc[j] - m);
                Ps[warp * SEQ + t] = e;
                sum += e;
            }
        }
#pragma unroll
        for (int off = 16; off > 0; off >>= 1) sum += __shfl_xor_sync(0xffffffffu, sum, off);
        float inv = 1.0f / sum;
        __syncwarp();

        // y[d] = sum_t p[t] * V[t][d]; lane owns d = lane, lane+32
        float y0 = 0.0f, y1 = 0.0f;
        for (int t = 0; t < SEQ; t++) {
            float p = Ps[warp * SEQ + t];
            y0 = fmaf(p, Vs[t * 65 + lane], y0);
            y1 = fmaf(p, Vs[t * 65 + lane + 32], y1);
        }
        float* yr = y + (size_t)(b * SEQ + s) * DMODEL + h * DHEAD;
        yr[lane]      = y0 * inv;
        yr[lane + 32] = y1 * inv;
        __syncwarp();
    }
}

// ---------------- KAN head: logits = einsum(sin(x*f+phi), amp) ----------------
__global__ __launch_bounds__(256) void head_kernel(const float* __restrict__ x,
                                                   const float* __restrict__ amp,
                                                   float* __restrict__ logits) {
    __shared__ float sines[4 * DMODEL];
    int b = blockIdx.x;
    int tid = threadIdx.x;
    const float* xr = x + (size_t)b * SEQ * DMODEL;  // cls token (s=0)
    const float PI = 3.14159265358979323846f;
    for (int i = tid; i < DMODEL; i += 256) {
        float xv = xr[i];
        float ph = (float)i * (PI / (float)DMODEL);
#pragma unroll
        for (int g = 0; g < 4; g++) sines[g * DMODEL + i] = sinf(xv * (float)(g + 1) + ph);
    }
    __syncthreads();

    int warp = tid >> 5, lane = tid & 31;
    int o = blockIdx.y * 8 + warp;
    if (o < NOUT) {
        const float* ar = amp + (size_t)o * 4 * DMODEL;
        float acc = 0.0f;
        for (int i = lane; i < 4 * DMODEL; i += 32) acc = fmaf(sines[i], ar[i], acc);
#pragma unroll
        for (int off = 16; off > 0; off >>= 1) acc += __shfl_xor_sync(0xffffffffu, acc, off);
        if (lane == 0) logits[(size_t)b * NOUT + o] = acc * (1.0f / 55.42562584220407f); // 1/sqrt(3072)
    }
}

// ---------------- final softmax over 1000 classes ----------------
__global__ __launch_bounds__(256) void softmax_kernel(const float* __restrict__ logits,
                                                      float* __restrict__ out) {
    int b = blockIdx.x;
    int tid = threadIdx.x;
    const float* lr = logits + (size_t)b * NOUT;
    __shared__ float red[256];

    float m = -1e30f;
    for (int i = tid; i < NOUT; i += 256) m = fmaxf(m, lr[i]);
    red[tid] = m;
    __syncthreads();
    for (int off = 128; off > 0; off >>= 1) {
        if (tid < off) red[tid] = fmaxf(red[tid], red[tid + off]);
        __syncthreads();
    }
    m = red[0];
    __syncthreads();

    float s = 0.0f;
    for (int i = tid; i < NOUT; i += 256) s += expf(lr[i] - m);
    red[tid] = s;
    __syncthreads();
    for (int off = 128; off > 0; off >>= 1) {
        if (tid < off) red[tid] += red[tid + off];
        __syncthreads();
    }
    float inv = 1.0f / red[0];

    float* orow = out + (size_t)b * NOUT;
    for (int i = tid; i < NOUT; i += 256) orow[i] = expf(lr[i] - m) * inv;
}

// ---------------- launch ----------------
extern "C" void kernel_launch(void* const* d_in, const int* in_sizes, int n_in,
                              void* d_out, int out_size) {
    (void)in_sizes; (void)n_in; (void)out_size;
    const float* images    = (const float*)d_in[0];
    const float* v_class   = (const float*)d_in[1];
    const float* W_map     = (const float*)d_in[2];
    const float* b_map     = (const float*)d_in[3];
    const float* ln1_scale = (const float*)d_in[4];
    const float* ln1_bias  = (const float*)d_in[5];
    const float* Wqkv      = (const float*)d_in[6];
    const float* bqkv      = (const float*)d_in[7];
    const float* Wo        = (const float*)d_in[8];
    const float* bo        = (const float*)d_in[9];
    const float* ln2_scale = (const float*)d_in[10];
    const float* ln2_bias  = (const float*)d_in[11];
    const float* Wmlp1     = (const float*)d_in[12];
    const float* bmlp1     = (const float*)d_in[13];
    const float* Wmlp2     = (const float*)d_in[14];
    const float* bmlp2     = (const float*)d_in[15];
    const float* kan_amp   = (const float*)d_in[16];
    float* out = (float*)d_out;

    void *pp, *pt, *px, *ph, *pq, *py, *pf, *pl;
    cudaGetSymbolAddress(&pp, g_patches);
    cudaGetSymbolAddress(&pt, g_tok);
    cudaGetSymbolAddress(&px, g_x);
    cudaGetSymbolAddress(&ph, g_h);
    cudaGetSymbolAddress(&pq, g_qkv);
    cudaGetSymbolAddress(&py, g_y);
    cudaGetSymbolAddress(&pf, g_ff);
    cudaGetSymbolAddress(&pl, g_logits);
    float* patches = (float*)pp;
    float* tok     = (float*)pt;
    float* x       = (float*)px;
    float* h       = (float*)ph;
    float* qkv     = (float*)pq;
    float* y       = (float*)py;
    float* ff      = (float*)pf;
    float* logits  = (float*)pl;

    cudaFuncSetAttribute(attn_kernel, cudaFuncAttributeMaxDynamicSharedMemorySize, (int)ATTN_SMEM);

    // patch extraction + patch embedding GEMM + pos embed
    patch_kernel<<<(M_PAT * DMODEL + 255) / 256, 256>>>(images, patches);
    {
        dim3 grid((DMODEL + 127) / 128, (M_PAT + 127) / 128);
        sgemm_kernel<<<grid, 256>>>(patches, W_map, b_map, nullptr, tok,
                                    M_PAT, DMODEL, DMODEL, 0);
    }
    embed_kernel<<<(M_ALL * DMODEL + 255) / 256, 256>>>(tok, v_class, x);

    dim3 gQKV((3 * DMODEL + 127) / 128, (M_ALL + 127) / 128);
    dim3 gD  ((DMODEL + 127) / 128,     (M_ALL + 127) / 128);
    dim3 gFF ((FFDIM + 127) / 128,      (M_ALL + 127) / 128);

    for (int blk = 0; blk < NBLK; blk++) {
        const float* g1 = ln1_scale + (size_t)blk * DMODEL;
        const float* b1 = ln1_bias  + (size_t)blk * DMODEL;
        const float* wq = Wqkv + (size_t)blk * DMODEL * 3 * DMODEL;
        const float* bq = bqkv + (size_t)blk * 3 * DMODEL;
        const float* wo = Wo   + (size_t)blk * DMODEL * DMODEL;
        const float* bo_ = bo  + (size_t)blk * DMODEL;
        const float* g2 = ln2_scale + (size_t)blk * DMODEL;
        const float* b2 = ln2_bias  + (size_t)blk * DMODEL;
        const float* w1 = Wmlp1 + (size_t)blk * DMODEL * FFDIM;
        const float* bm1 = bmlp1 + (size_t)blk * FFDIM;
        const float* w2 = Wmlp2 + (size_t)blk * FFDIM * DMODEL;
        const float* bm2 = bmlp2 + (size_t)blk * DMODEL;

        ln_kernel<<<M_ALL, 256>>>(x, g1, b1, h);
        sgemm_kernel<<<gQKV, 256>>>(h, wq, bq, nullptr, qkv, M_ALL, 3 * DMODEL, DMODEL, 0);
        attn_kernel<<<dim3(NHEAD, BATCH), 256, ATTN_SMEM>>>(qkv, y);
        sgemm_kernel<<<gD, 256>>>(y, wo, bo_, x, x, M_ALL, DMODEL, DMODEL, 0);
        ln_kernel<<<M_ALL, 256>>>(x, g2, b2, h);
        sgemm_kernel<<<gFF, 256>>>(h, w1, bm1, nullptr, ff, M_ALL, FFDIM, DMODEL, 1);
        sgemm_kernel<<<gD, 256>>>(ff, w2, bm2, x, x, M_ALL, DMODEL, FFDIM, 0);
    }

    head_kernel<<<dim3(BATCH, 125), 256>>>(x, kan_amp, logits);
    softmax_kernel<<<BATCH, 256>>>(logits, out);
}

// round 2
// speedup vs baseline: 1.0010x; 1.0010x over previous
#include <cuda_runtime.h>
#include <math.h>

// ---------------- problem constants ----------------
#define BATCH 64
#define SEQ   197
#define DMODEL 768
#define NBLK  12
#define NHEAD 12
#define DHEAD 64
#define FFDIM 3072
#define NOUT  1000
#define NTOK  196          // patches per image
#define M_ALL (BATCH*SEQ)  // 12608
#define M_PAT (BATCH*NTOK) // 12544

// ---------------- device scratch (static, allocation-free) ----------------
__device__ float g_patches[(size_t)M_PAT * DMODEL];
__device__ float g_tok    [(size_t)M_PAT * DMODEL];
__device__ float g_x      [(size_t)M_ALL * DMODEL];
__device__ float g_h      [(size_t)M_ALL * DMODEL];
__device__ float g_qkv    [(size_t)M_ALL * 3 * DMODEL];
__device__ float g_y      [(size_t)M_ALL * DMODEL];
__device__ float g_ff     [(size_t)M_ALL * FFDIM];
__device__ float g_logits [(size_t)BATCH * NOUT];

// ---------------- patch extraction ----------------
__global__ __launch_bounds__(256) void patch_kernel(const float* __restrict__ img,
                                                    float* __restrict__ out) {
    int idx = blockIdx.x * 256 + threadIdx.x;
    if (idx >= M_PAT * DMODEL) return;
    int i   = idx % DMODEL;        // c*256 + iy*16 + ix
    int row = idx / DMODEL;        // b*196 + p
    int p   = row % NTOK;
    int b   = row / NTOK;
    int c   = i >> 8;
    int rem = i & 255;
    int iy  = rem >> 4;
    int ix  = rem & 15;
    int py  = p / 14, px = p % 14;
    out[idx] = img[(((size_t)(b * 3 + c) * 224) + py * 16 + iy) * 224 + px * 16 + ix];
}

// ---------------- generic SGEMM: C = act(A@B + bias) (+res) ----------------
// A: MxK row-major, B: KxN row-major, bias: N, res: MxN (optional), C: MxN
// act: 0 = none, 1 = gelu(tanh approx)
__global__ __launch_bounds__(256) void sgemm_kernel(
    const float* __restrict__ A, const float* __restrict__ B,
    const float* __restrict__ bias, const float* __restrict__ res,
    float* __restrict__ C, int M, int N, int K, int act)
{
    __shared__ float As[8][128];
    __shared__ float Bs[8][128];
    int tid = threadIdx.x;
    int tx = tid & 15, ty = tid >> 4;          // 16x16 thread grid, 8x8 per thread
    int rowStart = blockIdx.y * 128;
    int colStart = blockIdx.x * 128;

    float acc[8][8];
#pragma unroll
    for (int i = 0; i < 8; i++)
#pragma unroll
        for (int j = 0; j < 8; j++) acc[i][j] = 0.0f;

    int arow = tid >> 1,  acol = (tid & 1) * 4;   // A tile 128x8 via float4
    int brow = tid >> 5,  bcol = (tid & 31) * 4;  // B tile 8x128 via float4

    for (int k0 = 0; k0 < K; k0 += 8) {
        float4 a4 = make_float4(0.f, 0.f, 0.f, 0.f);
        if (rowStart + arow < M)
            a4 = *reinterpret_cast<const float4*>(A + (size_t)(rowStart + arow) * K + k0 + acol);
        As[acol + 0][arow] = a4.x;
        As[acol + 1][arow] = a4.y;
        As[acol + 2][arow] = a4.z;
        As[acol + 3][arow] = a4.w;

        float4 b4 = *reinterpret_cast<const float4*>(B + (size_t)(k0 + brow) * N + colStart + bcol);
        *reinterpret_cast<float4*>(&Bs[brow][bcol]) = b4;
        __syncthreads();

#pragma unroll
        for (int kk = 0; kk < 8; kk++) {
            float ar[8], br[8];
            *reinterpret_cast<float4*>(&ar[0]) = *reinterpret_cast<const float4*>(&As[kk][ty * 8]);
            *reinterpret_cast<float4*>(&ar[4]) = *reinterpret_cast<const float4*>(&As[kk][ty * 8 + 4]);
            *reinterpret_cast<float4*>(&br[0]) = *reinterpret_cast<const float4*>(&Bs[kk][tx * 8]);
            *reinterpret_cast<float4*>(&br[4]) = *reinterpret_cast<const float4*>(&Bs[kk][tx * 8 + 4]);
#pragma unroll
            for (int i = 0; i < 8; i++)
#pragma unroll
                for (int j = 0; j < 8; j++) acc[i][j] = fmaf(ar[i], br[j], acc[i][j]);
        }
        __syncthreads();
    }

#pragma unroll
    for (int i = 0; i < 8; i++) {
        int row = rowStart + ty * 8 + i;
        if (row >= M) continue;
#pragma unroll
        for (int j = 0; j < 8; j++) {
            int col = colStart + tx * 8 + j;
            if (col >= N) continue;
            float v = acc[i][j] + bias[col];
            if (act == 1) {
                float u = v;
                float inner = 0.7978845608028654f * (u + 0.044715f * u * u * u);
                v = 0.5f * u * (1.0f + tanhf(inner));
            }
            if (res) v += res[(size_t)row * N + col];
            C[(size_t)row * N + col] = v;
        }
    }
}

// ---------------- embed: concat(cls, tokens) + sinusoidal pos ----------------
__global__ __launch_bounds__(256) void embed_kernel(const float* __restrict__ tok,
                                                    const float* __restrict__ v_class,
                                                    float* __restrict__ x) {
    int idx = blockIdx.x * 256 + threadIdx.x;
    if (idx >= M_ALL * DMODEL) return;
    int d = idx % DMODEL;
    int r = idx / DMODEL;
    int s = r % SEQ;
    int b = r / SEQ;
    float t = (s == 0) ? v_class[d] : tok[(size_t)(b * NTOK + s - 1) * DMODEL + d];
    float expo = (float)d / (float)DMODEL;
    float ang = (float)s / powf(10000.0f, expo);
    float pe = ((d & 1) == 0) ? sinf(ang) : cosf(ang);
    x[idx] = t + pe;
}

// ---------------- LayerNorm (two-pass, per row) ----------------
__global__ __launch_bounds__(256) void ln_kernel(const float* __restrict__ x,
                                                 const float* __restrict__ gamma,
                                                 const float* __restrict__ beta,
                                                 float* __restrict__ out) {
    int row = blockIdx.x;
    int tid = threadIdx.x;
    const float* xr = x + (size_t)row * DMODEL;
    float v0 = xr[tid], v1 = xr[tid + 256], v2 = xr[tid + 512];

    __shared__ float red[256];
    red[tid] = v0 + v1 + v2;
    __syncthreads();
    for (int off = 128; off > 0; off >>= 1) {
        if (tid < off) red[tid] += red[tid + off];
        __syncthreads();
    }
    float mean = red[0] * (1.0f / DMODEL);
    __syncthreads();

    float d0 = v0 - mean, d1 = v1 - mean, d2 = v2 - mean;
    red[tid] = d0 * d0 + d1 * d1 + d2 * d2;
    __syncthreads();
    for (int off = 128; off > 0; off >>= 1) {
        if (tid < off) red[tid] += red[tid + off];
        __syncthreads();
    }
    float var = red[0] * (1.0f / DMODEL);
    float rstd = rsqrtf(var + 1e-5f);

    float* orow = out + (size_t)row * DMODEL;
    orow[tid]       = d0 * rstd * gamma[tid]       + beta[tid];
    orow[tid + 256] = d1 * rstd * gamma[tid + 256] + beta[tid + 256];
    orow[tid + 512] = d2 * rstd * gamma[tid + 512] + beta[tid + 512];
}

// ---------------- fused attention per (b,h) ----------------
// smem: K[197][65], V[197][65], P[8][197], Q[8][64]
#define ATTN_SMEM ((2 * 197 * 65 + 8 * 197 + 8 * 64) * sizeof(float))
__global__ __launch_bounds__(256) void attn_kernel(const float* __restrict__ qkv,
                                                   float* __restrict__ y) {
    extern __shared__ float sm[];
    float* Ks = sm;                     // 197*65
    float* Vs = Ks + 197 * 65;          // 197*65
    float* Ps = Vs + 197 * 65;          // 8*197
    float* Qs = Ps + 8 * 197;           // 8*64

    int h = blockIdx.x;
    int b = blockIdx.y;
    int tid = threadIdx.x;

    // stage K and V for this (b,h)
    for (int idx = tid; idx < SEQ * DHEAD; idx += 256) {
        int t = idx >> 6, d = idx & 63;
        const float* base = qkv + (size_t)(b * SEQ + t) * (3 * DMODEL) + h * DHEAD + d;
        Ks[t * 65 + d] = base[DMODEL];       // K at offset 768
        Vs[t * 65 + d] = base[2 * DMODEL];   // V at offset 1536
    }
    __syncthreads();

    int warp = tid >> 5, lane = tid & 31;
    const float scale = 0.125f; // 1/sqrt(64)

    for (int s = warp; s < SEQ; s += 8) {
        // stage Q row
        const float* qp = qkv + (size_t)(b * SEQ + s) * (3 * DMODEL) + h * DHEAD;
        Qs[warp * 64 + lane]      = qp[lane];
        Qs[warp * 64 + lane + 32] = qp[lane + 32];
        __syncwarp();

        // scores for t = lane + 32j
        float sc[7];
        float m = -1e30f;
#pragma unroll
        for (int j = 0; j < 7; j++) {
            int t = lane + 32 * j;
            if (t < SEQ) {
                float a = 0.0f;
#pragma unroll
                for (int d = 0; d < 64; d++) a = fmaf(Qs[warp * 64 + d], Ks[t * 65 + d], a);
                sc[j] = a * scale;
                m = fmaxf(m, sc[j]);
            } else {
                sc[j] = -1e30f;
            }
        }
#pragma unroll
        for (int off = 16; off > 0; off >>= 1) m = fmaxf(m, __shfl_xor_sync(0xffffffffu, m, off));

        float sum = 0.0f;
#pragma unroll
        for (int j = 0; j < 7; j++) {
            int t = lane + 32 * j;
            if (t < SEQ) {
                float e = expf(sc[j] - m);
                Ps[warp * SEQ + t] = e;
                sum += e;
            }
        }
#pragma unroll
        for (int off = 16; off > 0; off >>= 1) sum += __shfl_xor_sync(0xffffffffu, sum, off);
        float inv = 1.0f / sum;
        __syncwarp();

        // y[d] = sum_t p[t] * V[t][d]; lane owns d = lane, lane+32
        float y0 = 0.0f, y1 = 0.0f;
        for (int t = 0; t < SEQ; t++) {
            float p = Ps[warp * SEQ + t];
            y0 = fmaf(p, Vs[t * 65 + lane], y0);
            y1 = fmaf(p, Vs[t * 65 + lane + 32], y1);
        }
        float* yr = y + (size_t)(b * SEQ + s) * DMODEL + h * DHEAD;
        yr[lane]      = y0 * inv;
        yr[lane + 32] = y1 * inv;
        __syncwarp();
    }
}

// ---------------- KAN head: logits = einsum(sin(x*f+phi), amp) ----------------
__global__ __launch_bounds__(256) void head_kernel(const float* __restrict__ x,
                                                   const float* __restrict__ amp,
                                                   float* __restrict__ logits) {
    __shared__ float sines[4 * DMODEL];
    int b = blockIdx.x;
    int tid = threadIdx.x;
    const float* xr = x + (size_t)b * SEQ * DMODEL;  // cls token (s=0)
    const float PI = 3.14159265358979323846f;
    for (int i = tid; i < DMODEL; i += 256) {
        float xv = xr[i];
        float ph = (float)i * (PI / (float)DMODEL);
#pragma unroll
        for (int g = 0; g < 4; g++) sines[g * DMODEL + i] = sinf(xv * (float)(g + 1) + ph);
    }
    __syncthreads();

    int warp = tid >> 5, lane = tid & 31;
    int o = blockIdx.y * 8 + warp;
    if (o < NOUT) {
        const float* ar = amp + (size_t)o * 4 * DMODEL;
        float acc = 0.0f;
        for (int i = lane; i < 4 * DMODEL; i += 32) acc = fmaf(sines[i], ar[i], acc);
#pragma unroll
        for (int off = 16; off > 0; off >>= 1) acc += __shfl_xor_sync(0xffffffffu, acc, off);
        if (lane == 0) logits[(size_t)b * NOUT + o] = acc * (1.0f / 55.42562584220407f); // 1/sqrt(3072)
    }
}

// ---------------- final softmax over 1000 classes ----------------
__global__ __launch_bounds__(256) void softmax_kernel(const float* __restrict__ logits,
                                                      float* __restrict__ out) {
    int b = blockIdx.x;
    int tid = threadIdx.x;
    const float* lr = logits + (size_t)b * NOUT;
    __shared__ float red[256];

    float m = -1e30f;
    for (int i = tid; i < NOUT; i += 256) m = fmaxf(m, lr[i]);
    red[tid] = m;
    __syncthreads();
    for (int off = 128; off > 0; off >>= 1) {
        if (tid < off) red[tid] = fmaxf(red[tid], red[tid + off]);
        __syncthreads();
    }
    m = red[0];
    __syncthreads();

    float s = 0.0f;
    for (int i = tid; i < NOUT; i += 256) s += expf(lr[i] - m);
    red[tid] = s;
    __syncthreads();
    for (int off = 128; off > 0; off >>= 1) {
        if (tid < off) red[tid] += red[tid + off];
        __syncthreads();
    }
    float inv = 1.0f / red[0];

    float* orow = out + (size_t)b * NOUT;
    for (int i = tid; i < NOUT; i += 256) orow[i] = expf(lr[i] - m) * inv;
}

// ---------------- launch ----------------
extern "C" void kernel_launch(void* const* d_in, const int* in_sizes, int n_in,
                              void* d_out, int out_size) {
    (void)in_sizes; (void)n_in; (void)out_size;
    const float* images    = (const float*)d_in[0];
    const float* v_class   = (const float*)d_in[1];
    const float* W_map     = (const float*)d_in[2];
    const float* b_map     = (const float*)d_in[3];
    const float* ln1_scale = (const float*)d_in[4];
    const float* ln1_bias  = (const float*)d_in[5];
    const float* Wqkv      = (const float*)d_in[6];
    const float* bqkv      = (const float*)d_in[7];
    const float* Wo        = (const float*)d_in[8];
    const float* bo        = (const float*)d_in[9];
    const float* ln2_scale = (const float*)d_in[10];
    const float* ln2_bias  = (const float*)d_in[11];
    const float* Wmlp1     = (const float*)d_in[12];
    const float* bmlp1     = (const float*)d_in[13];
    const float* Wmlp2     = (const float*)d_in[14];
    const float* bmlp2     = (const float*)d_in[15];
    const float* kan_amp   = (const float*)d_in[16];
    float* out = (float*)d_out;

    void *pp, *pt, *px, *ph, *pq, *py, *pf, *pl;
    cudaGetSymbolAddress(&pp, g_patches);
    cudaGetSymbolAddress(&pt, g_tok);
    cudaGetSymbolAddress(&px, g_x);
    cudaGetSymbolAddress(&ph, g_h);
    cudaGetSymbolAddress(&pq, g_qkv);
    cudaGetSymbolAddress(&py, g_y);
    cudaGetSymbolAddress(&pf, g_ff);
    cudaGetSymbolAddress(&pl, g_logits);
    float* patches = (float*)pp;
    float* tok     = (float*)pt;
    float* x       = (float*)px;
    float* h       = (float*)ph;
    float* qkv     = (float*)pq;
    float* y       = (float*)py;
    float* ff      = (float*)pf;
    float* logits  = (float*)pl;

    cudaFuncSetAttribute(attn_kernel, cudaFuncAttributeMaxDynamicSharedMemorySize, (int)ATTN_SMEM);

    // patch extraction + patch embedding GEMM + pos embed
    patch_kernel<<<(M_PAT * DMODEL + 255) / 256, 256>>>(images, patches);
    {
        dim3 grid((DMODEL + 127) / 128, (M_PAT + 127) / 128);
        sgemm_kernel<<<grid, 256>>>(patches, W_map, b_map, nullptr, tok,
                                    M_PAT, DMODEL, DMODEL, 0);
    }
    embed_kernel<<<(M_ALL * DMODEL + 255) / 256, 256>>>(tok, v_class, x);

    dim3 gQKV((3 * DMODEL + 127) / 128, (M_ALL + 127) / 128);
    dim3 gD  ((DMODEL + 127) / 128,     (M_ALL + 127) / 128);
    dim3 gFF ((FFDIM + 127) / 128,      (M_ALL + 127) / 128);

    for (int blk = 0; blk < NBLK; blk++) {
        const float* g1 = ln1_scale + (size_t)blk * DMODEL;
        const float* b1 = ln1_bias  + (size_t)blk * DMODEL;
        const float* wq = Wqkv + (size_t)blk * DMODEL * 3 * DMODEL;
        const float* bq = bqkv + (size_t)blk * 3 * DMODEL;
        const float* wo = Wo   + (size_t)blk * DMODEL * DMODEL;
        const float* bo_ = bo  + (size_t)blk * DMODEL;
        const float* g2 = ln2_scale + (size_t)blk * DMODEL;
        const float* b2 = ln2_bias  + (size_t)blk * DMODEL;
        const float* w1 = Wmlp1 + (size_t)blk * DMODEL * FFDIM;
        const float* bm1 = bmlp1 + (size_t)blk * FFDIM;
        const float* w2 = Wmlp2 + (size_t)blk * FFDIM * DMODEL;
        const float* bm2 = bmlp2 + (size_t)blk * DMODEL;

        ln_kernel<<<M_ALL, 256>>>(x, g1, b1, h);
        sgemm_kernel<<<gQKV, 256>>>(h, wq, bq, nullptr, qkv, M_ALL, 3 * DMODEL, DMODEL, 0);
        attn_kernel<<<dim3(NHEAD, BATCH), 256, ATTN_SMEM>>>(qkv, y);
        sgemm_kernel<<<gD, 256>>>(y, wo, bo_, x, x, M_ALL, DMODEL, DMODEL, 0);
        ln_kernel<<<M_ALL, 256>>>(x, g2, b2, h);
        sgemm_kernel<<<gFF, 256>>>(h, w1, bm1, nullptr, ff, M_ALL, FFDIM, DMODEL, 1);
        sgemm_kernel<<<gD, 256>>>(ff, w2, bm2, x, x, M_ALL, DMODEL, FFDIM, 0);
    }

    head_kernel<<<dim3(BATCH, 125), 256>>>(x, kan_amp, logits);
    softmax_kernel<<<BATCH, 256>>>(logits, out);
}

// round 6
// speedup vs baseline: 2.0018x; 1.9997x over previous
#include <cuda_runtime.h>
#include <cuda_bf16.h>
#include <stdint.h>
#include <math.h>

#define BATCH 64
#define SEQ   197
#define DMODEL 768
#define NBLK  12
#define NHEAD 12
#define DHEAD 64
#define FFDIM 3072
#define NOUT  1000
#define NTOK  196
#define M_ALL (BATCH*SEQ)   // 12608
#define M_PAT (BATCH*NTOK)  // 12544 = 98*128
#define MPAD  12800         // 100*128

// ---- scratch ----
__device__ __align__(16) __nv_bfloat16 g_patch_s[(size_t)M_PAT * 2 * DMODEL];
__device__ float         g_tok   [(size_t)M_PAT * DMODEL];
__device__ float         g_x     [(size_t)M_ALL * DMODEL];
__device__ __align__(16) __nv_bfloat16 g_h_s [(size_t)MPAD * 2 * DMODEL];
__device__ float         g_qkv   [(size_t)M_ALL * 3 * DMODEL];
__device__ __align__(16) __nv_bfloat16 g_y_s [(size_t)MPAD * 2 * DMODEL];
__device__ __align__(16) __nv_bfloat16 g_ff_s[(size_t)MPAD * 2 * FFDIM];
__device__ float         g_logits[BATCH * NOUT];
__device__ __align__(16) __nv_bfloat16 g_wmap_t[(size_t)DMODEL * 2 * DMODEL];
__device__ __align__(16) __nv_bfloat16 g_wqkv_t[(size_t)NBLK * 3 * DMODEL * 2 * DMODEL];
__device__ __align__(16) __nv_bfloat16 g_wo_t  [(size_t)NBLK * DMODEL * 2 * DMODEL];
__device__ __align__(16) __nv_bfloat16 g_wm1_t [(size_t)NBLK * FFDIM * 2 * DMODEL];
__device__ __align__(16) __nv_bfloat16 g_wm2_t [(size_t)NBLK * DMODEL * 2 * FFDIM];

__device__ __forceinline__ uint32_t smem_u32(const void* p) {
    uint32_t a;
    asm("{ .reg .u64 t; cvta.to.shared.u64 t, %1; cvt.u32.u64 %0, t; }" : "=r"(a) : "l"(p));
    return a;
}
__device__ __forceinline__ void cpasync16(uint32_t s, const void* g) {
    asm volatile("cp.async.cg.shared.global [%0], [%1], 16;" :: "r"(s), "l"(g));
}
#define CP_COMMIT() asm volatile("cp.async.commit_group;" ::: "memory")
#define CP_WAIT1()  asm volatile("cp.async.wait_group 1;" ::: "memory")
#define CP_WAIT0()  asm volatile("cp.async.wait_group 0;" ::: "memory")

__device__ __forceinline__ void mma_bf16(float& c0, float& c1, float& c2, float& c3,
                                         uint32_t a0, uint32_t a1, uint32_t a2, uint32_t a3,
                                         uint32_t b0, uint32_t b1) {
    asm volatile("mma.sync.aligned.m16n8k16.row.col.f32.bf16.bf16.f32 "
                 "{%0,%1,%2,%3}, {%4,%5,%6,%7}, {%8,%9}, {%0,%1,%2,%3};"
                 : "+f"(c0), "+f"(c1), "+f"(c2), "+f"(c3)
                 : "r"(a0), "r"(a1), "r"(a2), "r"(a3), "r"(b0), "r"(b1));
}

__device__ __forceinline__ void split_bf16(float v, __nv_bfloat16& hi, __nv_bfloat16& lo) {
    hi = __float2bfloat16(v);
    lo = __float2bfloat16(v - __bfloat162float(hi));
}

// ---- HMMA GEMM: C[M,N] = act(A@Bw^T + bias) (+res), 3x bf16 split ----
// A:[Mpad,2K] bf16 (hi|lo). Bw:[N,2K] bf16 (hi|lo). CTA tile 128x128, K-chunk 64.
#define LDK 72                       // padded smem row (elems)
#define STAGE_E (128 * LDK)          // elems per A (or B) stage
#define GEMM_SMEM (4 * STAGE_E * 2)  // 2 stages * (A+B) * 2B = 73728

__global__ __launch_bounds__(256, 2) void mma_gemm_kernel(
    const __nv_bfloat16* __restrict__ A, const __nv_bfloat16* __restrict__ Bw,
    const float* __restrict__ bias, const float* __restrict__ res,
    float* __restrict__ outF, __nv_bfloat16* __restrict__ outS,
    int Mreal, int N, int K, int act)
{
    extern __shared__ __nv_bfloat16 smem[];
    int tid = threadIdx.x;
    int wid = tid >> 5, lane = tid & 31;
    int warpM = wid & 1, warpN = wid >> 1;        // 2 x 4 warps
    int gid = lane >> 2, tig = lane & 3;
    int mT = blockIdx.y * 128, nT = blockIdx.x * 128;
    const int kcN = K / 64, C = 3 * kcN;
    const size_t rowE = (size_t)2 * K;

    const __nv_bfloat16* Ab = A + (size_t)mT * rowE;
    const __nv_bfloat16* Bb = Bw + (size_t)nT * rowE;
    uint32_t sbase = smem_u32(smem);

    // per-thread load map: 4 chunks of A + 4 of B per stage
    int ldrow[4], ldseg[4];
#pragma unroll
    for (int i = 0; i < 4; i++) {
        int c = tid + i * 256;
        ldrow[i] = c >> 3;
        ldseg[i] = c & 7;
    }

    auto load_chunk = [&](int c) {
        int s = c & 1;
        int ph = c / kcN, kc = c - ph * kcN;
        int aOff = ((ph == 2) ? K : 0) + kc * 64;
        int bOff = ((ph == 1) ? K : 0) + kc * 64;
        uint32_t sA = sbase + s * (2 * STAGE_E * 2);
        uint32_t sB = sA + STAGE_E * 2;
#pragma unroll
        for (int i = 0; i < 4; i++) {
            int r = ldrow[i], sg = ldseg[i];
            cpasync16(sA + (r * LDK + sg * 8) * 2, Ab + (size_t)r * rowE + aOff + sg * 8);
            cpasync16(sB + (r * LDK + sg * 8) * 2, Bb + (size_t)r * rowE + bOff + sg * 8);
        }
        CP_COMMIT();
    };

    float acc[4][4][4];
#pragma unroll
    for (int i = 0; i < 4; i++)
#pragma unroll
        for (int j = 0; j < 4; j++)
#pragma unroll
            for (int k = 0; k < 4; k++) acc[i][j][k] = 0.0f;

    load_chunk(0);
    if (C > 1) load_chunk(1);

    for (int c = 0; c < C; c++) {
        if (c + 1 < C) CP_WAIT1(); else CP_WAIT0();
        __syncthreads();
        const __nv_bfloat16* As = smem + (c & 1) * 2 * STAGE_E;
        const __nv_bfloat16* Bs = As + STAGE_E;
#pragma unroll
        for (int ks = 0; ks < 4; ks++) {
            int kk = ks * 16 + tig * 2;
            uint32_t a[4][4], b[4][2];
#pragma unroll
            for (int mt = 0; mt < 4; mt++) {
                const __nv_bfloat16* ap = As + (warpM * 64 + mt * 16 + gid) * LDK + kk;
                a[mt][0] = *(const uint32_t*)(ap);
                a[mt][1] = *(const uint32_t*)(ap + 8 * LDK);
                a[mt][2] = *(const uint32_t*)(ap + 8);
                a[mt][3] = *(const uint32_t*)(ap + 8 * LDK + 8);
            }
#pragma unroll
            for (int nt = 0; nt < 4; nt++) {
                const __nv_bfloat16* bp = Bs + (warpN * 32 + nt * 8 + gid) * LDK + kk;
                b[nt][0] = *(const uint32_t*)(bp);
                b[nt][1] = *(const uint32_t*)(bp + 8);
            }
#pragma unroll
            for (int mt = 0; mt < 4; mt++)
#pragma unroll
                for (int nt = 0; nt < 4; nt++)
                    mma_bf16(acc[mt][nt][0], acc[mt][nt][1], acc[mt][nt][2], acc[mt][nt][3],
                             a[mt][0], a[mt][1], a[mt][2], a[mt][3], b[nt][0], b[nt][1]);
        }
        __syncthreads();
        if (c + 2 < C) load_chunk(c + 2);
    }

    // epilogue
    const size_t ldS = (size_t)2 * N;
#pragma unroll
    for (int mt = 0; mt < 4; mt++) {
#pragma unroll
        for (int half = 0; half < 2; half++) {
            int row = mT + warpM * 64 + mt * 16 + gid + half * 8;
            if (row >= Mreal) continue;
#pragma unroll
            for (int nt = 0; nt < 4; nt++) {
                int col = nT + warpN * 32 + nt * 8 + tig * 2;
                float v0 = acc[mt][nt][half * 2 + 0];
                float v1 = acc[mt][nt][half * 2 + 1];
                float2 bb = *(const float2*)(bias + col);
                v0 += bb.x; v1 += bb.y;
                if (act == 1) {
                    float u;
                    u = v0; v0 = 0.5f*u*(1.0f + tanhf(0.7978845608028654f*(u + 0.044715f*u*u*u)));
                    u = v1; v1 = 0.5f*u*(1.0f + tanhf(0.7978845608028654f*(u + 0.044715f*u*u*u)));
                }
                if (res) {
                    float2 rr = *(const float2*)(res + (size_t)row * N + col);
                    v0 += rr.x; v1 += rr.y;
                }
                if (outF) *(float2*)(outF + (size_t)row * N + col) = make_float2(v0, v1);
                if (outS) {
                    union { __nv_bfloat16 b[2]; uint32_t u; } H, L;
                    split_bf16(v0, H.b[0], L.b[0]);
                    split_bf16(v1, H.b[1], L.b[1]);
                    *(uint32_t*)(outS + (size_t)row * ldS + col)     = H.u;
                    *(uint32_t*)(outS + (size_t)row * ldS + N + col) = L.u;
                }
            }
        }
    }
}

// ---- weight split+transpose: W[K,N] f32 -> out[N,2K] bf16 (hi|lo) ----
__global__ __launch_bounds__(256) void wsplit_kernel(const float* __restrict__ W,
                                                     __nv_bfloat16* __restrict__ out,
                                                     int K, int N) {
    __shared__ float t[32][33];
    int k0 = blockIdx.y * 32, n0 = blockIdx.x * 32;
    int tx = threadIdx.x & 31, ty = threadIdx.x >> 5;
    for (int i = ty; i < 32; i += 8) t[i][tx] = W[(size_t)(k0 + i) * N + n0 + tx];
    __syncthreads();
    for (int i = ty; i < 32; i += 8) {
        __nv_bfloat16 hi, lo;
        split_bf16(t[tx][i], hi, lo);
        size_t base = (size_t)(n0 + i) * 2 * K + k0 + tx;
        out[base] = hi; out[base + K] = lo;
    }
}

// ---- patch extraction (split bf16 out) ----
__global__ __launch_bounds__(256) void patch_kernel(const float* __restrict__ img,
                                                    __nv_bfloat16* __restrict__ out) {
    int idx = blockIdx.x * 256 + threadIdx.x;
    if (idx >= M_PAT * DMODEL) return;
    int i = idx % DMODEL, row = idx / DMODEL;
    int p = row % NTOK, b = row / NTOK;
    int c = i >> 8, rem = i & 255, iy = rem >> 4, ix = rem & 15;
    int py = p / 14, px = p % 14;
    float v = img[(((size_t)(b*3 + c) * 224) + py*16 + iy) * 224 + px*16 + ix];
    __nv_bfloat16 hi, lo; split_bf16(v, hi, lo);
    out[(size_t)row * 2 * DMODEL + i] = hi;
    out[(size_t)row * 2 * DMODEL + DMODEL + i] = lo;
}

// ---- embed ----
__global__ __launch_bounds__(256) void embed_kernel(const float* __restrict__ tok,
                                                    const float* __restrict__ v_class,
                                                    float* __restrict__ x) {
    int idx = blockIdx.x * 256 + threadIdx.x;
    if (idx >= M_ALL * DMODEL) return;
    int d = idx % DMODEL, r = idx / DMODEL;
    int s = r % SEQ, b = r / SEQ;
    float t = (s == 0) ? v_class[d] : tok[(size_t)(b * NTOK + s - 1) * DMODEL + d];
    float ang = (float)s / powf(10000.0f, (float)d / (float)DMODEL);
    x[idx] = t + (((d & 1) == 0) ? sinf(ang) : cosf(ang));
}

// ---- LayerNorm -> split bf16 ----
__global__ __launch_bounds__(256) void ln_kernel(const float* __restrict__ x,
                                                 const float* __restrict__ gamma,
                                                 const float* __restrict__ beta,
                                                 __nv_bfloat16* __restrict__ outS) {
    int row = blockIdx.x, tid = threadIdx.x;
    const float* xr = x + (size_t)row * DMODEL;
    float v0 = xr[tid], v1 = xr[tid+256], v2 = xr[tid+512];
    __shared__ float red[256];
    red[tid] = v0 + v1 + v2; __syncthreads();
    for (int o = 128; o > 0; o >>= 1) { if (tid < o) red[tid] += red[tid+o]; __syncthreads(); }
    float mean = red[0] * (1.0f / DMODEL); __syncthreads();
    float d0 = v0-mean, d1 = v1-mean, d2 = v2-mean;
    red[tid] = d0*d0 + d1*d1 + d2*d2; __syncthreads();
    for (int o = 128; o > 0; o >>= 1) { if (tid < o) red[tid] += red[tid+o]; __syncthreads(); }
    float rstd = rsqrtf(red[0] * (1.0f / DMODEL) + 1e-5f);
    __nv_bfloat16* orow = outS + (size_t)row * 2 * DMODEL;
    __nv_bfloat16 hi, lo;
    float o0 = d0*rstd*gamma[tid]     + beta[tid];
    float o1 = d1*rstd*gamma[tid+256] + beta[tid+256];
    float o2 = d2*rstd*gamma[tid+512] + beta[tid+512];
    split_bf16(o0,hi,lo); orow[tid]=hi;     orow[DMODEL+tid]=lo;
    split_bf16(o1,hi,lo); orow[tid+256]=hi; orow[DMODEL+tid+256]=lo;
    split_bf16(o2,hi,lo); orow[tid+512]=hi; orow[DMODEL+tid+512]=lo;
}

// ---- fused attention per (b,h), split bf16 out ----
#define ATTN_SMEM ((2*197*65 + 8*197 + 8*64) * sizeof(float))
__global__ __launch_bounds__(256) void attn_kernel(const float* __restrict__ qkv,
                                                   __nv_bfloat16* __restrict__ yS) {
    extern __shared__ float smf[];
    float* Ks = smf;
    float* Vs = Ks + 197*65;
    float* Ps = Vs + 197*65;
    float* Qs = Ps + 8*197;
    int h = blockIdx.x, b = blockIdx.y, tid = threadIdx.x;
    for (int idx = tid; idx < SEQ * DHEAD; idx += 256) {
        int t = idx >> 6, d = idx & 63;
        const float* base = qkv + (size_t)(b*SEQ + t) * (3*DMODEL) + h*DHEAD + d;
        Ks[t*65 + d] = base[DMODEL];
        Vs[t*65 + d] = base[2*DMODEL];
    }
    __syncthreads();
    int warp = tid >> 5, lane = tid & 31;
    for (int s = warp; s < SEQ; s += 8) {
        const float* qp = qkv + (size_t)(b*SEQ + s) * (3*DMODEL) + h*DHEAD;
        Qs[warp*64 + lane]      = qp[lane];
        Qs[warp*64 + lane + 32] = qp[lane + 32];
        __syncwarp();
        float sc[7], m = -1e30f;
#pragma unroll
        for (int j = 0; j < 7; j++) {
            int t = lane + 32*j;
            if (t < SEQ) {
                float a = 0.0f;
#pragma unroll
                for (int d = 0; d < 64; d++) a = fmaf(Qs[warp*64 + d], Ks[t*65 + d], a);
                sc[j] = a * 0.125f; m = fmaxf(m, sc[j]);
            } else sc[j] = -1e30f;
        }
#pragma unroll
        for (int o = 16; o > 0; o >>= 1) m = fmaxf(m, __shfl_xor_sync(0xffffffffu, m, o));
        float sum = 0.0f;
#pragma unroll
        for (int j = 0; j < 7; j++) {
            int t = lane + 32*j;
            if (t < SEQ) { float e = expf(sc[j] - m); Ps[warp*SEQ + t] = e; sum += e; }
        }
#pragma unroll
        for (int o = 16; o > 0; o >>= 1) sum += __shfl_xor_sync(0xffffffffu, sum, o);
        float inv = 1.0f / sum;
        __syncwarp();
        float y0 = 0.0f, y1 = 0.0f;
        for (int t = 0; t < SEQ; t++) {
            float p = Ps[warp*SEQ + t];
            y0 = fmaf(p, Vs[t*65 + lane], y0);
            y1 = fmaf(p, Vs[t*65 + lane + 32], y1);
        }
        __nv_bfloat16* yr = yS + (size_t)(b*SEQ + s) * 2 * DMODEL + h * DHEAD;
        __nv_bfloat16 hi, lo;
        split_bf16(y0 * inv, hi, lo); yr[lane] = hi;    yr[DMODEL + lane] = lo;
        split_bf16(y1 * inv, hi, lo); yr[lane+32] = hi; yr[DMODEL + lane + 32] = lo;
        __syncwarp();
    }
}

// ---- KAN head ----
__global__ __launch_bounds__(256) void head_kernel(const float* __restrict__ x,
                                                   const float* __restrict__ amp,
                                                   float* __restrict__ logits) {
    __shared__ float sines[4 * DMODEL];
    int b = blockIdx.x, tid = threadIdx.x;
    const float* xr = x + (size_t)b * SEQ * DMODEL;
    const float PI = 3.14159265358979323846f;
    for (int i = tid; i < DMODEL; i += 256) {
        float xv = xr[i], ph = (float)i * (PI / (float)DMODEL);
#pragma unroll
        for (int g = 0; g < 4; g++) sines[g*DMODEL + i] = sinf(xv * (float)(g+1) + ph);
    }
    __syncthreads();
    int warp = tid >> 5, lane = tid & 31;
    int o = blockIdx.y * 8 + warp;
    if (o < NOUT) {
        const float* ar = amp + (size_t)o * 4 * DMODEL;
        float acc = 0.0f;
        for (int i = lane; i < 4*DMODEL; i += 32) acc = fmaf(sines[i], ar[i], acc);
#pragma unroll
        for (int of = 16; of > 0; of >>= 1) acc += __shfl_xor_sync(0xffffffffu, acc, of);
        if (lane == 0) logits[(size_t)b*NOUT + o] = acc * (1.0f / 55.42562584220407f);
    }
}

// ---- softmax ----
__global__ __launch_bounds__(256) void softmax_kernel(const float* __restrict__ logits,
                                                      float* __restrict__ out) {
    int b = blockIdx.x, tid = threadIdx.x;
    const float* lr = logits + (size_t)b * NOUT;
    __shared__ float red[256];
    float m = -1e30f;
    for (int i = tid; i < NOUT; i += 256) m = fmaxf(m, lr[i]);
    red[tid] = m; __syncthreads();
    for (int o = 128; o > 0; o >>= 1) { if (tid < o) red[tid] = fmaxf(red[tid], red[tid+o]); __syncthreads(); }
    m = red[0]; __syncthreads();
    float s = 0.0f;
    for (int i = tid; i < NOUT; i += 256) s += expf(lr[i] - m);
    red[tid] = s; __syncthreads();
    for (int o = 128; o > 0; o >>= 1) { if (tid < o) red[tid] += red[tid+o]; __syncthreads(); }
    float inv = 1.0f / red[0];
    for (int i = tid; i < NOUT; i += 256) out[(size_t)b*NOUT + i] = expf(lr[i] - m) * inv;
}

// ---- launch ----
extern "C" void kernel_launch(void* const* d_in, const int* in_sizes, int n_in,
                              void* d_out, int out_size) {
    (void)in_sizes; (void)n_in; (void)out_size;
    const float* images    = (const float*)d_in[0];
    const float* v_class   = (const float*)d_in[1];
    const float* W_map     = (const float*)d_in[2];
    const float* b_map     = (const float*)d_in[3];
    const float* ln1_scale = (const float*)d_in[4];
    const float* ln1_bias  = (const float*)d_in[5];
    const float* Wqkv      = (const float*)d_in[6];
    const float* bqkv      = (const float*)d_in[7];
    const float* Wo        = (const float*)d_in[8];
    const float* bo        = (const float*)d_in[9];
    const float* ln2_scale = (const float*)d_in[10];
    const float* ln2_bias  = (const float*)d_in[11];
    const float* Wmlp1     = (const float*)d_in[12];
    const float* bmlp1     = (const float*)d_in[13];
    const float* Wmlp2     = (const float*)d_in[14];
    const float* bmlp2     = (const float*)d_in[15];
    const float* kan_amp   = (const float*)d_in[16];
    float* out = (float*)d_out;

    void *p0,*p1,*p2,*p3,*p4,*p5,*p6,*p7,*p8,*p9,*p10,*p11,*p12;
    cudaGetSymbolAddress(&p0, g_patch_s); cudaGetSymbolAddress(&p1, g_tok);
    cudaGetSymbolAddress(&p2, g_x);       cudaGetSymbolAddress(&p3, g_h_s);
    cudaGetSymbolAddress(&p4, g_qkv);     cudaGetSymbolAddress(&p5, g_y_s);
    cudaGetSymbolAddress(&p6, g_ff_s);    cudaGetSymbolAddress(&p7, g_logits);
    cudaGetSymbolAddress(&p8, g_wmap_t);  cudaGetSymbolAddress(&p9, g_wqkv_t);
    cudaGetSymbolAddress(&p10, g_wo_t);   cudaGetSymbolAddress(&p11, g_wm1_t);
    cudaGetSymbolAddress(&p12, g_wm2_t);
    __nv_bfloat16* patch_s = (__nv_bfloat16*)p0;
    float* tok = (float*)p1;
    float* x   = (float*)p2;
    __nv_bfloat16* h_s = (__nv_bfloat16*)p3;
    float* qkv = (float*)p4;
    __nv_bfloat16* y_s = (__nv_bfloat16*)p5;
    __nv_bfloat16* ff_s = (__nv_bfloat16*)p6;
    float* logits = (float*)p7;
    __nv_bfloat16* wmap_t = (__nv_bfloat16*)p8;
    __nv_bfloat16* wqkv_t = (__nv_bfloat16*)p9;
    __nv_bfloat16* wo_t   = (__nv_bfloat16*)p10;
    __nv_bfloat16* wm1_t  = (__nv_bfloat16*)p11;
    __nv_bfloat16* wm2_t  = (__nv_bfloat16*)p12;

    cudaFuncSetAttribute(attn_kernel, cudaFuncAttributeMaxDynamicSharedMemorySize, (int)ATTN_SMEM);
    cudaFuncSetAttribute(mma_gemm_kernel, cudaFuncAttributeMaxDynamicSharedMemorySize, GEMM_SMEM);

    // weight splits
    wsplit_kernel<<<dim3(DMODEL/32, DMODEL/32), 256>>>(W_map, wmap_t, DMODEL, DMODEL);
    for (int blk = 0; blk < NBLK; blk++) {
        wsplit_kernel<<<dim3(3*DMODEL/32, DMODEL/32), 256>>>(
            Wqkv + (size_t)blk*DMODEL*3*DMODEL, wqkv_t + (size_t)blk*3*DMODEL*2*DMODEL, DMODEL, 3*DMODEL);
        wsplit_kernel<<<dim3(DMODEL/32, DMODEL/32), 256>>>(
            Wo + (size_t)blk*DMODEL*DMODEL, wo_t + (size_t)blk*DMODEL*2*DMODEL, DMODEL, DMODEL);
        wsplit_kernel<<<dim3(FFDIM/32, DMODEL/32), 256>>>(
            Wmlp1 + (size_t)blk*DMODEL*FFDIM, wm1_t + (size_t)blk*FFDIM*2*DMODEL, DMODEL, FFDIM);
        wsplit_kernel<<<dim3(DMODEL/32, FFDIM/32), 256>>>(
            Wmlp2 + (size_t)blk*FFDIM*DMODEL, wm2_t + (size_t)blk*DMODEL*2*FFDIM, FFDIM, DMODEL);
    }

    // patch embed
    patch_kernel<<<(M_PAT*DMODEL + 255)/256, 256>>>(images, patch_s);
    mma_gemm_kernel<<<dim3(DMODEL/128, M_PAT/128), 256, GEMM_SMEM>>>(
        patch_s, wmap_t, b_map, nullptr, tok, nullptr, M_PAT, DMODEL, DMODEL, 0);
    embed_kernel<<<(M_ALL*DMODEL + 255)/256, 256>>>(tok, v_class, x);

    for (int blk = 0; blk < NBLK; blk++) {
        ln_kernel<<<M_ALL, 256>>>(x, ln1_scale + (size_t)blk*DMODEL, ln1_bias + (size_t)blk*DMODEL, h_s);
        mma_gemm_kernel<<<dim3(3*DMODEL/128, MPAD/128), 256, GEMM_SMEM>>>(
            h_s, wqkv_t + (size_t)blk*3*DMODEL*2*DMODEL, bqkv + (size_t)blk*3*DMODEL,
            nullptr, qkv, nullptr, M_ALL, 3*DMODEL, DMODEL, 0);
        attn_kernel<<<dim3(NHEAD, BATCH), 256, ATTN_SMEM>>>(qkv, y_s);
        mma_gemm_kernel<<<dim3(DMODEL/128, MPAD/128), 256, GEMM_SMEM>>>(
            y_s, wo_t + (size_t)blk*DMODEL*2*DMODEL, bo + (size_t)blk*DMODEL,
            x, x, nullptr, M_ALL, DMODEL, DMODEL, 0);
        ln_kernel<<<M_ALL, 256>>>(x, ln2_scale + (size_t)blk*DMODEL, ln2_bias + (size_t)blk*DMODEL, h_s);
        mma_gemm_kernel<<<dim3(FFDIM/128, MPAD/128), 256, GEMM_SMEM>>>(
            h_s, wm1_t + (size_t)blk*FFDIM*2*DMODEL, bmlp1 + (size_t)blk*FFDIM,
            nullptr, nullptr, ff_s, M_ALL, FFDIM, DMODEL, 1);
        mma_gemm_kernel<<<dim3(DMODEL/128, MPAD/128), 256, GEMM_SMEM>>>(
            ff_s, wm2_t + (size_t)blk*DMODEL*2*FFDIM, bmlp2 + (size_t)blk*DMODEL,
            x, x, nullptr, M_ALL, DMODEL, FFDIM, 0);
    }

    head_kernel<<<dim3(BATCH, 125), 256>>>(x, kan_amp, logits);
    softmax_kernel<<<BATCH, 256>>>(logits, out);
}

// round 7
// speedup vs baseline: 3.6727x; 1.8347x over previous
#include <cuda_runtime.h>
#include <cuda_fp16.h>
#include <stdint.h>
#include <math.h>

#define BATCH 64
#define SEQ   197
#define DMODEL 768
#define NBLK  12
#define NHEAD 12
#define DHEAD 64
#define FFDIM 3072
#define NOUT  1000
#define NTOK  196
#define M_ALL (BATCH*SEQ)   // 12608
#define M_PAT (BATCH*NTOK)  // 12544 = 98*128
#define MPAD  12800         // 100*128

// ---- scratch (zero-initialized device globals) ----
__device__ __align__(16) __half g_patch_h[(size_t)M_PAT * DMODEL];
__device__ float  g_tok   [(size_t)M_PAT * DMODEL];
__device__ float  g_x     [(size_t)M_ALL * DMODEL];
__device__ __align__(16) __half g_h_h [(size_t)MPAD * DMODEL];
__device__ float  g_qkv   [(size_t)M_ALL * 3 * DMODEL];
__device__ __align__(16) __half g_y_h [(size_t)MPAD * DMODEL];
__device__ __align__(16) __half g_ff_h[(size_t)MPAD * FFDIM];
__device__ float  g_logits[BATCH * NOUT];
__device__ __align__(16) __half g_wmap_t[(size_t)DMODEL * DMODEL];
__device__ __align__(16) __half g_wqkv_t[(size_t)NBLK * 3 * DMODEL * DMODEL];
__device__ __align__(16) __half g_wo_t  [(size_t)NBLK * DMODEL * DMODEL];
__device__ __align__(16) __half g_wm1_t [(size_t)NBLK * FFDIM * DMODEL];
__device__ __align__(16) __half g_wm2_t [(size_t)NBLK * DMODEL * FFDIM];

__device__ __forceinline__ void cpasync16(uint32_t s, const void* g) {
    asm volatile("cp.async.cg.shared.global [%0], [%1], 16;" :: "r"(s), "l"(g));
}
__device__ __forceinline__ uint32_t smem_u32(const void* p) {
    uint32_t a;
    asm("{ .reg .u64 t; cvta.to.shared.u64 t, %1; cvt.u32.u64 %0, t; }" : "=r"(a) : "l"(p));
    return a;
}
#define CP_COMMIT() asm volatile("cp.async.commit_group;" ::: "memory")
#define CP_WAIT1()  asm volatile("cp.async.wait_group 1;" ::: "memory")
#define CP_WAIT0()  asm volatile("cp.async.wait_group 0;" ::: "memory")

__device__ __forceinline__ void mma_f16(float& c0, float& c1, float& c2, float& c3,
                                        uint32_t a0, uint32_t a1, uint32_t a2, uint32_t a3,
                                        uint32_t b0, uint32_t b1) {
    asm volatile("mma.sync.aligned.m16n8k16.row.col.f32.f16.f16.f32 "
                 "{%0,%1,%2,%3}, {%4,%5,%6,%7}, {%8,%9}, {%0,%1,%2,%3};"
                 : "+f"(c0), "+f"(c1), "+f"(c2), "+f"(c3)
                 : "r"(a0), "r"(a1), "r"(a2), "r"(a3), "r"(b0), "r"(b1));
}

// ---- HMMA GEMM: C[M,N] = act(A@Bw^T + bias) (+res), plain fp16 operands ----
// A:[Mpad,K] half. Bw:[N,K] half. CTA tile 128x128, K-chunk 64, 2-stage cp.async.
#define LDK 72
#define STAGE_E (128 * LDK)
#define GEMM_SMEM (4 * STAGE_E * 2)   // 73728 B

__global__ __launch_bounds__(256, 2) void mma_gemm_kernel(
    const __half* __restrict__ A, const __half* __restrict__ Bw,
    const float* __restrict__ bias, const float* __restrict__ res,
    float* __restrict__ outF, __half* __restrict__ outS,
    int Mreal, int N, int K, int act)
{
    extern __shared__ __half smem[];
    int tid = threadIdx.x;
    int wid = tid >> 5, lane = tid & 31;
    int warpM = wid & 1, warpN = wid >> 1;        // 2 x 4 warps
    int gid = lane >> 2, tig = lane & 3;
    int mT = blockIdx.y * 128, nT = blockIdx.x * 128;
    const int C = K / 64;

    const __half* Ab = A + (size_t)mT * K;
    const __half* Bb = Bw + (size_t)nT * K;
    uint32_t sbase = smem_u32(smem);

    int ldrow[4], ldseg[4];
#pragma unroll
    for (int i = 0; i < 4; i++) {
        int c = tid + i * 256;
        ldrow[i] = c >> 3;
        ldseg[i] = c & 7;
    }

    auto load_chunk = [&](int c) {
        int s = c & 1;
        int kOff = c * 64;
        uint32_t sA = sbase + s * (2 * STAGE_E * 2);
        uint32_t sB = sA + STAGE_E * 2;
#pragma unroll
        for (int i = 0; i < 4; i++) {
            int r = ldrow[i], sg = ldseg[i];
            cpasync16(sA + (r * LDK + sg * 8) * 2, Ab + (size_t)r * K + kOff + sg * 8);
            cpasync16(sB + (r * LDK + sg * 8) * 2, Bb + (size_t)r * K + kOff + sg * 8);
        }
        CP_COMMIT();
    };

    float acc[4][4][4];
#pragma unroll
    for (int i = 0; i < 4; i++)
#pragma unroll
        for (int j = 0; j < 4; j++)
#pragma unroll
            for (int k = 0; k < 4; k++) acc[i][j][k] = 0.0f;

    load_chunk(0);
    if (C > 1) load_chunk(1);

    for (int c = 0; c < C; c++) {
        if (c + 1 < C) CP_WAIT1(); else CP_WAIT0();
        __syncthreads();
        const __half* As = smem + (c & 1) * 2 * STAGE_E;
        const __half* Bs = As + STAGE_E;
#pragma unroll
        for (int ks = 0; ks < 4; ks++) {
            int kk = ks * 16 + tig * 2;
            uint32_t a[4][4], b[4][2];
#pragma unroll
            for (int mt = 0; mt < 4; mt++) {
                const __half* ap = As + (warpM * 64 + mt * 16 + gid) * LDK + kk;
                a[mt][0] = *(const uint32_t*)(ap);
                a[mt][1] = *(const uint32_t*)(ap + 8 * LDK);
                a[mt][2] = *(const uint32_t*)(ap + 8);
                a[mt][3] = *(const uint32_t*)(ap + 8 * LDK + 8);
            }
#pragma unroll
            for (int nt = 0; nt < 4; nt++) {
                const __half* bp = Bs + (warpN * 32 + nt * 8 + gid) * LDK + kk;
                b[nt][0] = *(const uint32_t*)(bp);
                b[nt][1] = *(const uint32_t*)(bp + 8);
            }
#pragma unroll
            for (int mt = 0; mt < 4; mt++)
#pragma unroll
                for (int nt = 0; nt < 4; nt++)
                    mma_f16(acc[mt][nt][0], acc[mt][nt][1], acc[mt][nt][2], acc[mt][nt][3],
                            a[mt][0], a[mt][1], a[mt][2], a[mt][3], b[nt][0], b[nt][1]);
        }
        __syncthreads();
        if (c + 2 < C) load_chunk(c + 2);
    }

    // epilogue
#pragma unroll
    for (int mt = 0; mt < 4; mt++) {
#pragma unroll
        for (int half_ = 0; half_ < 2; half_++) {
            int row = mT + warpM * 64 + mt * 16 + gid + half_ * 8;
            if (row >= Mreal) continue;
#pragma unroll
            for (int nt = 0; nt < 4; nt++) {
                int col = nT + warpN * 32 + nt * 8 + tig * 2;
                float v0 = acc[mt][nt][half_ * 2 + 0];
                float v1 = acc[mt][nt][half_ * 2 + 1];
                float2 bb = *(const float2*)(bias + col);
                v0 += bb.x; v1 += bb.y;
                if (act == 1) {
                    float u;
                    u = v0; v0 = 0.5f*u*(1.0f + tanhf(0.7978845608028654f*(u + 0.044715f*u*u*u)));
                    u = v1; v1 = 0.5f*u*(1.0f + tanhf(0.7978845608028654f*(u + 0.044715f*u*u*u)));
                }
                if (res) {
                    float2 rr = *(const float2*)(res + (size_t)row * N + col);
                    v0 += rr.x; v1 += rr.y;
                }
                if (outF) *(float2*)(outF + (size_t)row * N + col) = make_float2(v0, v1);
                if (outS) {
                    union { __half h[2]; uint32_t u; } P;
                    P.h[0] = __float2half_rn(v0);
                    P.h[1] = __float2half_rn(v1);
                    *(uint32_t*)(outS + (size_t)row * N + col) = P.u;
                }
            }
        }
    }
}

// ---- weight convert+transpose: W[K,N] f32 -> out[N,K] fp16 ----
__global__ __launch_bounds__(256) void wconv_kernel(const float* __restrict__ W,
                                                    __half* __restrict__ out,
                                                    int K, int N) {
    __shared__ float t[32][33];
    int k0 = blockIdx.y * 32, n0 = blockIdx.x * 32;
    int tx = threadIdx.x & 31, ty = threadIdx.x >> 5;
    for (int i = ty; i < 32; i += 8) t[i][tx] = W[(size_t)(k0 + i) * N + n0 + tx];
    __syncthreads();
    for (int i = ty; i < 32; i += 8)
        out[(size_t)(n0 + i) * K + k0 + tx] = __float2half_rn(t[tx][i]);
}

// ---- patch extraction (fp16 out) ----
__global__ __launch_bounds__(256) void patch_kernel(const float* __restrict__ img,
                                                    __half* __restrict__ out) {
    int idx = blockIdx.x * 256 + threadIdx.x;
    if (idx >= M_PAT * DMODEL) return;
    int i = idx % DMODEL, row = idx / DMODEL;
    int p = row % NTOK, b = row / NTOK;
    int c = i >> 8, rem = i & 255, iy = rem >> 4, ix = rem & 15;
    int py = p / 14, px = p % 14;
    float v = img[(((size_t)(b*3 + c) * 224) + py*16 + iy) * 224 + px*16 + ix];
    out[idx] = __float2half_rn(v);
}

// ---- embed ----
__global__ __launch_bounds__(256) void embed_kernel(const float* __restrict__ tok,
                                                    const float* __restrict__ v_class,
                                                    float* __restrict__ x) {
    int idx = blockIdx.x * 256 + threadIdx.x;
    if (idx >= M_ALL * DMODEL) return;
    int d = idx % DMODEL, r = idx / DMODEL;
    int s = r % SEQ, b = r / SEQ;
    float t = (s == 0) ? v_class[d] : tok[(size_t)(b * NTOK + s - 1) * DMODEL + d];
    float ang = (float)s / powf(10000.0f, (float)d / (float)DMODEL);
    x[idx] = t + (((d & 1) == 0) ? sinf(ang) : cosf(ang));
}

// ---- LayerNorm -> fp16 ----
__global__ __launch_bounds__(256) void ln_kernel(const float* __restrict__ x,
                                                 const float* __restrict__ gamma,
                                                 const float* __restrict__ beta,
                                                 __half* __restrict__ outH) {
    int row = blockIdx.x, tid = threadIdx.x;
    const float* xr = x + (size_t)row * DMODEL;
    float v0 = xr[tid], v1 = xr[tid+256], v2 = xr[tid+512];
    __shared__ float red[256];
    red[tid] = v0 + v1 + v2; __syncthreads();
    for (int o = 128; o > 0; o >>= 1) { if (tid < o) red[tid] += red[tid+o]; __syncthreads(); }
    float mean = red[0] * (1.0f / DMODEL); __syncthreads();
    float d0 = v0-mean, d1 = v1-mean, d2 = v2-mean;
    red[tid] = d0*d0 + d1*d1 + d2*d2; __syncthreads();
    for (int o = 128; o > 0; o >>= 1) { if (tid < o) red[tid] += red[tid+o]; __syncthreads(); }
    float rstd = rsqrtf(red[0] * (1.0f / DMODEL) + 1e-5f);
    __half* orow = outH + (size_t)row * DMODEL;
    orow[tid]     = __float2half_rn(d0*rstd*gamma[tid]     + beta[tid]);
    orow[tid+256] = __float2half_rn(d1*rstd*gamma[tid+256] + beta[tid+256]);
    orow[tid+512] = __float2half_rn(d2*rstd*gamma[tid+512] + beta[tid+512]);
}

// ---- fused attention per (b,h), fp16 out ----
#define ATTN_SMEM ((2*197*65 + 8*197 + 8*64) * sizeof(float))
__global__ __launch_bounds__(256) void attn_kernel(const float* __restrict__ qkv,
                                                   __half* __restrict__ yH) {
    extern __shared__ float smf[];
    float* Ks = smf;
    float* Vs = Ks + 197*65;
    float* Ps = Vs + 197*65;
    float* Qs = Ps + 8*197;
    int h = blockIdx.x, b = blockIdx.y, tid = threadIdx.x;
    for (int idx = tid; idx < SEQ * DHEAD; idx += 256) {
        int t = idx >> 6, d = idx & 63;
        const float* base = qkv + (size_t)(b*SEQ + t) * (3*DMODEL) + h*DHEAD + d;
        Ks[t*65 + d] = base[DMODEL];
        Vs[t*65 + d] = base[2*DMODEL];
    }
    __syncthreads();
    int warp = tid >> 5, lane = tid & 31;
    for (int s = warp; s < SEQ; s += 8) {
        const float* qp = qkv + (size_t)(b*SEQ + s) * (3*DMODEL) + h*DHEAD;
        Qs[warp*64 + lane]      = qp[lane];
        Qs[warp*64 + lane + 32] = qp[lane + 32];
        __syncwarp();
        float sc[7], m = -1e30f;
#pragma unroll
        for (int j = 0; j < 7; j++) {
            int t = lane + 32*j;
            if (t < SEQ) {
                float a = 0.0f;
#pragma unroll
                for (int d = 0; d < 64; d++) a = fmaf(Qs[warp*64 + d], Ks[t*65 + d], a);
                sc[j] = a * 0.125f; m = fmaxf(m, sc[j]);
            } else sc[j] = -1e30f;
        }
#pragma unroll
        for (int o = 16; o > 0; o >>= 1) m = fmaxf(m, __shfl_xor_sync(0xffffffffu, m, o));
        float sum = 0.0f;
#pragma unroll
        for (int j = 0; j < 7; j++) {
            int t = lane + 32*j;
            if (t < SEQ) { float e = expf(sc[j] - m); Ps[warp*SEQ + t] = e; sum += e; }
        }
#pragma unroll
        for (int o = 16; o > 0; o >>= 1) sum += __shfl_xor_sync(0xffffffffu, sum, o);
        float inv = 1.0f / sum;
        __syncwarp();
        float y0 = 0.0f, y1 = 0.0f;
        for (int t = 0; t < SEQ; t++) {
            float p = Ps[warp*SEQ + t];
            y0 = fmaf(p, Vs[t*65 + lane], y0);
            y1 = fmaf(p, Vs[t*65 + lane + 32], y1);
        }
        __half* yr = yH + (size_t)(b*SEQ + s) * DMODEL + h * DHEAD;
        yr[lane]      = __float2half_rn(y0 * inv);
        yr[lane + 32] = __float2half_rn(y1 * inv);
        __syncwarp();
    }
}

// ---- KAN head ----
__global__ __launch_bounds__(256) void head_kernel(const float* __restrict__ x,
                                                   const float* __restrict__ amp,
                                                   float* __restrict__ logits) {
    __shared__ float sines[4 * DMODEL];
    int b = blockIdx.x, tid = threadIdx.x;
    const float* xr = x + (size_t)b * SEQ * DMODEL;
    const float PI = 3.14159265358979323846f;
    for (int i = tid; i < DMODEL; i += 256) {
        float xv = xr[i], ph = (float)i * (PI / (float)DMODEL);
#pragma unroll
        for (int g = 0; g < 4; g++) sines[g*DMODEL + i] = sinf(xv * (float)(g+1) + ph);
    }
    __syncthreads();
    int warp = tid >> 5, lane = tid & 31;
    int o = blockIdx.y * 8 + warp;
    if (o < NOUT) {
        const float* ar = amp + (size_t)o * 4 * DMODEL;
        float acc = 0.0f;
        for (int i = lane; i < 4*DMODEL; i += 32) acc = fmaf(sines[i], ar[i], acc);
#pragma unroll
        for (int of = 16; of > 0; of >>= 1) acc += __shfl_xor_sync(0xffffffffu, acc, of);
        if (lane == 0) logits[(size_t)b*NOUT + o] = acc * (1.0f / 55.42562584220407f);
    }
}

// ---- softmax ----
__global__ __launch_bounds__(256) void softmax_kernel(const float* __restrict__ logits,
                                                      float* __restrict__ out) {
    int b = blockIdx.x, tid = threadIdx.x;
    const float* lr = logits + (size_t)b * NOUT;
    __shared__ float red[256];
    float m = -1e30f;
    for (int i = tid; i < NOUT; i += 256) m = fmaxf(m, lr[i]);
    red[tid] = m; __syncthreads();
    for (int o = 128; o > 0; o >>= 1) { if (tid < o) red[tid] = fmaxf(red[tid], red[tid+o]); __syncthreads(); }
    m = red[0]; __syncthreads();
    float s = 0.0f;
    for (int i = tid; i < NOUT; i += 256) s += expf(lr[i] - m);
    red[tid] = s; __syncthreads();
    for (int o = 128; o > 0; o >>= 1) { if (tid < o) red[tid] += red[tid+o]; __syncthreads(); }
    float inv = 1.0f / red[0];
    for (int i = tid; i < NOUT; i += 256) out[(size_t)b*NOUT + i] = expf(lr[i] - m) * inv;
}

// ---- launch ----
extern "C" void kernel_launch(void* const* d_in, const int* in_sizes, int n_in,
                              void* d_out, int out_size) {
    (void)in_sizes; (void)n_in; (void)out_size;
    const float* images    = (const float*)d_in[0];
    const float* v_class   = (const float*)d_in[1];
    const float* W_map     = (const float*)d_in[2];
    const float* b_map     = (const float*)d_in[3];
    const float* ln1_scale = (const float*)d_in[4];
    const float* ln1_bias  = (const float*)d_in[5];
    const float* Wqkv      = (const float*)d_in[6];
    const float* bqkv      = (const float*)d_in[7];
    const float* Wo        = (const float*)d_in[8];
    const float* bo        = (const float*)d_in[9];
    const float* ln2_scale = (const float*)d_in[10];
    const float* ln2_bias  = (const float*)d_in[11];
    const float* Wmlp1     = (const float*)d_in[12];
    const float* bmlp1     = (const float*)d_in[13];
    const float* Wmlp2     = (const float*)d_in[14];
    const float* bmlp2     = (const float*)d_in[15];
    const float* kan_amp   = (const float*)d_in[16];
    float* out = (float*)d_out;

    void *p0,*p1,*p2,*p3,*p4,*p5,*p6,*p7,*p8,*p9,*p10,*p11,*p12;
    cudaGetSymbolAddress(&p0, g_patch_h); cudaGetSymbolAddress(&p1, g_tok);
    cudaGetSymbolAddress(&p2, g_x);       cudaGetSymbolAddress(&p3, g_h_h);
    cudaGetSymbolAddress(&p4, g_qkv);     cudaGetSymbolAddress(&p5, g_y_h);
    cudaGetSymbolAddress(&p6, g_ff_h);    cudaGetSymbolAddress(&p7, g_logits);
    cudaGetSymbolAddress(&p8, g_wmap_t);  cudaGetSymbolAddress(&p9, g_wqkv_t);
    cudaGetSymbolAddress(&p10, g_wo_t);   cudaGetSymbolAddress(&p11, g_wm1_t);
    cudaGetSymbolAddress(&p12, g_wm2_t);
    __half* patch_h = (__half*)p0;
    float* tok = (float*)p1;
    float* x   = (float*)p2;
    __half* h_h = (__half*)p3;
    float* qkv = (float*)p4;
    __half* y_h = (__half*)p5;
    __half* ff_h = (__half*)p6;
    float* logits = (float*)p7;
    __half* wmap_t = (__half*)p8;
    __half* wqkv_t = (__half*)p9;
    __half* wo_t   = (__half*)p10;
    __half* wm1_t  = (__half*)p11;
    __half* wm2_t  = (__half*)p12;

    cudaFuncSetAttribute(attn_kernel, cudaFuncAttributeMaxDynamicSharedMemorySize, (int)ATTN_SMEM);
    cudaFuncSetAttribute(mma_gemm_kernel, cudaFuncAttributeMaxDynamicSharedMemorySize, GEMM_SMEM);

    // weight convert+transpose
    wconv_kernel<<<dim3(DMODEL/32, DMODEL/32), 256>>>(W_map, wmap_t, DMODEL, DMODEL);
    for (int blk = 0; blk < NBLK; blk++) {
        wconv_kernel<<<dim3(3*DMODEL/32, DMODEL/32), 256>>>(
            Wqkv + (size_t)blk*DMODEL*3*DMODEL, wqkv_t + (size_t)blk*3*DMODEL*DMODEL, DMODEL, 3*DMODEL);
        wconv_kernel<<<dim3(DMODEL/32, DMODEL/32), 256>>>(
            Wo + (size_t)blk*DMODEL*DMODEL, wo_t + (size_t)blk*DMODEL*DMODEL, DMODEL, DMODEL);
        wconv_kernel<<<dim3(FFDIM/32, DMODEL/32), 256>>>(
            Wmlp1 + (size_t)blk*DMODEL*FFDIM, wm1_t + (size_t)blk*FFDIM*DMODEL, DMODEL, FFDIM);
        wconv_kernel<<<dim3(DMODEL/32, FFDIM/32), 256>>>(
            Wmlp2 + (size_t)blk*FFDIM*DMODEL, wm2_t + (size_t)blk*DMODEL*FFDIM, FFDIM, DMODEL);
    }

    // patch embed
    patch_kernel<<<(M_PAT*DMODEL + 255)/256, 256>>>(images, patch_h);
    mma_gemm_kernel<<<dim3(DMODEL/128, M_PAT/128), 256, GEMM_SMEM>>>(
        patch_h, wmap_t, b_map, nullptr, tok, nullptr, M_PAT, DMODEL, DMODEL, 0);
    embed_kernel<<<(M_ALL*DMODEL + 255)/256, 256>>>(tok, v_class, x);

    for (int blk = 0; blk < NBLK; blk++) {
        ln_kernel<<<M_ALL, 256>>>(x, ln1_scale + (size_t)blk*DMODEL, ln1_bias + (size_t)blk*DMODEL, h_h);
        mma_gemm_kernel<<<dim3(3*DMODEL/128, MPAD/128), 256, GEMM_SMEM>>>(
            h_h, wqkv_t + (size_t)blk*3*DMODEL*DMODEL, bqkv + (size_t)blk*3*DMODEL,
            nullptr, qkv, nullptr, M_ALL, 3*DMODEL, DMODEL, 0);
        attn_kernel<<<dim3(NHEAD, BATCH), 256, ATTN_SMEM>>>(qkv, y_h);
        mma_gemm_kernel<<<dim3(DMODEL/128, MPAD/128), 256, GEMM_SMEM>>>(
            y_h, wo_t + (size_t)blk*DMODEL*DMODEL, bo + (size_t)blk*DMODEL,
            x, x, nullptr, M_ALL, DMODEL, DMODEL, 0);
        ln_kernel<<<M_ALL, 256>>>(x, ln2_scale + (size_t)blk*DMODEL, ln2_bias + (size_t)blk*DMODEL, h_h);
        mma_gemm_kernel<<<dim3(FFDIM/128, MPAD/128), 256, GEMM_SMEM>>>(
            h_h, wm1_t + (size_t)blk*FFDIM*DMODEL, bmlp1 + (size_t)blk*FFDIM,
            nullptr, nullptr, ff_h, M_ALL, FFDIM, DMODEL, 1);
        mma_gemm_kernel<<<dim3(DMODEL/128, MPAD/128), 256, GEMM_SMEM>>>(
            ff_h, wm2_t + (size_t)blk*DMODEL*FFDIM, bmlp2 + (size_t)blk*DMODEL,
            x, x, nullptr, M_ALL, DMODEL, FFDIM, 0);
    }

    head_kernel<<<dim3(BATCH, 125), 256>>>(x, kan_amp, logits);
    softmax_kernel<<<BATCH, 256>>>(logits, out);
}

// round 8
// speedup vs baseline: 5.9062x; 1.6081x over previous
#include <cuda_runtime.h>
#include <cuda_fp16.h>
#include <stdint.h>
#include <math.h>

#define BATCH 64
#define SEQ   197
#define DMODEL 768
#define NBLK  12
#define NHEAD 12
#define DHEAD 64
#define FFDIM 3072
#define NOUT  1000
#define NTOK  196
#define M_ALL (BATCH*SEQ)   // 12608
#define M_PAT (BATCH*NTOK)  // 12544
#define MPAD  12800

// ---- scratch ----
__device__ __align__(16) __half g_patch_h[(size_t)M_PAT * DMODEL];
__device__ float  g_tok   [(size_t)M_PAT * DMODEL];
__device__ float  g_x     [(size_t)M_ALL * DMODEL];
__device__ __align__(16) __half g_h_h [(size_t)MPAD * DMODEL];
__device__ __align__(16) __half g_qkv_h[(size_t)M_ALL * 3 * DMODEL];
__device__ __align__(16) __half g_y_h [(size_t)MPAD * DMODEL];
__device__ __align__(16) __half g_ff_h[(size_t)MPAD * FFDIM];
__device__ float  g_logits[BATCH * NOUT];
__device__ __align__(16) __half g_wmap_t[(size_t)DMODEL * DMODEL];
__device__ __align__(16) __half g_wqkv_t[(size_t)NBLK * 3 * DMODEL * DMODEL];
__device__ __align__(16) __half g_wo_t  [(size_t)NBLK * DMODEL * DMODEL];
__device__ __align__(16) __half g_wm1_t [(size_t)NBLK * FFDIM * DMODEL];
__device__ __align__(16) __half g_wm2_t [(size_t)NBLK * DMODEL * FFDIM];

__device__ __forceinline__ void cpasync16(uint32_t s, const void* g) {
    asm volatile("cp.async.cg.shared.global [%0], [%1], 16;" :: "r"(s), "l"(g));
}
__device__ __forceinline__ uint32_t smem_u32(const void* p) {
    uint32_t a;
    asm("{ .reg .u64 t; cvta.to.shared.u64 t, %1; cvt.u32.u64 %0, t; }" : "=r"(a) : "l"(p));
    return a;
}
#define CP_COMMIT() asm volatile("cp.async.commit_group;" ::: "memory")
#define CP_WAIT1()  asm volatile("cp.async.wait_group 1;" ::: "memory")
#define CP_WAIT0()  asm volatile("cp.async.wait_group 0;" ::: "memory")

__device__ __forceinline__ void mma_f16(float& c0, float& c1, float& c2, float& c3,
                                        uint32_t a0, uint32_t a1, uint32_t a2, uint32_t a3,
                                        uint32_t b0, uint32_t b1) {
    asm volatile("mma.sync.aligned.m16n8k16.row.col.f32.f16.f16.f32 "
                 "{%0,%1,%2,%3}, {%4,%5,%6,%7}, {%8,%9}, {%0,%1,%2,%3};"
                 : "+f"(c0), "+f"(c1), "+f"(c2), "+f"(c3)
                 : "r"(a0), "r"(a1), "r"(a2), "r"(a3), "r"(b0), "r"(b1));
}

// ---- HMMA GEMM (unchanged from R7) ----
#define LDK 72
#define STAGE_E (128 * LDK)
#define GEMM_SMEM (4 * STAGE_E * 2)

__global__ __launch_bounds__(256, 2) void mma_gemm_kernel(
    const __half* __restrict__ A, const __half* __restrict__ Bw,
    const float* __restrict__ bias, const float* __restrict__ res,
    float* __restrict__ outF, __half* __restrict__ outS,
    int Mreal, int N, int K, int act)
{
    extern __shared__ __half smem[];
    int tid = threadIdx.x;
    int wid = tid >> 5, lane = tid & 31;
    int warpM = wid & 1, warpN = wid >> 1;
    int gid = lane >> 2, tig = lane & 3;
    int mT = blockIdx.y * 128, nT = blockIdx.x * 128;
    const int C = K / 64;

    const __half* Ab = A + (size_t)mT * K;
    const __half* Bb = Bw + (size_t)nT * K;
    uint32_t sbase = smem_u32(smem);

    int ldrow[4], ldseg[4];
#pragma unroll
    for (int i = 0; i < 4; i++) {
        int c = tid + i * 256;
        ldrow[i] = c >> 3;
        ldseg[i] = c & 7;
    }

    auto load_chunk = [&](int c) {
        int s = c & 1;
        int kOff = c * 64;
        uint32_t sA = sbase + s * (2 * STAGE_E * 2);
        uint32_t sB = sA + STAGE_E * 2;
#pragma unroll
        for (int i = 0; i < 4; i++) {
            int r = ldrow[i], sg = ldseg[i];
            cpasync16(sA + (r * LDK + sg * 8) * 2, Ab + (size_t)r * K + kOff + sg * 8);
            cpasync16(sB + (r * LDK + sg * 8) * 2, Bb + (size_t)r * K + kOff + sg * 8);
        }
        CP_COMMIT();
    };

    float acc[4][4][4];
#pragma unroll
    for (int i = 0; i < 4; i++)
#pragma unroll
        for (int j = 0; j < 4; j++)
#pragma unroll
            for (int k = 0; k < 4; k++) acc[i][j][k] = 0.0f;

    load_chunk(0);
    if (C > 1) load_chunk(1);

    for (int c = 0; c < C; c++) {
        if (c + 1 < C) CP_WAIT1(); else CP_WAIT0();
        __syncthreads();
        const __half* As = smem + (c & 1) * 2 * STAGE_E;
        const __half* Bs = As + STAGE_E;
#pragma unroll
        for (int ks = 0; ks < 4; ks++) {
            int kk = ks * 16 + tig * 2;
            uint32_t a[4][4], b[4][2];
#pragma unroll
            for (int mt = 0; mt < 4; mt++) {
                const __half* ap = As + (warpM * 64 + mt * 16 + gid) * LDK + kk;
                a[mt][0] = *(const uint32_t*)(ap);
                a[mt][1] = *(const uint32_t*)(ap + 8 * LDK);
                a[mt][2] = *(const uint32_t*)(ap + 8);
                a[mt][3] = *(const uint32_t*)(ap + 8 * LDK + 8);
            }
#pragma unroll
            for (int nt = 0; nt < 4; nt++) {
                const __half* bp = Bs + (warpN * 32 + nt * 8 + gid) * LDK + kk;
                b[nt][0] = *(const uint32_t*)(bp);
                b[nt][1] = *(const uint32_t*)(bp + 8);
            }
#pragma unroll
            for (int mt = 0; mt < 4; mt++)
#pragma unroll
                for (int nt = 0; nt < 4; nt++)
                    mma_f16(acc[mt][nt][0], acc[mt][nt][1], acc[mt][nt][2], acc[mt][nt][3],
                            a[mt][0], a[mt][1], a[mt][2], a[mt][3], b[nt][0], b[nt][1]);
        }
        __syncthreads();
        if (c + 2 < C) load_chunk(c + 2);
    }

#pragma unroll
    for (int mt = 0; mt < 4; mt++) {
#pragma unroll
        for (int half_ = 0; half_ < 2; half_++) {
            int row = mT + warpM * 64 + mt * 16 + gid + half_ * 8;
            if (row >= Mreal) continue;
#pragma unroll
            for (int nt = 0; nt < 4; nt++) {
                int col = nT + warpN * 32 + nt * 8 + tig * 2;
                float v0 = acc[mt][nt][half_ * 2 + 0];
                float v1 = acc[mt][nt][half_ * 2 + 1];
                float2 bb = *(const float2*)(bias + col);
                v0 += bb.x; v1 += bb.y;
                if (act == 1) {
                    float u;
                    u = v0; v0 = 0.5f*u*(1.0f + tanhf(0.7978845608028654f*(u + 0.044715f*u*u*u)));
                    u = v1; v1 = 0.5f*u*(1.0f + tanhf(0.7978845608028654f*(u + 0.044715f*u*u*u)));
                }
                if (res) {
                    float2 rr = *(const float2*)(res + (size_t)row * N + col);
                    v0 += rr.x; v1 += rr.y;
                }
                if (outF) *(float2*)(outF + (size_t)row * N + col) = make_float2(v0, v1);
                if (outS) {
                    union { __half h[2]; uint32_t u; } P;
                    P.h[0] = __float2half_rn(v0);
                    P.h[1] = __float2half_rn(v1);
                    *(uint32_t*)(outS + (size_t)row * N + col) = P.u;
                }
            }
        }
    }
}

// ---- tensor-core attention per (b,h) ----
// smem: Q[224][72] K[224][72] fp16, Vt[64][232] fp16, S[64][228] fp32, P[64][232] fp16
#define SP 224
#define LDQK 72
#define LDV 232
#define LDSF 228
#define ATTN_SMEM (SP*LDQK*2*2 + 64*LDV*2 + 64*LDSF*4 + 64*LDV*2)  // 182272

__global__ __launch_bounds__(256) void attn_kernel(const __half* __restrict__ qkv,
                                                   __half* __restrict__ yH) {
    extern __shared__ char smc[];
    __half* Qs = (__half*)smc;
    __half* Ks = Qs + SP * LDQK;
    __half* Vt = Ks + SP * LDQK;
    float*  Sf = (float*)(Vt + 64 * LDV);
    __half* Pm = (__half*)(Sf + 64 * LDSF);

    int h = blockIdx.x, b = blockIdx.y;
    int tid = threadIdx.x, wid = tid >> 5, lane = tid & 31;
    int gid = lane >> 2, tig = lane & 3;
    int wm = wid >> 2, wn = wid & 3;  // 2 x 4

    const __half* base = qkv + (size_t)(b * SEQ) * (3 * DMODEL) + h * DHEAD;

    // stage Q (x0.125) and K (u32 = 2 halves per thread)
    for (int idx = tid; idx < SP * 32; idx += 256) {
        int t = idx >> 5, p = idx & 31;
        uint32_t qv = 0, kv = 0;
        if (t < SEQ) {
            const __half* rp = base + (size_t)t * (3 * DMODEL);
            __half2 q2 = *(const __half2*)(rp + 2 * p);
            float2 qf = __half22float2(q2);
            __half2 qs = __floats2half2_rn(qf.x * 0.125f, qf.y * 0.125f);
            qv = *(uint32_t*)&qs;
            kv = *(const uint32_t*)(rp + DMODEL + 2 * p);
        }
        *(uint32_t*)(Qs + t * LDQK + 2 * p) = qv;
        *(uint32_t*)(Ks + t * LDQK + 2 * p) = kv;
    }
    // stage V transposed
    for (int idx = tid; idx < SP * 64; idx += 256) {
        int t = idx >> 6, d = idx & 63;
        __half v = __float2half(0.0f);
        if (t < SEQ) v = base[(size_t)t * (3 * DMODEL) + 2 * DMODEL + d];
        Vt[d * LDV + t] = v;
    }
    __syncthreads();

    for (int q0 = 0; q0 < SP; q0 += 64) {
        // ---- S = Q(chunk) @ K^T : warp tile 32x56, grid 2x4 ----
        float c[2][7][4];
#pragma unroll
        for (int mi = 0; mi < 2; mi++)
#pragma unroll
            for (int ni = 0; ni < 7; ni++)
#pragma unroll
                for (int k = 0; k < 4; k++) c[mi][ni][k] = 0.0f;
#pragma unroll
        for (int ks = 0; ks < 4; ks++) {
            int kk = ks * 16 + tig * 2;
            uint32_t a[2][4], bf[7][2];
#pragma unroll
            for (int mi = 0; mi < 2; mi++) {
                const __half* ap = Qs + (q0 + wm * 32 + mi * 16 + gid) * LDQK + kk;
                a[mi][0] = *(const uint32_t*)(ap);
                a[mi][1] = *(const uint32_t*)(ap + 8 * LDQK);
                a[mi][2] = *(const uint32_t*)(ap + 8);
                a[mi][3] = *(const uint32_t*)(ap + 8 * LDQK + 8);
            }
#pragma unroll
            for (int ni = 0; ni < 7; ni++) {
                const __half* bp = Ks + (wn * 56 + ni * 8 + gid) * LDQK + kk;
                bf[ni][0] = *(const uint32_t*)(bp);
                bf[ni][1] = *(const uint32_t*)(bp + 8);
            }
#pragma unroll
            for (int mi = 0; mi < 2; mi++)
#pragma unroll
                for (int ni = 0; ni < 7; ni++)
                    mma_f16(c[mi][ni][0], c[mi][ni][1], c[mi][ni][2], c[mi][ni][3],
                            a[mi][0], a[mi][1], a[mi][2], a[mi][3], bf[ni][0], bf[ni][1]);
        }
#pragma unroll
        for (int mi = 0; mi < 2; mi++) {
            int r = wm * 32 + mi * 16 + gid;
#pragma unroll
            for (int ni = 0; ni < 7; ni++) {
                int cb = wn * 56 + ni * 8 + 2 * tig;
                *(float2*)(Sf + r * LDSF + cb)       = make_float2(c[mi][ni][0], c[mi][ni][1]);
                *(float2*)(Sf + (r + 8) * LDSF + cb) = make_float2(c[mi][ni][2], c[mi][ni][3]);
            }
        }
        __syncthreads();

        // ---- softmax rows (8 rows per warp) -> P fp16 normalized ----
        for (int i = 0; i < 8; i++) {
            int row = wid * 8 + i;
            int q = q0 + row;
            if (q >= SEQ) break;
            float vals[7], m = -1e30f;
#pragma unroll
            for (int j = 0; j < 7; j++) {
                int cc = lane + 32 * j;
                float v = (cc < SEQ) ? Sf[row * LDSF + cc] : -1e30f;
                vals[j] = v; m = fmaxf(m, v);
            }
#pragma unroll
            for (int o = 16; o > 0; o >>= 1) m = fmaxf(m, __shfl_xor_sync(0xffffffffu, m, o));
            float sum = 0.0f;
#pragma unroll
            for (int j = 0; j < 7; j++) {
                int cc = lane + 32 * j;
                float e = (cc < SEQ) ? __expf(vals[j] - m) : 0.0f;
                vals[j] = e; sum += e;
            }
#pragma unroll
            for (int o = 16; o > 0; o >>= 1) sum += __shfl_xor_sync(0xffffffffu, sum, o);
            float inv = 1.0f / sum;
#pragma unroll
            for (int j = 0; j < 7; j++) {
                int cc = lane + 32 * j;
                Pm[row * LDV + cc] = __float2half(vals[j] * inv);
            }
        }
        __syncthreads();

        // ---- O(chunk) = P @ V^T : warp tile 32x16, grid 2x4, k=224 ----
        float o[2][2][4];
#pragma unroll
        for (int mi = 0; mi < 2; mi++)
#pragma unroll
            for (int ni = 0; ni < 2; ni++)
#pragma unroll
                for (int k = 0; k < 4; k++) o[mi][ni][k] = 0.0f;
#pragma unroll
        for (int ks = 0; ks < 14; ks++) {
            int kk = ks * 16 + tig * 2;
            uint32_t a[2][4], bf[2][2];
#pragma unroll
            for (int mi = 0; mi < 2; mi++) {
                const __half* ap = Pm + (wm * 32 + mi * 16 + gid) * LDV + kk;
                a[mi][0] = *(const uint32_t*)(ap);
                a[mi][1] = *(const uint32_t*)(ap + 8 * LDV);
                a[mi][2] = *(const uint32_t*)(ap + 8);
                a[mi][3] = *(const uint32_t*)(ap + 8 * LDV + 8);
            }
#pragma unroll
            for (int ni = 0; ni < 2; ni++) {
                const __half* bp = Vt + (wn * 16 + ni * 8 + gid) * LDV + kk;
                bf[ni][0] = *(const uint32_t*)(bp);
                bf[ni][1] = *(const uint32_t*)(bp + 8);
            }
#pragma unroll
            for (int mi = 0; mi < 2; mi++)
#pragma unroll
                for (int ni = 0; ni < 2; ni++)
                    mma_f16(o[mi][ni][0], o[mi][ni][1], o[mi][ni][2], o[mi][ni][3],
                            a[mi][0], a[mi][1], a[mi][2], a[mi][3], bf[ni][0], bf[ni][1]);
        }
#pragma unroll
        for (int mi = 0; mi < 2; mi++) {
#pragma unroll
            for (int half_ = 0; half_ < 2; half_++) {
                int q = q0 + wm * 32 + mi * 16 + gid + half_ * 8;
                if (q >= SEQ) continue;
#pragma unroll
                for (int ni = 0; ni < 2; ni++) {
                    int d = wn * 16 + ni * 8 + 2 * tig;
                    union { __half h[2]; uint32_t u; } P2;
                    P2.h[0] = __float2half_rn(o[mi][ni][half_ * 2 + 0]);
                    P2.h[1] = __float2half_rn(o[mi][ni][half_ * 2 + 1]);
                    *(uint32_t*)(yH + (size_t)(b * SEQ + q) * DMODEL + h * DHEAD + d) = P2.u;
                }
            }
        }
        __syncthreads();
    }
}

// ---- weight convert+transpose ----
__global__ __launch_bounds__(256) void wconv_kernel(const float* __restrict__ W,
                                                    __half* __restrict__ out,
                                                    int K, int N) {
    __shared__ float t[32][33];
    int k0 = blockIdx.y * 32, n0 = blockIdx.x * 32;
    int tx = threadIdx.x & 31, ty = threadIdx.x >> 5;
    for (int i = ty; i < 32; i += 8) t[i][tx] = W[(size_t)(k0 + i) * N + n0 + tx];
    __syncthreads();
    for (int i = ty; i < 32; i += 8)
        out[(size_t)(n0 + i) * K + k0 + tx] = __float2half_rn(t[tx][i]);
}

// ---- patch extraction ----
__global__ __launch_bounds__(256) void patch_kernel(const float* __restrict__ img,
                                                    __half* __restrict__ out) {
    int idx = blockIdx.x * 256 + threadIdx.x;
    if (idx >= M_PAT * DMODEL) return;
    int i = idx % DMODEL, row = idx / DMODEL;
    int p = row % NTOK, b = row / NTOK;
    int c = i >> 8, rem = i & 255, iy = rem >> 4, ix = rem & 15;
    int py = p / 14, px = p % 14;
    float v = img[(((size_t)(b*3 + c) * 224) + py*16 + iy) * 224 + px*16 + ix];
    out[idx] = __float2half_rn(v);
}

// ---- embed ----
__global__ __launch_bounds__(256) void embed_kernel(const float* __restrict__ tok,
                                                    const float* __restrict__ v_class,
                                                    float* __restrict__ x) {
    int idx = blockIdx.x * 256 + threadIdx.x;
    if (idx >= M_ALL * DMODEL) return;
    int d = idx % DMODEL, r = idx / DMODEL;
    int s = r % SEQ, b = r / SEQ;
    float t = (s == 0) ? v_class[d] : tok[(size_t)(b * NTOK + s - 1) * DMODEL + d];
    float ang = (float)s / powf(10000.0f, (float)d / (float)DMODEL);
    x[idx] = t + (((d & 1) == 0) ? sinf(ang) : cosf(ang));
}

// ---- LayerNorm -> fp16 ----
__global__ __launch_bounds__(256) void ln_kernel(const float* __restrict__ x,
                                                 const float* __restrict__ gamma,
                                                 const float* __restrict__ beta,
                                                 __half* __restrict__ outH) {
    int row = blockIdx.x, tid = threadIdx.x;
    const float* xr = x + (size_t)row * DMODEL;
    float v0 = xr[tid], v1 = xr[tid+256], v2 = xr[tid+512];
    __shared__ float red[256];
    red[tid] = v0 + v1 + v2; __syncthreads();
    for (int o = 128; o > 0; o >>= 1) { if (tid < o) red[tid] += red[tid+o]; __syncthreads(); }
    float mean = red[0] * (1.0f / DMODEL); __syncthreads();
    float d0 = v0-mean, d1 = v1-mean, d2 = v2-mean;
    red[tid] = d0*d0 + d1*d1 + d2*d2; __syncthreads();
    for (int o = 128; o > 0; o >>= 1) { if (tid < o) red[tid] += red[tid+o]; __syncthreads(); }
    float rstd = rsqrtf(red[0] * (1.0f / DMODEL) + 1e-5f);
    __half* orow = outH + (size_t)row * DMODEL;
    orow[tid]     = __float2half_rn(d0*rstd*gamma[tid]     + beta[tid]);
    orow[tid+256] = __float2half_rn(d1*rstd*gamma[tid+256] + beta[tid+256]);
    orow[tid+512] = __float2half_rn(d2*rstd*gamma[tid+512] + beta[tid+512]);
}

// ---- KAN head ----
__global__ __launch_bounds__(256) void head_kernel(const float* __restrict__ x,
                                                   const float* __restrict__ amp,
                                                   float* __restrict__ logits) {
    __shared__ float sines[4 * DMODEL];
    int b = blockIdx.x, tid = threadIdx.x;
    const float* xr = x + (size_t)b * SEQ * DMODEL;
    const float PI = 3.14159265358979323846f;
    for (int i = tid; i < DMODEL; i += 256) {
        float xv = xr[i], ph = (float)i * (PI / (float)DMODEL);
#pragma unroll
        for (int g = 0; g < 4; g++) sines[g*DMODEL + i] = sinf(xv * (float)(g+1) + ph);
    }
    __syncthreads();
    int warp = tid >> 5, lane = tid & 31;
    int o = blockIdx.y * 8 + warp;
    if (o < NOUT) {
        const float* ar = amp + (size_t)o * 4 * DMODEL;
        float acc = 0.0f;
        for (int i = lane; i < 4*DMODEL; i += 32) acc = fmaf(sines[i], ar[i], acc);
#pragma unroll
        for (int of = 16; of > 0; of >>= 1) acc += __shfl_xor_sync(0xffffffffu, acc, of);
        if (lane == 0) logits[(size_t)b*NOUT + o] = acc * (1.0f / 55.42562584220407f);
    }
}

// ---- softmax ----
__global__ __launch_bounds__(256) void softmax_kernel(const float* __restrict__ logits,
                                                      float* __restrict__ out) {
    int b = blockIdx.x, tid = threadIdx.x;
    const float* lr = logits + (size_t)b * NOUT;
    __shared__ float red[256];
    float m = -1e30f;
    for (int i = tid; i < NOUT; i += 256) m = fmaxf(m, lr[i]);
    red[tid] = m; __syncthreads();
    for (int o = 128; o > 0; o >>= 1) { if (tid < o) red[tid] = fmaxf(red[tid], red[tid+o]); __syncthreads(); }
    m = red[0]; __syncthreads();
    float s = 0.0f;
    for (int i = tid; i < NOUT; i += 256) s += expf(lr[i] - m);
    red[tid] = s; __syncthreads();
    for (int o = 128; o > 0; o >>= 1) { if (tid < o) red[tid] += red[tid+o]; __syncthreads(); }
    float inv = 1.0f / red[0];
    for (int i = tid; i < NOUT; i += 256) out[(size_t)b*NOUT + i] = expf(lr[i] - m) * inv;
}

// ---- launch ----
extern "C" void kernel_launch(void* const* d_in, const int* in_sizes, int n_in,
                              void* d_out, int out_size) {
    (void)in_sizes; (void)n_in; (void)out_size;
    const float* images    = (const float*)d_in[0];
    const float* v_class   = (const float*)d_in[1];
    const float* W_map     = (const float*)d_in[2];
    const float* b_map     = (const float*)d_in[3];
    const float* ln1_scale = (const float*)d_in[4];
    const float* ln1_bias  = (const float*)d_in[5];
    const float* Wqkv      = (const float*)d_in[6];
    const float* bqkv      = (const float*)d_in[7];
    const float* Wo        = (const float*)d_in[8];
    const float* bo        = (const float*)d_in[9];
    const float* ln2_scale = (const float*)d_in[10];
    const float* ln2_bias  = (const float*)d_in[11];
    const float* Wmlp1     = (const float*)d_in[12];
    const float* bmlp1     = (const float*)d_in[13];
    const float* Wmlp2     = (const float*)d_in[14];
    const float* bmlp2     = (const float*)d_in[15];
    const float* kan_amp   = (const float*)d_in[16];
    float* out = (float*)d_out;

    void *p0,*p1,*p2,*p3,*p4,*p5,*p6,*p7,*p8,*p9,*p10,*p11,*p12;
    cudaGetSymbolAddress(&p0, g_patch_h); cudaGetSymbolAddress(&p1, g_tok);
    cudaGetSymbolAddress(&p2, g_x);       cudaGetSymbolAddress(&p3, g_h_h);
    cudaGetSymbolAddress(&p4, g_qkv_h);   cudaGetSymbolAddress(&p5, g_y_h);
    cudaGetSymbolAddress(&p6, g_ff_h);    cudaGetSymbolAddress(&p7, g_logits);
    cudaGetSymbolAddress(&p8, g_wmap_t);  cudaGetSymbolAddress(&p9, g_wqkv_t);
    cudaGetSymbolAddress(&p10, g_wo_t);   cudaGetSymbolAddress(&p11, g_wm1_t);
    cudaGetSymbolAddress(&p12, g_wm2_t);
    __half* patch_h = (__half*)p0;
    float* tok = (float*)p1;
    float* x   = (float*)p2;
    __half* h_h = (__half*)p3;
    __half* qkv_h = (__half*)p4;
    __half* y_h = (__half*)p5;
    __half* ff_h = (__half*)p6;
    float* logits = (float*)p7;
    __half* wmap_t = (__half*)p8;
    __half* wqkv_t = (__half*)p9;
    __half* wo_t   = (__half*)p10;
    __half* wm1_t  = (__half*)p11;
    __half* wm2_t  = (__half*)p12;

    cudaFuncSetAttribute(attn_kernel, cudaFuncAttributeMaxDynamicSharedMemorySize, (int)ATTN_SMEM);
    cudaFuncSetAttribute(mma_gemm_kernel, cudaFuncAttributeMaxDynamicSharedMemorySize, GEMM_SMEM);

    wconv_kernel<<<dim3(DMODEL/32, DMODEL/32), 256>>>(W_map, wmap_t, DMODEL, DMODEL);
    for (int blk = 0; blk < NBLK; blk++) {
        wconv_kernel<<<dim3(3*DMODEL/32, DMODEL/32), 256>>>(
            Wqkv + (size_t)blk*DMODEL*3*DMODEL, wqkv_t + (size_t)blk*3*DMODEL*DMODEL, DMODEL, 3*DMODEL);
        wconv_kernel<<<dim3(DMODEL/32, DMODEL/32), 256>>>(
            Wo + (size_t)blk*DMODEL*DMODEL, wo_t + (size_t)blk*DMODEL*DMODEL, DMODEL, DMODEL);
        wconv_kernel<<<dim3(FFDIM/32, DMODEL/32), 256>>>(
            Wmlp1 + (size_t)blk*DMODEL*FFDIM, wm1_t + (size_t)blk*FFDIM*DMODEL, DMODEL, FFDIM);
        wconv_kernel<<<dim3(DMODEL/32, FFDIM/32), 256>>>(
            Wmlp2 + (size_t)blk*FFDIM*DMODEL, wm2_t + (size_t)blk*DMODEL*FFDIM, FFDIM, DMODEL);
    }

    patch_kernel<<<(M_PAT*DMODEL + 255)/256, 256>>>(images, patch_h);
    mma_gemm_kernel<<<dim3(DMODEL/128, M_PAT/128), 256, GEMM_SMEM>>>(
        patch_h, wmap_t, b_map, nullptr, tok, nullptr, M_PAT, DMODEL, DMODEL, 0);
    embed_kernel<<<(M_ALL*DMODEL + 255)/256, 256>>>(tok, v_class, x);

    for (int blk = 0; blk < NBLK; blk++) {
        ln_kernel<<<M_ALL, 256>>>(x, ln1_scale + (size_t)blk*DMODEL, ln1_bias + (size_t)blk*DMODEL, h_h);
        mma_gemm_kernel<<<dim3(3*DMODEL/128, MPAD/128), 256, GEMM_SMEM>>>(
            h_h, wqkv_t + (size_t)blk*3*DMODEL*DMODEL, bqkv + (size_t)blk*3*DMODEL,
            nullptr, nullptr, qkv_h, M_ALL, 3*DMODEL, DMODEL, 0);
        attn_kernel<<<dim3(NHEAD, BATCH), 256, ATTN_SMEM>>>(qkv_h, y_h);
        mma_gemm_kernel<<<dim3(DMODEL/128, MPAD/128), 256, GEMM_SMEM>>>(
            y_h, wo_t + (size_t)blk*DMODEL*DMODEL, bo + (size_t)blk*DMODEL,
            x, x, nullptr, M_ALL, DMODEL, DMODEL, 0);
        ln_kernel<<<M_ALL, 256>>>(x, ln2_scale + (size_t)blk*DMODEL, ln2_bias + (size_t)blk*DMODEL, h_h);
        mma_gemm_kernel<<<dim3(FFDIM/128, MPAD/128), 256, GEMM_SMEM>>>(
            h_h, wm1_t + (size_t)blk*FFDIM*DMODEL, bmlp1 + (size_t)blk*FFDIM,
            nullptr, nullptr, ff_h, M_ALL, FFDIM, DMODEL, 1);
        mma_gemm_kernel<<<dim3(DMODEL/128, MPAD/128), 256, GEMM_SMEM>>>(
            ff_h, wm2_t + (size_t)blk*DMODEL*FFDIM, bmlp2 + (size_t)blk*DMODEL,
            x, x, nullptr, M_ALL, DMODEL, FFDIM, 0);
    }

    head_kernel<<<dim3(BATCH, 125), 256>>>(x, kan_amp, logits);
    softmax_kernel<<<BATCH, 256>>>(logits, out);
}

// round 9
// speedup vs baseline: 6.1950x; 1.0489x over previous
#include <cuda_runtime.h>
#include <cuda_fp16.h>
#include <stdint.h>
#include <math.h>

#define BATCH 64
#define SEQ   197
#define DMODEL 768
#define NBLK  12
#define NHEAD 12
#define DHEAD 64
#define FFDIM 3072
#define NOUT  1000
#define NTOK  196
#define M_ALL (BATCH*SEQ)   // 12608
#define M_PAT (BATCH*NTOK)  // 12544
#define MPAD  12800

// ---- scratch ----
__device__ __align__(16) __half g_patch_h[(size_t)M_PAT * DMODEL];
__device__ float  g_tok   [(size_t)M_PAT * DMODEL];
__device__ float  g_x     [(size_t)M_ALL * DMODEL];
__device__ __align__(16) __half g_h_h [(size_t)MPAD * DMODEL];
__device__ __align__(16) __half g_qkv_h[(size_t)M_ALL * 3 * DMODEL];
__device__ __align__(16) __half g_y_h [(size_t)MPAD * DMODEL];
__device__ __align__(16) __half g_ff_h[(size_t)MPAD * FFDIM];
__device__ float  g_logits[BATCH * NOUT];
__device__ __align__(16) __half g_wmap_t[(size_t)DMODEL * DMODEL];
__device__ __align__(16) __half g_wqkv_t[(size_t)NBLK * 3 * DMODEL * DMODEL];
__device__ __align__(16) __half g_wo_t  [(size_t)NBLK * DMODEL * DMODEL];
__device__ __align__(16) __half g_wm1_t [(size_t)NBLK * FFDIM * DMODEL];
__device__ __align__(16) __half g_wm2_t [(size_t)NBLK * DMODEL * FFDIM];

__device__ __forceinline__ void cpasync16(uint32_t s, const void* g) {
    asm volatile("cp.async.cg.shared.global [%0], [%1], 16;" :: "r"(s), "l"(g));
}
__device__ __forceinline__ uint32_t smem_u32(const void* p) {
    uint32_t a;
    asm("{ .reg .u64 t; cvta.to.shared.u64 t, %1; cvt.u32.u64 %0, t; }" : "=r"(a) : "l"(p));
    return a;
}
#define CP_COMMIT() asm volatile("cp.async.commit_group;" ::: "memory")
#define CP_WAIT1()  asm volatile("cp.async.wait_group 1;" ::: "memory")
#define CP_WAIT0()  asm volatile("cp.async.wait_group 0;" ::: "memory")

__device__ __forceinline__ void mma_f16f32(float& c0, float& c1, float& c2, float& c3,
                                           uint32_t a0, uint32_t a1, uint32_t a2, uint32_t a3,
                                           uint32_t b0, uint32_t b1) {
    asm volatile("mma.sync.aligned.m16n8k16.row.col.f32.f16.f16.f32 "
                 "{%0,%1,%2,%3}, {%4,%5,%6,%7}, {%8,%9}, {%0,%1,%2,%3};"
                 : "+f"(c0), "+f"(c1), "+f"(c2), "+f"(c3)
                 : "r"(a0), "r"(a1), "r"(a2), "r"(a3), "r"(b0), "r"(b1));
}
__device__ __forceinline__ void mma_f16acc(uint32_t& d0, uint32_t& d1,
                                           uint32_t a0, uint32_t a1, uint32_t a2, uint32_t a3,
                                           uint32_t b0, uint32_t b1) {
    asm volatile("mma.sync.aligned.m16n8k16.row.col.f16.f16.f16.f16 "
                 "{%0,%1}, {%2,%3,%4,%5}, {%6,%7}, {%0,%1};"
                 : "+r"(d0), "+r"(d1)
                 : "r"(a0), "r"(a1), "r"(a2), "r"(a3), "r"(b0), "r"(b1));
}

// ---- HMMA GEMM, fp16 accumulators ----
#define LDK 72
#define STAGE_E (128 * LDK)
#define GEMM_SMEM (4 * STAGE_E * 2)

__global__ __launch_bounds__(256, 2) void mma_gemm_kernel(
    const __half* __restrict__ A, const __half* __restrict__ Bw,
    const float* __restrict__ bias, const float* __restrict__ res,
    float* __restrict__ outF, __half* __restrict__ outS,
    int Mreal, int N, int K, int act)
{
    extern __shared__ __half smem[];
    int tid = threadIdx.x;
    int wid = tid >> 5, lane = tid & 31;
    int warpM = wid & 1, warpN = wid >> 1;
    int gid = lane >> 2, tig = lane & 3;
    int mT = blockIdx.y * 128, nT = blockIdx.x * 128;
    const int C = K / 64;

    const __half* Ab = A + (size_t)mT * K;
    const __half* Bb = Bw + (size_t)nT * K;
    uint32_t sbase = smem_u32(smem);

    int ldrow[4], ldseg[4];
#pragma unroll
    for (int i = 0; i < 4; i++) {
        int c = tid + i * 256;
        ldrow[i] = c >> 3;
        ldseg[i] = c & 7;
    }

    auto load_chunk = [&](int c) {
        int s = c & 1;
        int kOff = c * 64;
        uint32_t sA = sbase + s * (2 * STAGE_E * 2);
        uint32_t sB = sA + STAGE_E * 2;
#pragma unroll
        for (int i = 0; i < 4; i++) {
            int r = ldrow[i], sg = ldseg[i];
            cpasync16(sA + (r * LDK + sg * 8) * 2, Ab + (size_t)r * K + kOff + sg * 8);
            cpasync16(sB + (r * LDK + sg * 8) * 2, Bb + (size_t)r * K + kOff + sg * 8);
        }
        CP_COMMIT();
    };

    uint32_t acc[4][4][2];
#pragma unroll
    for (int i = 0; i < 4; i++)
#pragma unroll
        for (int j = 0; j < 4; j++) { acc[i][j][0] = 0u; acc[i][j][1] = 0u; }

    load_chunk(0);
    if (C > 1) load_chunk(1);

    for (int c = 0; c < C; c++) {
        if (c + 1 < C) CP_WAIT1(); else CP_WAIT0();
        __syncthreads();
        const __half* As = smem + (c & 1) * 2 * STAGE_E;
        const __half* Bs = As + STAGE_E;
#pragma unroll
        for (int ks = 0; ks < 4; ks++) {
            int kk = ks * 16 + tig * 2;
            uint32_t a[4][4], b[4][2];
#pragma unroll
            for (int mt = 0; mt < 4; mt++) {
                const __half* ap = As + (warpM * 64 + mt * 16 + gid) * LDK + kk;
                a[mt][0] = *(const uint32_t*)(ap);
                a[mt][1] = *(const uint32_t*)(ap + 8 * LDK);
                a[mt][2] = *(const uint32_t*)(ap + 8);
                a[mt][3] = *(const uint32_t*)(ap + 8 * LDK + 8);
            }
#pragma unroll
            for (int nt = 0; nt < 4; nt++) {
                const __half* bp = Bs + (warpN * 32 + nt * 8 + gid) * LDK + kk;
                b[nt][0] = *(const uint32_t*)(bp);
                b[nt][1] = *(const uint32_t*)(bp + 8);
            }
#pragma unroll
            for (int mt = 0; mt < 4; mt++)
#pragma unroll
                for (int nt = 0; nt < 4; nt++)
                    mma_f16acc(acc[mt][nt][0], acc[mt][nt][1],
                               a[mt][0], a[mt][1], a[mt][2], a[mt][3], b[nt][0], b[nt][1]);
        }
        __syncthreads();
        if (c + 2 < C) load_chunk(c + 2);
    }

#pragma unroll
    for (int mt = 0; mt < 4; mt++) {
#pragma unroll
        for (int half_ = 0; half_ < 2; half_++) {
            int row = mT + warpM * 64 + mt * 16 + gid + half_ * 8;
            if (row >= Mreal) continue;
#pragma unroll
            for (int nt = 0; nt < 4; nt++) {
                int col = nT + warpN * 32 + nt * 8 + tig * 2;
                float2 vf = __half22float2(*(__half2*)&acc[mt][nt][half_]);
                float v0 = vf.x, v1 = vf.y;
                float2 bb = *(const float2*)(bias + col);
                v0 += bb.x; v1 += bb.y;
                if (act == 1) {
                    float u;
                    u = v0; v0 = 0.5f*u*(1.0f + tanhf(0.7978845608028654f*(u + 0.044715f*u*u*u)));
                    u = v1; v1 = 0.5f*u*(1.0f + tanhf(0.7978845608028654f*(u + 0.044715f*u*u*u)));
                }
                if (res) {
                    float2 rr = *(const float2*)(res + (size_t)row * N + col);
                    v0 += rr.x; v1 += rr.y;
                }
                if (outF) *(float2*)(outF + (size_t)row * N + col) = make_float2(v0, v1);
                if (outS) {
                    union { __half h[2]; uint32_t u; } P;
                    P.h[0] = __float2half_rn(v0);
                    P.h[1] = __float2half_rn(v1);
                    *(uint32_t*)(outS + (size_t)row * N + col) = P.u;
                }
            }
        }
    }
}

// ---- tensor-core attention per (b,h) (unchanged, f32 acc) ----
#define SP 224
#define LDQK 72
#define LDV 232
#define LDSF 228
#define ATTN_SMEM (SP*LDQK*2*2 + 64*LDV*2 + 64*LDSF*4 + 64*LDV*2)

__global__ __launch_bounds__(256) void attn_kernel(const __half* __restrict__ qkv,
                                                   __half* __restrict__ yH) {
    extern __shared__ char smc[];
    __half* Qs = (__half*)smc;
    __half* Ks = Qs + SP * LDQK;
    __half* Vt = Ks + SP * LDQK;
    float*  Sf = (float*)(Vt + 64 * LDV);
    __half* Pm = (__half*)(Sf + 64 * LDSF);

    int h = blockIdx.x, b = blockIdx.y;
    int tid = threadIdx.x, wid = tid >> 5, lane = tid & 31;
    int gid = lane >> 2, tig = lane & 3;
    int wm = wid >> 2, wn = wid & 3;

    const __half* base = qkv + (size_t)(b * SEQ) * (3 * DMODEL) + h * DHEAD;

    for (int idx = tid; idx < SP * 32; idx += 256) {
        int t = idx >> 5, p = idx & 31;
        uint32_t qv = 0, kv = 0;
        if (t < SEQ) {
            const __half* rp = base + (size_t)t * (3 * DMODEL);
            __half2 q2 = *(const __half2*)(rp + 2 * p);
            float2 qf = __half22float2(q2);
            __half2 qs = __floats2half2_rn(qf.x * 0.125f, qf.y * 0.125f);
            qv = *(uint32_t*)&qs;
            kv = *(const uint32_t*)(rp + DMODEL + 2 * p);
        }
        *(uint32_t*)(Qs + t * LDQK + 2 * p) = qv;
        *(uint32_t*)(Ks + t * LDQK + 2 * p) = kv;
    }
    for (int idx = tid; idx < SP * 64; idx += 256) {
        int t = idx >> 6, d = idx & 63;
        __half v = __float2half(0.0f);
        if (t < SEQ) v = base[(size_t)t * (3 * DMODEL) + 2 * DMODEL + d];
        Vt[d * LDV + t] = v;
    }
    __syncthreads();

    for (int q0 = 0; q0 < SP; q0 += 64) {
        float c[2][7][4];
#pragma unroll
        for (int mi = 0; mi < 2; mi++)
#pragma unroll
            for (int ni = 0; ni < 7; ni++)
#pragma unroll
                for (int k = 0; k < 4; k++) c[mi][ni][k] = 0.0f;
#pragma unroll
        for (int ks = 0; ks < 4; ks++) {
            int kk = ks * 16 + tig * 2;
            uint32_t a[2][4], bf[7][2];
#pragma unroll
            for (int mi = 0; mi < 2; mi++) {
                const __half* ap = Qs + (q0 + wm * 32 + mi * 16 + gid) * LDQK + kk;
                a[mi][0] = *(const uint32_t*)(ap);
                a[mi][1] = *(const uint32_t*)(ap + 8 * LDQK);
                a[mi][2] = *(const uint32_t*)(ap + 8);
                a[mi][3] = *(const uint32_t*)(ap + 8 * LDQK + 8);
            }
#pragma unroll
            for (int ni = 0; ni < 7; ni++) {
                const __half* bp = Ks + (wn * 56 + ni * 8 + gid) * LDQK + kk;
                bf[ni][0] = *(const uint32_t*)(bp);
                bf[ni][1] = *(const uint32_t*)(bp + 8);
            }
#pragma unroll
            for (int mi = 0; mi < 2; mi++)
#pragma unroll
                for (int ni = 0; ni < 7; ni++)
                    mma_f16f32(c[mi][ni][0], c[mi][ni][1], c[mi][ni][2], c[mi][ni][3],
                               a[mi][0], a[mi][1], a[mi][2], a[mi][3], bf[ni][0], bf[ni][1]);
        }
#pragma unroll
        for (int mi = 0; mi < 2; mi++) {
            int r = wm * 32 + mi * 16 + gid;
#pragma unroll
            for (int ni = 0; ni < 7; ni++) {
                int cb = wn * 56 + ni * 8 + 2 * tig;
                *(float2*)(Sf + r * LDSF + cb)       = make_float2(c[mi][ni][0], c[mi][ni][1]);
                *(float2*)(Sf + (r + 8) * LDSF + cb) = make_float2(c[mi][ni][2], c[mi][ni][3]);
            }
        }
        __syncthreads();

        for (int i = 0; i < 8; i++) {
            int row = wid * 8 + i;
            int q = q0 + row;
            if (q >= SEQ) break;
            float vals[7], m = -1e30f;
#pragma unroll
            for (int j = 0; j < 7; j++) {
                int cc = lane + 32 * j;
                float v = (cc < SEQ) ? Sf[row * LDSF + cc] : -1e30f;
                vals[j] = v; m = fmaxf(m, v);
            }
#pragma unroll
            for (int o = 16; o > 0; o >>= 1) m = fmaxf(m, __shfl_xor_sync(0xffffffffu, m, o));
            float sum = 0.0f;
#pragma unroll
            for (int j = 0; j < 7; j++) {
                int cc = lane + 32 * j;
                float e = (cc < SEQ) ? __expf(vals[j] - m) : 0.0f;
                vals[j] = e; sum += e;
            }
#pragma unroll
            for (int o = 16; o > 0; o >>= 1) sum += __shfl_xor_sync(0xffffffffu, sum, o);
            float inv = 1.0f / sum;
#pragma unroll
            for (int j = 0; j < 7; j++) {
                int cc = lane + 32 * j;
                Pm[row * LDV + cc] = __float2half(vals[j] * inv);
            }
        }
        __syncthreads();

        float o[2][2][4];
#pragma unroll
        for (int mi = 0; mi < 2; mi++)
#pragma unroll
            for (int ni = 0; ni < 2; ni++)
#pragma unroll
                for (int k = 0; k < 4; k++) o[mi][ni][k] = 0.0f;
#pragma unroll
        for (int ks = 0; ks < 14; ks++) {
            int kk = ks * 16 + tig * 2;
            uint32_t a[2][4], bf[2][2];
#pragma unroll
            for (int mi = 0; mi < 2; mi++) {
                const __half* ap = Pm + (wm * 32 + mi * 16 + gid) * LDV + kk;
                a[mi][0] = *(const uint32_t*)(ap);
                a[mi][1] = *(const uint32_t*)(ap + 8 * LDV);
                a[mi][2] = *(const uint32_t*)(ap + 8);
                a[mi][3] = *(const uint32_t*)(ap + 8 * LDV + 8);
            }
#pragma unroll
            for (int ni = 0; ni < 2; ni++) {
                const __half* bp = Vt + (wn * 16 + ni * 8 + gid) * LDV + kk;
                bf[ni][0] = *(const uint32_t*)(bp);
                bf[ni][1] = *(const uint32_t*)(bp + 8);
            }
#pragma unroll
            for (int mi = 0; mi < 2; mi++)
#pragma unroll
                for (int ni = 0; ni < 2; ni++)
                    mma_f16f32(o[mi][ni][0], o[mi][ni][1], o[mi][ni][2], o[mi][ni][3],
                               a[mi][0], a[mi][1], a[mi][2], a[mi][3], bf[ni][0], bf[ni][1]);
        }
#pragma unroll
        for (int mi = 0; mi < 2; mi++) {
#pragma unroll
            for (int half_ = 0; half_ < 2; half_++) {
                int q = q0 + wm * 32 + mi * 16 + gid + half_ * 8;
                if (q >= SEQ) continue;
#pragma unroll
                for (int ni = 0; ni < 2; ni++) {
                    int d = wn * 16 + ni * 8 + 2 * tig;
                    union { __half h[2]; uint32_t u; } P2;
                    P2.h[0] = __float2half_rn(o[mi][ni][half_ * 2 + 0]);
                    P2.h[1] = __float2half_rn(o[mi][ni][half_ * 2 + 1]);
                    *(uint32_t*)(yH + (size_t)(b * SEQ + q) * DMODEL + h * DHEAD + d) = P2.u;
                }
            }
        }
        __syncthreads();
    }
}

// ---- weight convert+transpose, batched over blocks via gridDim.z ----
__global__ __launch_bounds__(256) void wconv_kernel(const float* __restrict__ W,
                                                    __half* __restrict__ out,
                                                    int K, int N) {
    __shared__ float t[32][33];
    W   += (size_t)blockIdx.z * K * N;
    out += (size_t)blockIdx.z * N * K;
    int k0 = blockIdx.y * 32, n0 = blockIdx.x * 32;
    int tx = threadIdx.x & 31, ty = threadIdx.x >> 5;
    for (int i = ty; i < 32; i += 8) t[i][tx] = W[(size_t)(k0 + i) * N + n0 + tx];
    __syncthreads();
    for (int i = ty; i < 32; i += 8)
        out[(size_t)(n0 + i) * K + k0 + tx] = __float2half_rn(t[tx][i]);
}

// ---- patch extraction ----
__global__ __launch_bounds__(256) void patch_kernel(const float* __restrict__ img,
                                                    __half* __restrict__ out) {
    int idx = blockIdx.x * 256 + threadIdx.x;
    if (idx >= M_PAT * DMODEL) return;
    int i = idx % DMODEL, row = idx / DMODEL;
    int p = row % NTOK, b = row / NTOK;
    int c = i >> 8, rem = i & 255, iy = rem >> 4, ix = rem & 15;
    int py = p / 14, px = p % 14;
    float v = img[(((size_t)(b*3 + c) * 224) + py*16 + iy) * 224 + px*16 + ix];
    out[idx] = __float2half_rn(v);
}

// ---- embed ----
__global__ __launch_bounds__(256) void embed_kernel(const float* __restrict__ tok,
                                                    const float* __restrict__ v_class,
                                                    float* __restrict__ x) {
    int idx = blockIdx.x * 256 + threadIdx.x;
    if (idx >= M_ALL * DMODEL) return;
    int d = idx % DMODEL, r = idx / DMODEL;
    int s = r % SEQ, b = r / SEQ;
    float t = (s == 0) ? v_class[d] : tok[(size_t)(b * NTOK + s - 1) * DMODEL + d];
    float ang = (float)s * __expf((float)d * (-9.210340371976184f / (float)DMODEL));
    x[idx] = t + (((d & 1) == 0) ? sinf(ang) : cosf(ang));
}

// ---- LayerNorm: warp per row, shuffle-only reductions ----
__global__ __launch_bounds__(256) void ln_kernel(const float* __restrict__ x,
                                                 const float* __restrict__ gamma,
                                                 const float* __restrict__ beta,
                                                 __half* __restrict__ outH) {
    int warp = threadIdx.x >> 5, lane = threadIdx.x & 31;
    int row = blockIdx.x * 8 + warp;
    const float4* xr = (const float4*)(x + (size_t)row * DMODEL);
    float4 v[6];
    float sum = 0.0f;
#pragma unroll
    for (int j = 0; j < 6; j++) {
        v[j] = xr[lane + 32 * j];
        sum += v[j].x + v[j].y + v[j].z + v[j].w;
    }
#pragma unroll
    for (int o = 16; o > 0; o >>= 1) sum += __shfl_xor_sync(0xffffffffu, sum, o);
    float mean = sum * (1.0f / DMODEL);
    float var = 0.0f;
#pragma unroll
    for (int j = 0; j < 6; j++) {
        float a = v[j].x - mean, b = v[j].y - mean, c = v[j].z - mean, d = v[j].w - mean;
        var += a*a + b*b + c*c + d*d;
    }
#pragma unroll
    for (int o = 16; o > 0; o >>= 1) var += __shfl_xor_sync(0xffffffffu, var, o);
    float rstd = rsqrtf(var * (1.0f / DMODEL) + 1e-5f);

    const float4* gr = (const float4*)gamma;
    const float4* br = (const float4*)beta;
    uint2* orow = (uint2*)(outH + (size_t)row * DMODEL);
#pragma unroll
    for (int j = 0; j < 6; j++) {
        float4 g = gr[lane + 32 * j], bb = br[lane + 32 * j];
        float o0 = (v[j].x - mean) * rstd * g.x + bb.x;
        float o1 = (v[j].y - mean) * rstd * g.y + bb.y;
        float o2 = (v[j].z - mean) * rstd * g.z + bb.z;
        float o3 = (v[j].w - mean) * rstd * g.w + bb.w;
        __half2 h01 = __floats2half2_rn(o0, o1);
        __half2 h23 = __floats2half2_rn(o2, o3);
        uint2 u;
        u.x = *(uint32_t*)&h01;
        u.y = *(uint32_t*)&h23;
        orow[lane + 32 * j] = u;
    }
}

// ---- KAN head ----
__global__ __launch_bounds__(256) void head_kernel(const float* __restrict__ x,
                                                   const float* __restrict__ amp,
                                                   float* __restrict__ logits) {
    __shared__ float sines[4 * DMODEL];
    int b = blockIdx.x, tid = threadIdx.x;
    const float* xr = x + (size_t)b * SEQ * DMODEL;
    const float PI = 3.14159265358979323846f;
    for (int i = tid; i < DMODEL; i += 256) {
        float xv = xr[i], ph = (float)i * (PI / (float)DMODEL);
#pragma unroll
        for (int g = 0; g < 4; g++) sines[g*DMODEL + i] = sinf(xv * (float)(g+1) + ph);
    }
    __syncthreads();
    int warp = tid >> 5, lane = tid & 31;
    int o = blockIdx.y * 8 + warp;
    if (o < NOUT) {
        const float* ar = amp + (size_t)o * 4 * DMODEL;
        float acc = 0.0f;
        for (int i = lane; i < 4*DMODEL; i += 32) acc = fmaf(sines[i], ar[i], acc);
#pragma unroll
        for (int of = 16; of > 0; of >>= 1) acc += __shfl_xor_sync(0xffffffffu, acc, of);
        if (lane == 0) logits[(size_t)b*NOUT + o] = acc * (1.0f / 55.42562584220407f);
    }
}

// ---- softmax ----
__global__ __launch_bounds__(256) void softmax_kernel(const float* __restrict__ logits,
                                                      float* __restrict__ out) {
    int b = blockIdx.x, tid = threadIdx.x;
    const float* lr = logits + (size_t)b * NOUT;
    __shared__ float red[256];
    float m = -1e30f;
    for (int i = tid; i < NOUT; i += 256) m = fmaxf(m, lr[i]);
    red[tid] = m; __syncthreads();
    for (int o = 128; o > 0; o >>= 1) { if (tid < o) red[tid] = fmaxf(red[tid], red[tid+o]); __syncthreads(); }
    m = red[0]; __syncthreads();
    float s = 0.0f;
    for (int i = tid; i < NOUT; i += 256) s += expf(lr[i] - m);
    red[tid] = s; __syncthreads();
    for (int o = 128; o > 0; o >>= 1) { if (tid < o) red[tid] += red[tid+o]; __syncthreads(); }
    float inv = 1.0f / red[0];
    for (int i = tid; i < NOUT; i += 256) out[(size_t)b*NOUT + i] = expf(lr[i] - m) * inv;
}

// ---- launch ----
extern "C" void kernel_launch(void* const* d_in, const int* in_sizes, int n_in,
                              void* d_out, int out_size) {
    (void)in_sizes; (void)n_in; (void)out_size;
    const float* images    = (const float*)d_in[0];
    const float* v_class   = (const float*)d_in[1];
    const float* W_map     = (const float*)d_in[2];
    const float* b_map     = (const float*)d_in[3];
    const float* ln1_scale = (const float*)d_in[4];
    const float* ln1_bias  = (const float*)d_in[5];
    const float* Wqkv      = (const float*)d_in[6];
    const float* bqkv      = (const float*)d_in[7];
    const float* Wo        = (const float*)d_in[8];
    const float* bo        = (const float*)d_in[9];
    const float* ln2_scale = (const float*)d_in[10];
    const float* ln2_bias  = (const float*)d_in[11];
    const float* Wmlp1     = (const float*)d_in[12];
    const float* bmlp1     = (const float*)d_in[13];
    const float* Wmlp2     = (const float*)d_in[14];
    const float* bmlp2     = (const float*)d_in[15];
    const float* kan_amp   = (const float*)d_in[16];
    float* out = (float*)d_out;

    void *p0,*p1,*p2,*p3,*p4,*p5,*p6,*p7,*p8,*p9,*p10,*p11,*p12;
    cudaGetSymbolAddress(&p0, g_patch_h); cudaGetSymbolAddress(&p1, g_tok);
    cudaGetSymbolAddress(&p2, g_x);       cudaGetSymbolAddress(&p3, g_h_h);
    cudaGetSymbolAddress(&p4, g_qkv_h);   cudaGetSymbolAddress(&p5, g_y_h);
    cudaGetSymbolAddress(&p6, g_ff_h);    cudaGetSymbolAddress(&p7, g_logits);
    cudaGetSymbolAddress(&p8, g_wmap_t);  cudaGetSymbolAddress(&p9, g_wqkv_t);
    cudaGetSymbolAddress(&p10, g_wo_t);   cudaGetSymbolAddress(&p11, g_wm1_t);
    cudaGetSymbolAddress(&p12, g_wm2_t);
    __half* patch_h = (__half*)p0;
    float* tok = (float*)p1;
    float* x   = (float*)p2;
    __half* h_h = (__half*)p3;
    __half* qkv_h = (__half*)p4;
    __half* y_h = (__half*)p5;
    __half* ff_h = (__half*)p6;
    float* logits = (float*)p7;
    __half* wmap_t = (__half*)p8;
    __half* wqkv_t = (__half*)p9;
    __half* wo_t   = (__half*)p10;
    __half* wm1_t  = (__half*)p11;
    __half* wm2_t  = (__half*)p12;

    cudaFuncSetAttribute(attn_kernel, cudaFuncAttributeMaxDynamicSharedMemorySize, (int)ATTN_SMEM);
    cudaFuncSetAttribute(mma_gemm_kernel, cudaFuncAttributeMaxDynamicSharedMemorySize, GEMM_SMEM);

    // batched weight converts (5 launches total)
    wconv_kernel<<<dim3(DMODEL/32, DMODEL/32, 1), 256>>>(W_map, wmap_t, DMODEL, DMODEL);
    wconv_kernel<<<dim3(3*DMODEL/32, DMODEL/32, NBLK), 256>>>(Wqkv, wqkv_t, DMODEL, 3*DMODEL);
    wconv_kernel<<<dim3(DMODEL/32, DMODEL/32, NBLK), 256>>>(Wo, wo_t, DMODEL, DMODEL);
    wconv_kernel<<<dim3(FFDIM/32, DMODEL/32, NBLK), 256>>>(Wmlp1, wm1_t, DMODEL, FFDIM);
    wconv_kernel<<<dim3(DMODEL/32, FFDIM/32, NBLK), 256>>>(Wmlp2, wm2_t, FFDIM, DMODEL);

    patch_kernel<<<(M_PAT*DMODEL + 255)/256, 256>>>(images, patch_h);
    mma_gemm_kernel<<<dim3(DMODEL/128, M_PAT/128), 256, GEMM_SMEM>>>(
        patch_h, wmap_t, b_map, nullptr, tok, nullptr, M_PAT, DMODEL, DMODEL, 0);
    embed_kernel<<<(M_ALL*DMODEL + 255)/256, 256>>>(tok, v_class, x);

    for (int blk = 0; blk < NBLK; blk++) {
        ln_kernel<<<M_ALL/8, 256>>>(x, ln1_scale + (size_t)blk*DMODEL, ln1_bias + (size_t)blk*DMODEL, h_h);
        mma_gemm_kernel<<<dim3(3*DMODEL/128, MPAD/128), 256, GEMM_SMEM>>>(
            h_h, wqkv_t + (size_t)blk*3*DMODEL*DMODEL, bqkv + (size_t)blk*3*DMODEL,
            nullptr, nullptr, qkv_h, M_ALL, 3*DMODEL, DMODEL, 0);
        attn_kernel<<<dim3(NHEAD, BATCH), 256, ATTN_SMEM>>>(qkv_h, y_h);
        mma_gemm_kernel<<<dim3(DMODEL/128, MPAD/128), 256, GEMM_SMEM>>>(
            y_h, wo_t + (size_t)blk*DMODEL*DMODEL, bo + (size_t)blk*DMODEL,
            x, x, nullptr, M_ALL, DMODEL, DMODEL, 0);
        ln_kernel<<<M_ALL/8, 256>>>(x, ln2_scale + (size_t)blk*DMODEL, ln2_bias + (size_t)blk*DMODEL, h_h);
        mma_gemm_kernel<<<dim3(FFDIM/128, MPAD/128), 256, GEMM_SMEM>>>(
            h_h, wm1_t + (size_t)blk*FFDIM*DMODEL, bmlp1 + (size_t)blk*FFDIM,
            nullptr, nullptr, ff_h, M_ALL, FFDIM, DMODEL, 1);
        mma_gemm_kernel<<<dim3(DMODEL/128, MPAD/128), 256, GEMM_SMEM>>>(
            ff_h, wm2_t + (size_t)blk*DMODEL*FFDIM, bmlp2 + (size_t)blk*DMODEL,
            x, x, nullptr, M_ALL, DMODEL, FFDIM, 0);
    }

    head_kernel<<<dim3(BATCH, 125), 256>>>(x, kan_amp, logits);
    softmax_kernel<<<BATCH, 256>>>(logits, out);
}

// round 10
// speedup vs baseline: 6.8210x; 1.1010x over previous
#include <cuda_runtime.h>
#include <cuda_fp16.h>
#include <stdint.h>
#include <math.h>

#define BATCH 64
#define SEQ   197
#define DMODEL 768
#define NBLK  12
#define NHEAD 12
#define DHEAD 64
#define FFDIM 3072
#define NOUT  1000
#define NTOK  196
#define M_ALL (BATCH*SEQ)   // 12608
#define M_PAT (BATCH*NTOK)  // 12544
#define MPAD  12800
#define MTILES 99           // ceil(12608/128)

// ---- scratch ----
__device__ __align__(16) __half g_patch_h[(size_t)M_PAT * DMODEL];
__device__ float  g_tok   [(size_t)M_PAT * DMODEL];
__device__ float  g_x     [(size_t)M_ALL * DMODEL];
__device__ __align__(16) __half g_h_h [(size_t)MPAD * DMODEL];
__device__ __align__(16) __half g_qkv_h[(size_t)M_ALL * 3 * DMODEL];
__device__ __align__(16) __half g_y_h [(size_t)MPAD * DMODEL];
__device__ __align__(16) __half g_ff_h[(size_t)MPAD * FFDIM];
__device__ float  g_logits[BATCH * NOUT];
__device__ __align__(16) __half g_wmap_t[(size_t)DMODEL * DMODEL];
__device__ __align__(16) __half g_wqkv_t[(size_t)NBLK * 3 * DMODEL * DMODEL];
__device__ __align__(16) __half g_wo_t  [(size_t)NBLK * DMODEL * DMODEL];
__device__ __align__(16) __half g_wm1_t [(size_t)NBLK * FFDIM * DMODEL];
__device__ __align__(16) __half g_wm2_t [(size_t)NBLK * DMODEL * FFDIM];

__device__ __forceinline__ void cpasync16(uint32_t s, const void* g) {
    asm volatile("cp.async.cg.shared.global [%0], [%1], 16;" :: "r"(s), "l"(g));
}
__device__ __forceinline__ uint32_t smem_u32(const void* p) {
    uint32_t a;
    asm("{ .reg .u64 t; cvta.to.shared.u64 t, %1; cvt.u32.u64 %0, t; }" : "=r"(a) : "l"(p));
    return a;
}
#define CP_COMMIT() asm volatile("cp.async.commit_group;" ::: "memory")
#define CP_WAIT1()  asm volatile("cp.async.wait_group 1;" ::: "memory")
#define CP_WAIT0()  asm volatile("cp.async.wait_group 0;" ::: "memory")

__device__ __forceinline__ void mma_f16f32(float& c0, float& c1, float& c2, float& c3,
                                           uint32_t a0, uint32_t a1, uint32_t a2, uint32_t a3,
                                           uint32_t b0, uint32_t b1) {
    asm volatile("mma.sync.aligned.m16n8k16.row.col.f32.f16.f16.f32 "
                 "{%0,%1,%2,%3}, {%4,%5,%6,%7}, {%8,%9}, {%0,%1,%2,%3};"
                 : "+f"(c0), "+f"(c1), "+f"(c2), "+f"(c3)
                 : "r"(a0), "r"(a1), "r"(a2), "r"(a3), "r"(b0), "r"(b1));
}

// ---- HMMA GEMM, f32 accumulators ----
#define LDK 72
#define STAGE_E (128 * LDK)
#define GEMM_SMEM (4 * STAGE_E * 2)

__global__ __launch_bounds__(256, 2) void mma_gemm_kernel(
    const __half* __restrict__ A, const __half* __restrict__ Bw,
    const float* __restrict__ bias, const float* __restrict__ res,
    float* __restrict__ outF, __half* __restrict__ outS,
    int Mreal, int N, int K, int act)
{
    extern __shared__ __half smem[];
    int tid = threadIdx.x;
    int wid = tid >> 5, lane = tid & 31;
    int warpM = wid & 1, warpN = wid >> 1;
    int gid = lane >> 2, tig = lane & 3;
    int mT = blockIdx.y * 128, nT = blockIdx.x * 128;
    const int C = K / 64;

    const __half* Ab = A + (size_t)mT * K;
    const __half* Bb = Bw + (size_t)nT * K;
    uint32_t sbase = smem_u32(smem);

    int ldrow[4], ldseg[4];
#pragma unroll
    for (int i = 0; i < 4; i++) {
        int c = tid + i * 256;
        ldrow[i] = c >> 3;
        ldseg[i] = c & 7;
    }

    auto load_chunk = [&](int c) {
        int s = c & 1;
        int kOff = c * 64;
        uint32_t sA = sbase + s * (2 * STAGE_E * 2);
        uint32_t sB = sA + STAGE_E * 2;
#pragma unroll
        for (int i = 0; i < 4; i++) {
            int r = ldrow[i], sg = ldseg[i];
            cpasync16(sA + (r * LDK + sg * 8) * 2, Ab + (size_t)r * K + kOff + sg * 8);
            cpasync16(sB + (r * LDK + sg * 8) * 2, Bb + (size_t)r * K + kOff + sg * 8);
        }
        CP_COMMIT();
    };

    float acc[4][4][4];
#pragma unroll
    for (int i = 0; i < 4; i++)
#pragma unroll
        for (int j = 0; j < 4; j++)
#pragma unroll
            for (int k = 0; k < 4; k++) acc[i][j][k] = 0.0f;

    load_chunk(0);
    if (C > 1) load_chunk(1);

    for (int c = 0; c < C; c++) {
        if (c + 1 < C) CP_WAIT1(); else CP_WAIT0();
        __syncthreads();
        const __half* As = smem + (c & 1) * 2 * STAGE_E;
        const __half* Bs = As + STAGE_E;
#pragma unroll
        for (int ks = 0; ks < 4; ks++) {
            int kk = ks * 16 + tig * 2;
            uint32_t a[4][4], b[4][2];
#pragma unroll
            for (int mt = 0; mt < 4; mt++) {
                const __half* ap = As + (warpM * 64 + mt * 16 + gid) * LDK + kk;
                a[mt][0] = *(const uint32_t*)(ap);
                a[mt][1] = *(const uint32_t*)(ap + 8 * LDK);
                a[mt][2] = *(const uint32_t*)(ap + 8);
                a[mt][3] = *(const uint32_t*)(ap + 8 * LDK + 8);
            }
#pragma unroll
            for (int nt = 0; nt < 4; nt++) {
                const __half* bp = Bs + (warpN * 32 + nt * 8 + gid) * LDK + kk;
                b[nt][0] = *(const uint32_t*)(bp);
                b[nt][1] = *(const uint32_t*)(bp + 8);
            }
#pragma unroll
            for (int mt = 0; mt < 4; mt++)
#pragma unroll
                for (int nt = 0; nt < 4; nt++)
                    mma_f16f32(acc[mt][nt][0], acc[mt][nt][1], acc[mt][nt][2], acc[mt][nt][3],
                               a[mt][0], a[mt][1], a[mt][2], a[mt][3], b[nt][0], b[nt][1]);
        }
        __syncthreads();
        if (c + 2 < C) load_chunk(c + 2);
    }

#pragma unroll
    for (int mt = 0; mt < 4; mt++) {
#pragma unroll
        for (int half_ = 0; half_ < 2; half_++) {
            int row = mT + warpM * 64 + mt * 16 + gid + half_ * 8;
            if (row >= Mreal) continue;
#pragma unroll
            for (int nt = 0; nt < 4; nt++) {
                int col = nT + warpN * 32 + nt * 8 + tig * 2;
                float v0 = acc[mt][nt][half_ * 2 + 0];
                float v1 = acc[mt][nt][half_ * 2 + 1];
                float2 bb = *(const float2*)(bias + col);
                v0 += bb.x; v1 += bb.y;
                if (act == 1) {
                    float u;
                    u = v0; v0 = 0.5f*u*(1.0f + tanhf(0.7978845608028654f*(u + 0.044715f*u*u*u)));
                    u = v1; v1 = 0.5f*u*(1.0f + tanhf(0.7978845608028654f*(u + 0.044715f*u*u*u)));
                }
                if (res) {
                    float2 rr = *(const float2*)(res + (size_t)row * N + col);
                    v0 += rr.x; v1 += rr.y;
                }
                if (outF) *(float2*)(outF + (size_t)row * N + col) = make_float2(v0, v1);
                if (outS) {
                    union { __half h[2]; uint32_t u; } P;
                    P.h[0] = __float2half_rn(v0);
                    P.h[1] = __float2half_rn(v1);
                    *(uint32_t*)(outS + (size_t)row * N + col) = P.u;
                }
            }
        }
    }
}

// ---- tensor-core attention, register softmax, 2 CTA/SM ----
// smem: Q[64][72] (per-chunk), K[224][72], Vt[64][232], Pm[64][232], redA/redB[64][4]
#define SP 224
#define LDQK 72
#define LDV 232
#define ATTN_SMEM ((64*LDQK + SP*LDQK + 64*LDV + 64*LDV) * 2 + 2 * 64 * 4 * 4)

__global__ __launch_bounds__(256, 2) void attn_kernel(const __half* __restrict__ qkv,
                                                      __half* __restrict__ yH) {
    extern __shared__ char smc[];
    __half* Qs = (__half*)smc;              // 64 x 72
    __half* Ks = Qs + 64 * LDQK;            // 224 x 72
    __half* Vt = Ks + SP * LDQK;            // 64 x 232
    __half* Pm = Vt + 64 * LDV;             // 64 x 232
    float*  redA = (float*)(Pm + 64 * LDV); // 64 x 4
    float*  redB = redA + 64 * 4;           // 64 x 4

    int h = blockIdx.x, b = blockIdx.y;
    int tid = threadIdx.x, wid = tid >> 5, lane = tid & 31;
    int gid = lane >> 2, tig = lane & 3;
    int wm = wid >> 2, wn = wid & 3;        // 2 x 4 warps

    const __half* base = qkv + (size_t)(b * SEQ) * (3 * DMODEL) + h * DHEAD;

    // stage K [224 x 64] (zero-padded)
    for (int idx = tid; idx < SP * 32; idx += 256) {
        int t = idx >> 5, p = idx & 31;
        uint32_t kv = 0;
        if (t < SEQ) kv = *(const uint32_t*)(base + (size_t)t * (3 * DMODEL) + DMODEL + 2 * p);
        *(uint32_t*)(Ks + t * LDQK + 2 * p) = kv;
    }
    // stage V transposed [64 x 224] (zero-padded), uint2 gmem loads
    for (int idx = tid; idx < SP * 16; idx += 256) {
        int t = idx >> 4, dq = idx & 15;
        int d = dq * 4;
        __half v[4] = {__float2half(0.f), __float2half(0.f), __float2half(0.f), __float2half(0.f)};
        if (t < SEQ) *(uint2*)v = *(const uint2*)(base + (size_t)t * (3 * DMODEL) + 2 * DMODEL + d);
        Vt[(d + 0) * LDV + t] = v[0];
        Vt[(d + 1) * LDV + t] = v[1];
        Vt[(d + 2) * LDV + t] = v[2];
        Vt[(d + 3) * LDV + t] = v[3];
    }
    __syncthreads();

    for (int q0 = 0; q0 < SP; q0 += 64) {
        // stage Q chunk (x 0.125)
        for (int idx = tid; idx < 64 * 32; idx += 256) {
            int rl = idx >> 5, p = idx & 31;
            int t = q0 + rl;
            uint32_t qv = 0;
            if (t < SEQ) {
                __half2 q2 = *(const __half2*)(base + (size_t)t * (3 * DMODEL) + 2 * p);
                float2 qf = __half22float2(q2);
                __half2 qs = __floats2half2_rn(qf.x * 0.125f, qf.y * 0.125f);
                qv = *(uint32_t*)&qs;
            }
            *(uint32_t*)(Qs + rl * LDQK + 2 * p) = qv;
        }
        __syncthreads();

        // S = Qchunk @ K^T : warp tile 32x56
        float c[2][7][4];
#pragma unroll
        for (int mi = 0; mi < 2; mi++)
#pragma unroll
            for (int ni = 0; ni < 7; ni++)
#pragma unroll
                for (int k = 0; k < 4; k++) c[mi][ni][k] = 0.0f;
#pragma unroll
        for (int ks = 0; ks < 4; ks++) {
            int kk = ks * 16 + tig * 2;
            uint32_t a[2][4], bf[7][2];
#pragma unroll
            for (int mi = 0; mi < 2; mi++) {
                const __half* ap = Qs + (wm * 32 + mi * 16 + gid) * LDQK + kk;
                a[mi][0] = *(const uint32_t*)(ap);
                a[mi][1] = *(const uint32_t*)(ap + 8 * LDQK);
                a[mi][2] = *(const uint32_t*)(ap + 8);
                a[mi][3] = *(const uint32_t*)(ap + 8 * LDQK + 8);
            }
#pragma unroll
            for (int ni = 0; ni < 7; ni++) {
                const __half* bp = Ks + (wn * 56 + ni * 8 + gid) * LDQK + kk;
                bf[ni][0] = *(const uint32_t*)(bp);
                bf[ni][1] = *(const uint32_t*)(bp + 8);
            }
#pragma unroll
            for (int mi = 0; mi < 2; mi++)
#pragma unroll
                for (int ni = 0; ni < 7; ni++)
                    mma_f16f32(c[mi][ni][0], c[mi][ni][1], c[mi][ni][2], c[mi][ni][3],
                               a[mi][0], a[mi][1], a[mi][2], a[mi][3], bf[ni][0], bf[ni][1]);
        }

        // mask padded key columns
#pragma unroll
        for (int ni = 0; ni < 7; ni++) {
            int col = wn * 56 + ni * 8 + 2 * tig;
            if (col >= SEQ) { c[0][ni][0] = c[0][ni][2] = c[1][ni][0] = c[1][ni][2] = -1e30f; }
            if (col + 1 >= SEQ) { c[0][ni][1] = c[0][ni][3] = c[1][ni][1] = c[1][ni][3] = -1e30f; }
        }

        // per-row partial max (this warp's 14 cols), reduce over tig group
#pragma unroll
        for (int mi = 0; mi < 2; mi++) {
            float m0 = -1e30f, m1 = -1e30f;
#pragma unroll
            for (int ni = 0; ni < 7; ni++) {
                m0 = fmaxf(m0, fmaxf(c[mi][ni][0], c[mi][ni][1]));
                m1 = fmaxf(m1, fmaxf(c[mi][ni][2], c[mi][ni][3]));
            }
#pragma unroll
            for (int o = 1; o <= 2; o <<= 1) {
                m0 = fmaxf(m0, __shfl_xor_sync(0xffffffffu, m0, o));
                m1 = fmaxf(m1, __shfl_xor_sync(0xffffffffu, m1, o));
            }
            if (tig == 0) {
                int rr = wm * 32 + mi * 16 + gid;
                redA[rr * 4 + wn] = m0;
                redA[(rr + 8) * 4 + wn] = m1;
            }
        }
        __syncthreads();

        // exp + partial sums
#pragma unroll
        for (int mi = 0; mi < 2; mi++) {
            int rr = wm * 32 + mi * 16 + gid;
            float4 ra = *(const float4*)(redA + rr * 4);
            float4 rb = *(const float4*)(redA + (rr + 8) * 4);
            float m0 = fmaxf(fmaxf(ra.x, ra.y), fmaxf(ra.z, ra.w));
            float m1 = fmaxf(fmaxf(rb.x, rb.y), fmaxf(rb.z, rb.w));
            float s0 = 0.0f, s1 = 0.0f;
#pragma unroll
            for (int ni = 0; ni < 7; ni++) {
                float e0 = __expf(c[mi][ni][0] - m0);
                float e1 = __expf(c[mi][ni][1] - m0);
                float e2 = __expf(c[mi][ni][2] - m1);
                float e3 = __expf(c[mi][ni][3] - m1);
                c[mi][ni][0] = e0; c[mi][ni][1] = e1; c[mi][ni][2] = e2; c[mi][ni][3] = e3;
                s0 += e0 + e1; s1 += e2 + e3;
            }
#pragma unroll
            for (int o = 1; o <= 2; o <<= 1) {
                s0 += __shfl_xor_sync(0xffffffffu, s0, o);
                s1 += __shfl_xor_sync(0xffffffffu, s1, o);
            }
            if (tig == 0) {
                redB[rr * 4 + wn] = s0;
                redB[(rr + 8) * 4 + wn] = s1;
            }
        }
        __syncthreads();

        // normalize -> Pm fp16
#pragma unroll
        for (int mi = 0; mi < 2; mi++) {
            int rr = wm * 32 + mi * 16 + gid;
            float4 ra = *(const float4*)(redB + rr * 4);
            float4 rb = *(const float4*)(redB + (rr + 8) * 4);
            float i0 = 1.0f / (ra.x + ra.y + ra.z + ra.w);
            float i1 = 1.0f / (rb.x + rb.y + rb.z + rb.w);
#pragma unroll
            for (int ni = 0; ni < 7; ni++) {
                int col = wn * 56 + ni * 8 + 2 * tig;
                __half2 p0 = __floats2half2_rn(c[mi][ni][0] * i0, c[mi][ni][1] * i0);
                __half2 p1 = __floats2half2_rn(c[mi][ni][2] * i1, c[mi][ni][3] * i1);
                *(__half2*)(Pm + rr * LDV + col) = p0;
                *(__half2*)(Pm + (rr + 8) * LDV + col) = p1;
            }
        }
        __syncthreads();

        // O = P @ V^T : warp tile 32x16, k = 224
        float o[2][2][4];
#pragma unroll
        for (int mi = 0; mi < 2; mi++)
#pragma unroll
            for (int ni = 0; ni < 2; ni++)
#pragma unroll
                for (int k = 0; k < 4; k++) o[mi][ni][k] = 0.0f;
#pragma unroll
        for (int ks = 0; ks < 14; ks++) {
            int kk = ks * 16 + tig * 2;
            uint32_t a[2][4], bf[2][2];
#pragma unroll
            for (int mi = 0; mi < 2; mi++) {
                const __half* ap = Pm + (wm * 32 + mi * 16 + gid) * LDV + kk;
                a[mi][0] = *(const uint32_t*)(ap);
                a[mi][1] = *(const uint32_t*)(ap + 8 * LDV);
                a[mi][2] = *(const uint32_t*)(ap + 8);
                a[mi][3] = *(const uint32_t*)(ap + 8 * LDV + 8);
            }
#pragma unroll
            for (int ni = 0; ni < 2; ni++) {
                const __half* bp = Vt + (wn * 16 + ni * 8 + gid) * LDV + kk;
                bf[ni][0] = *(const uint32_t*)(bp);
                bf[ni][1] = *(const uint32_t*)(bp + 8);
            }
#pragma unroll
            for (int mi = 0; mi < 2; mi++)
#pragma unroll
                for (int ni = 0; ni < 2; ni++)
                    mma_f16f32(o[mi][ni][0], o[mi][ni][1], o[mi][ni][2], o[mi][ni][3],
                               a[mi][0], a[mi][1], a[mi][2], a[mi][3], bf[ni][0], bf[ni][1]);
        }
#pragma unroll
        for (int mi = 0; mi < 2; mi++) {
#pragma unroll
            for (int half_ = 0; half_ < 2; half_++) {
                int q = q0 + wm * 32 + mi * 16 + gid + half_ * 8;
                if (q >= SEQ) continue;
#pragma unroll
                for (int ni = 0; ni < 2; ni++) {
                    int d = wn * 16 + ni * 8 + 2 * tig;
                    union { __half h[2]; uint32_t u; } P2;
                    P2.h[0] = __float2half_rn(o[mi][ni][half_ * 2 + 0]);
                    P2.h[1] = __float2half_rn(o[mi][ni][half_ * 2 + 1]);
                    *(uint32_t*)(yH + (size_t)(b * SEQ + q) * DMODEL + h * DHEAD + d) = P2.u;
                }
            }
        }
        __syncthreads();
    }
}

// ---- weight convert+transpose, batched ----
__global__ __launch_bounds__(256) void wconv_kernel(const float* __restrict__ W,
                                                    __half* __restrict__ out,
                                                    int K, int N) {
    __shared__ float t[32][33];
    W   += (size_t)blockIdx.z * K * N;
    out += (size_t)blockIdx.z * N * K;
    int k0 = blockIdx.y * 32, n0 = blockIdx.x * 32;
    int tx = threadIdx.x & 31, ty = threadIdx.x >> 5;
    for (int i = ty; i < 32; i += 8) t[i][tx] = W[(size_t)(k0 + i) * N + n0 + tx];
    __syncthreads();
    for (int i = ty; i < 32; i += 8)
        out[(size_t)(n0 + i) * K + k0 + tx] = __float2half_rn(t[tx][i]);
}

// ---- patch extraction ----
__global__ __launch_bounds__(256) void patch_kernel(const float* __restrict__ img,
                                                    __half* __restrict__ out) {
    int idx = blockIdx.x * 256 + threadIdx.x;
    if (idx >= M_PAT * DMODEL) return;
    int i = idx % DMODEL, row = idx / DMODEL;
    int p = row % NTOK, b = row / NTOK;
    int c = i >> 8, rem = i & 255, iy = rem >> 4, ix = rem & 15;
    int py = p / 14, px = p % 14;
    float v = img[(((size_t)(b*3 + c) * 224) + py*16 + iy) * 224 + px*16 + ix];
    out[idx] = __float2half_rn(v);
}

// ---- embed ----
__global__ __launch_bounds__(256) void embed_kernel(const float* __restrict__ tok,
                                                    const float* __restrict__ v_class,
                                                    float* __restrict__ x) {
    int idx = blockIdx.x * 256 + threadIdx.x;
    if (idx >= M_ALL * DMODEL) return;
    int d = idx % DMODEL, r = idx / DMODEL;
    int s = r % SEQ, b = r / SEQ;
    float t = (s == 0) ? v_class[d] : tok[(size_t)(b * NTOK + s - 1) * DMODEL + d];
    float ang = (float)s * __expf((float)d * (-9.210340371976184f / (float)DMODEL));
    x[idx] = t + (((d & 1) == 0) ? sinf(ang) : cosf(ang));
}

// ---- LayerNorm: warp per row ----
__global__ __launch_bounds__(256) void ln_kernel(const float* __restrict__ x,
                                                 const float* __restrict__ gamma,
                                                 const float* __restrict__ beta,
                                                 __half* __restrict__ outH) {
    int warp = threadIdx.x >> 5, lane = threadIdx.x & 31;
    int row = blockIdx.x * 8 + warp;
    const float4* xr = (const float4*)(x + (size_t)row * DMODEL);
    float4 v[6];
    float sum = 0.0f;
#pragma unroll
    for (int j = 0; j < 6; j++) {
        v[j] = xr[lane + 32 * j];
        sum += v[j].x + v[j].y + v[j].z + v[j].w;
    }
#pragma unroll
    for (int o = 16; o > 0; o >>= 1) sum += __shfl_xor_sync(0xffffffffu, sum, o);
    float mean = sum * (1.0f / DMODEL);
    float var = 0.0f;
#pragma unroll
    for (int j = 0; j < 6; j++) {
        float a = v[j].x - mean, b = v[j].y - mean, c = v[j].z - mean, d = v[j].w - mean;
        var += a*a + b*b + c*c + d*d;
    }
#pragma unroll
    for (int o = 16; o > 0; o >>= 1) var += __shfl_xor_sync(0xffffffffu, var, o);
    float rstd = rsqrtf(var * (1.0f / DMODEL) + 1e-5f);

    const float4* gr = (const float4*)gamma;
    const float4* br = (const float4*)beta;
    uint2* orow = (uint2*)(outH + (size_t)row * DMODEL);
#pragma unroll
    for (int j = 0; j < 6; j++) {
        float4 g = gr[lane + 32 * j], bb = br[lane + 32 * j];
        float o0 = (v[j].x - mean) * rstd * g.x + bb.x;
        float o1 = (v[j].y - mean) * rstd * g.y + bb.y;
        float o2 = (v[j].z - mean) * rstd * g.z + bb.z;
        float o3 = (v[j].w - mean) * rstd * g.w + bb.w;
        __half2 h01 = __floats2half2_rn(o0, o1);
        __half2 h23 = __floats2half2_rn(o2, o3);
        uint2 u;
        u.x = *(uint32_t*)&h01;
        u.y = *(uint32_t*)&h23;
        orow[lane + 32 * j] = u;
    }
}

// ---- KAN head ----
__global__ __launch_bounds__(256) void head_kernel(const float* __restrict__ x,
                                                   const float* __restrict__ amp,
                                                   float* __restrict__ logits) {
    __shared__ float sines[4 * DMODEL];
    int b = blockIdx.x, tid = threadIdx.x;
    const float* xr = x + (size_t)b * SEQ * DMODEL;
    const float PI = 3.14159265358979323846f;
    for (int i = tid; i < DMODEL; i += 256) {
        float xv = xr[i], ph = (float)i * (PI / (float)DMODEL);
#pragma unroll
        for (int g = 0; g < 4; g++) sines[g*DMODEL + i] = sinf(xv * (float)(g+1) + ph);
    }
    __syncthreads();
    int warp = tid >> 5, lane = tid & 31;
    int o = blockIdx.y * 8 + warp;
    if (o < NOUT) {
        const float* ar = amp + (size_t)o * 4 * DMODEL;
        float acc = 0.0f;
        for (int i = lane; i < 4*DMODEL; i += 32) acc = fmaf(sines[i], ar[i], acc);
#pragma unroll
        for (int of = 16; of > 0; of >>= 1) acc += __shfl_xor_sync(0xffffffffu, acc, of);
        if (lane == 0) logits[(size_t)b*NOUT + o] = acc * (1.0f / 55.42562584220407f);
    }
}

// ---- softmax ----
__global__ __launch_bounds__(256) void softmax_kernel(const float* __restrict__ logits,
                                                      float* __restrict__ out) {
    int b = blockIdx.x, tid = threadIdx.x;
    const float* lr = logits + (size_t)b * NOUT;
    __shared__ float red[256];
    float m = -1e30f;
    for (int i = tid; i < NOUT; i += 256) m = fmaxf(m, lr[i]);
    red[tid] = m; __syncthreads();
    for (int o = 128; o > 0; o >>= 1) { if (tid < o) red[tid] = fmaxf(red[tid], red[tid+o]); __syncthreads(); }
    m = red[0]; __syncthreads();
    float s = 0.0f;
    for (int i = tid; i < NOUT; i += 256) s += expf(lr[i] - m);
    red[tid] = s; __syncthreads();
    for (int o = 128; o > 0; o >>= 1) { if (tid < o) red[tid] += red[tid+o]; __syncthreads(); }
    float inv = 1.0f / red[0];
    for (int i = tid; i < NOUT; i += 256) out[(size_t)b*NOUT + i] = expf(lr[i] - m) * inv;
}

// ---- launch ----
extern "C" void kernel_launch(void* const* d_in, const int* in_sizes, int n_in,
                              void* d_out, int out_size) {
    (void)in_sizes; (void)n_in; (void)out_size;
    const float* images    = (const float*)d_in[0];
    const float* v_class   = (const float*)d_in[1];
    const float* W_map     = (const float*)d_in[2];
    const float* b_map     = (const float*)d_in[3];
    const float* ln1_scale = (const float*)d_in[4];
    const float* ln1_bias  = (const float*)d_in[5];
    const float* Wqkv      = (const float*)d_in[6];
    const float* bqkv      = (const float*)d_in[7];
    const float* Wo        = (const float*)d_in[8];
    const float* bo        = (const float*)d_in[9];
    const float* ln2_scale = (const float*)d_in[10];
    const float* ln2_bias  = (const float*)d_in[11];
    const float* Wmlp1     = (const float*)d_in[12];
    const float* bmlp1     = (const float*)d_in[13];
    const float* Wmlp2     = (const float*)d_in[14];
    const float* bmlp2     = (const float*)d_in[15];
    const float* kan_amp   = (const float*)d_in[16];
    float* out = (float*)d_out;

    void *p0,*p1,*p2,*p3,*p4,*p5,*p6,*p7,*p8,*p9,*p10,*p11,*p12;
    cudaGetSymbolAddress(&p0, g_patch_h); cudaGetSymbolAddress(&p1, g_tok);
    cudaGetSymbolAddress(&p2, g_x);       cudaGetSymbolAddress(&p3, g_h_h);
    cudaGetSymbolAddress(&p4, g_qkv_h);   cudaGetSymbolAddress(&p5, g_y_h);
    cudaGetSymbolAddress(&p6, g_ff_h);    cudaGetSymbolAddress(&p7, g_logits);
    cudaGetSymbolAddress(&p8, g_wmap_t);  cudaGetSymbolAddress(&p9, g_wqkv_t);
    cudaGetSymbolAddress(&p10, g_wo_t);   cudaGetSymbolAddress(&p11, g_wm1_t);
    cudaGetSymbolAddress(&p12, g_wm2_t);
    __half* patch_h = (__half*)p0;
    float* tok = (float*)p1;
    float* x   = (float*)p2;
    __half* h_h = (__half*)p3;
    __half* qkv_h = (__half*)p4;
    __half* y_h = (__half*)p5;
    __half* ff_h = (__half*)p6;
    float* logits = (float*)p7;
    __half* wmap_t = (__half*)p8;
    __half* wqkv_t = (__half*)p9;
    __half* wo_t   = (__half*)p10;
    __half* wm1_t  = (__half*)p11;
    __half* wm2_t  = (__half*)p12;

    cudaFuncSetAttribute(attn_kernel, cudaFuncAttributeMaxDynamicSharedMemorySize, (int)ATTN_SMEM);
    cudaFuncSetAttribute(mma_gemm_kernel, cudaFuncAttributeMaxDynamicSharedMemorySize, GEMM_SMEM);

    wconv_kernel<<<dim3(DMODEL/32, DMODEL/32, 1), 256>>>(W_map, wmap_t, DMODEL, DMODEL);
    wconv_kernel<<<dim3(3*DMODEL/32, DMODEL/32, NBLK), 256>>>(Wqkv, wqkv_t, DMODEL, 3*DMODEL);
    wconv_kernel<<<dim3(DMODEL/32, DMODEL/32, NBLK), 256>>>(Wo, wo_t, DMODEL, DMODEL);
    wconv_kernel<<<dim3(FFDIM/32, DMODEL/32, NBLK), 256>>>(Wmlp1, wm1_t, DMODEL, FFDIM);
    wconv_kernel<<<dim3(DMODEL/32, FFDIM/32, NBLK), 256>>>(Wmlp2, wm2_t, FFDIM, DMODEL);

    patch_kernel<<<(M_PAT*DMODEL + 255)/256, 256>>>(images, patch_h);
    mma_gemm_kernel<<<dim3(DMODEL/128, M_PAT/128), 256, GEMM_SMEM>>>(
        patch_h, wmap_t, b_map, nullptr, tok, nullptr, M_PAT, DMODEL, DMODEL, 0);
    embed_kernel<<<(M_ALL*DMODEL + 255)/256, 256>>>(tok, v_class, x);

    for (int blk = 0; blk < NBLK; blk++) {
        ln_kernel<<<M_ALL/8, 256>>>(x, ln1_scale + (size_t)blk*DMODEL, ln1_bias + (size_t)blk*DMODEL, h_h);
        mma_gemm_kernel<<<dim3(3*DMODEL/128, MTILES), 256, GEMM_SMEM>>>(
            h_h, wqkv_t + (size_t)blk*3*DMODEL*DMODEL, bqkv + (size_t)blk*3*DMODEL,
            nullptr, nullptr, qkv_h, M_ALL, 3*DMODEL, DMODEL, 0);
        attn_kernel<<<dim3(NHEAD, BATCH), 256, ATTN_SMEM>>>(qkv_h, y_h);
        mma_gemm_kernel<<<dim3(DMODEL/128, MTILES), 256, GEMM_SMEM>>>(
            y_h, wo_t + (size_t)blk*DMODEL*DMODEL, bo + (size_t)blk*DMODEL,
            x, x, nullptr, M_ALL, DMODEL, DMODEL, 0);
        ln_kernel<<<M_ALL/8, 256>>>(x, ln2_scale + (size_t)blk*DMODEL, ln2_bias + (size_t)blk*DMODEL, h_h);
        mma_gemm_kernel<<<dim3(FFDIM/128, MTILES), 256, GEMM_SMEM>>>(
            h_h, wm1_t + (size_t)blk*FFDIM*DMODEL, bmlp1 + (size_t)blk*FFDIM,
            nullptr, nullptr, ff_h, M_ALL, FFDIM, DMODEL, 1);
        mma_gemm_kernel<<<dim3(DMODEL/128, MTILES), 256, GEMM_SMEM>>>(
            ff_h, wm2_t + (size_t)blk*DMODEL*FFDIM, bmlp2 + (size_t)blk*DMODEL,
            x, x, nullptr, M_ALL, DMODEL, FFDIM, 0);
    }

    head_kernel<<<dim3(BATCH, 125), 256>>>(x, kan_amp, logits);
    softmax_kernel<<<BATCH, 256>>>(logits, out);
}

// round 11
// speedup vs baseline: 7.3412x; 1.0763x over previous
#include <cuda_runtime.h>
#include <cuda_fp16.h>
#include <stdint.h>
#include <math.h>

#define BATCH 64
#define SEQ   197
#define DMODEL 768
#define NBLK  12
#define NHEAD 12
#define DHEAD 64
#define FFDIM 3072
#define NOUT  1000
#define NTOK  196
#define M_ALL (BATCH*SEQ)   // 12608
#define M_PAT (BATCH*NTOK)  // 12544
#define MPAD  12800
#define MTILES 99           // ceil(12608/128)

// ---- scratch ----
__device__ __align__(16) __half g_patch_h[(size_t)M_PAT * DMODEL];
__device__ float  g_tok   [(size_t)M_PAT * DMODEL];
__device__ float  g_x     [(size_t)M_ALL * DMODEL];
__device__ __align__(16) __half g_h_h [(size_t)MPAD * DMODEL];
__device__ __align__(16) __half g_qkv_h[(size_t)M_ALL * 3 * DMODEL];
__device__ __align__(16) __half g_y_h [(size_t)MPAD * DMODEL];
__device__ __align__(16) __half g_ff_h[(size_t)MPAD * FFDIM];
__device__ float  g_logits[BATCH * NOUT];
__device__ __align__(16) __half g_wmap_t[(size_t)DMODEL * DMODEL];
__device__ __align__(16) __half g_wqkv_t[(size_t)NBLK * 3 * DMODEL * DMODEL];
__device__ __align__(16) __half g_wo_t  [(size_t)NBLK * DMODEL * DMODEL];
__device__ __align__(16) __half g_wm1_t [(size_t)NBLK * FFDIM * DMODEL];
__device__ __align__(16) __half g_wm2_t [(size_t)NBLK * DMODEL * FFDIM];

__device__ __forceinline__ void cpasync16(uint32_t s, const void* g) {
    asm volatile("cp.async.cg.shared.global [%0], [%1], 16;" :: "r"(s), "l"(g));
}
__device__ __forceinline__ uint32_t smem_u32(const void* p) {
    uint32_t a;
    asm("{ .reg .u64 t; cvta.to.shared.u64 t, %1; cvt.u32.u64 %0, t; }" : "=r"(a) : "l"(p));
    return a;
}
#define CP_COMMIT() asm volatile("cp.async.commit_group;" ::: "memory")
#define CP_WAIT2()  asm volatile("cp.async.wait_group 2;" ::: "memory")
#define CP_WAIT1()  asm volatile("cp.async.wait_group 1;" ::: "memory")
#define CP_WAIT0()  asm volatile("cp.async.wait_group 0;" ::: "memory")

#define LDSM_X4(r0,r1,r2,r3,addr) \
    asm volatile("ldmatrix.sync.aligned.m8n8.x4.shared.b16 {%0,%1,%2,%3}, [%4];" \
                 : "=r"(r0), "=r"(r1), "=r"(r2), "=r"(r3) : "r"(addr))
#define LDSM_X2(r0,r1,addr) \
    asm volatile("ldmatrix.sync.aligned.m8n8.x2.shared.b16 {%0,%1}, [%2];" \
                 : "=r"(r0), "=r"(r1) : "r"(addr))

__device__ __forceinline__ void mma_f16f32(float& c0, float& c1, float& c2, float& c3,
                                           uint32_t a0, uint32_t a1, uint32_t a2, uint32_t a3,
                                           uint32_t b0, uint32_t b1) {
    asm volatile("mma.sync.aligned.m16n8k16.row.col.f32.f16.f16.f32 "
                 "{%0,%1,%2,%3}, {%4,%5,%6,%7}, {%8,%9}, {%0,%1,%2,%3};"
                 : "+f"(c0), "+f"(c1), "+f"(c2), "+f"(c3)
                 : "r"(a0), "r"(a1), "r"(a2), "r"(a3), "r"(b0), "r"(b1));
}

// ---- HMMA GEMM, f32 acc, ldmatrix fragments, 3-stage cp.async ----
#define LDK 72
#define STAGE_E (128 * LDK)
#define GEMM_SMEM (6 * STAGE_E * 2)   // 110592 B (3 stages x (A+B))

__global__ __launch_bounds__(256, 2) void mma_gemm_kernel(
    const __half* __restrict__ A, const __half* __restrict__ Bw,
    const float* __restrict__ bias, const float* __restrict__ res,
    float* __restrict__ outF, __half* __restrict__ outS,
    int Mreal, int N, int K, int act)
{
    extern __shared__ __half smem[];
    int tid = threadIdx.x;
    int wid = tid >> 5, lane = tid & 31;
    int warpM = wid & 1, warpN = wid >> 1;
    int gid = lane >> 2, tig = lane & 3;
    int mT = blockIdx.y * 128, nT = blockIdx.x * 128;
    const int C = K / 64;

    const __half* Ab = A + (size_t)mT * K;
    const __half* Bb = Bw + (size_t)nT * K;
    uint32_t sbase = smem_u32(smem);

    int ldrow[4], ldseg[4];
#pragma unroll
    for (int i = 0; i < 4; i++) {
        int c = tid + i * 256;
        ldrow[i] = c >> 3;
        ldseg[i] = c & 7;
    }

    auto load_chunk = [&](int c) {
        int s = c % 3;
        int kOff = c * 64;
        uint32_t sA = sbase + s * (2 * STAGE_E * 2);
        uint32_t sB = sA + STAGE_E * 2;
#pragma unroll
        for (int i = 0; i < 4; i++) {
            int r = ldrow[i], sg = ldseg[i];
            cpasync16(sA + (r * LDK + sg * 8) * 2, Ab + (size_t)r * K + kOff + sg * 8);
            cpasync16(sB + (r * LDK + sg * 8) * 2, Bb + (size_t)r * K + kOff + sg * 8);
        }
        CP_COMMIT();
    };

    float acc[4][4][4];
#pragma unroll
    for (int i = 0; i < 4; i++)
#pragma unroll
        for (int j = 0; j < 4; j++)
#pragma unroll
            for (int k = 0; k < 4; k++) acc[i][j][k] = 0.0f;

    load_chunk(0);
    if (C > 1) load_chunk(1);
    if (C > 2) load_chunk(2);

    // ldmatrix lane address components
    int lr = lane & 7;
    uint32_t aRow = (uint32_t)(warpM * 64 + lr + ((lane >> 3) & 1) * 8);
    uint32_t aCol = (uint32_t)(((lane >> 4) & 1) * 8);
    uint32_t bRow = (uint32_t)(warpN * 32 + lr);
    uint32_t bCol = (uint32_t)(((lane >> 3) & 1) * 8);

    for (int c = 0; c < C; c++) {
        int rem = C - 1 - c;
        if (rem >= 2) CP_WAIT2(); else if (rem == 1) CP_WAIT1(); else CP_WAIT0();
        __syncthreads();
        uint32_t sAaddr = sbase + (c % 3) * (2 * STAGE_E * 2);
        uint32_t sBaddr = sAaddr + STAGE_E * 2;
#pragma unroll
        for (int ks = 0; ks < 4; ks++) {
            uint32_t kk0 = ks * 16;
            uint32_t a[4][4], b[4][2];
#pragma unroll
            for (int mt = 0; mt < 4; mt++)
                LDSM_X4(a[mt][0], a[mt][1], a[mt][2], a[mt][3],
                        sAaddr + ((aRow + mt * 16) * LDK + kk0 + aCol) * 2);
#pragma unroll
            for (int nt = 0; nt < 4; nt++)
                LDSM_X2(b[nt][0], b[nt][1],
                        sBaddr + ((bRow + nt * 8) * LDK + kk0 + bCol) * 2);
#pragma unroll
            for (int mt = 0; mt < 4; mt++)
#pragma unroll
                for (int nt = 0; nt < 4; nt++)
                    mma_f16f32(acc[mt][nt][0], acc[mt][nt][1], acc[mt][nt][2], acc[mt][nt][3],
                               a[mt][0], a[mt][1], a[mt][2], a[mt][3], b[nt][0], b[nt][1]);
        }
        __syncthreads();
        if (c + 3 < C) load_chunk(c + 3);
    }

#pragma unroll
    for (int mt = 0; mt < 4; mt++) {
#pragma unroll
        for (int half_ = 0; half_ < 2; half_++) {
            int row = mT + warpM * 64 + mt * 16 + gid + half_ * 8;
            if (row >= Mreal) continue;
#pragma unroll
            for (int nt = 0; nt < 4; nt++) {
                int col = nT + warpN * 32 + nt * 8 + tig * 2;
                float v0 = acc[mt][nt][half_ * 2 + 0];
                float v1 = acc[mt][nt][half_ * 2 + 1];
                float2 bb = *(const float2*)(bias + col);
                v0 += bb.x; v1 += bb.y;
                if (act == 1) {
                    float u;
                    u = v0; v0 = 0.5f*u*(1.0f + tanhf(0.7978845608028654f*(u + 0.044715f*u*u*u)));
                    u = v1; v1 = 0.5f*u*(1.0f + tanhf(0.7978845608028654f*(u + 0.044715f*u*u*u)));
                }
                if (res) {
                    float2 rr = *(const float2*)(res + (size_t)row * N + col);
                    v0 += rr.x; v1 += rr.y;
                }
                if (outF) *(float2*)(outF + (size_t)row * N + col) = make_float2(v0, v1);
                if (outS) {
                    union { __half h[2]; uint32_t u; } P;
                    P.h[0] = __float2half_rn(v0);
                    P.h[1] = __float2half_rn(v1);
                    *(uint32_t*)(outS + (size_t)row * N + col) = P.u;
                }
            }
        }
    }
}

// ---- tensor-core attention, register softmax, 2 CTA/SM ----
#define SP 224
#define LDQK 72
#define LDV 232
#define ATTN_SMEM ((64*LDQK + SP*LDQK + 64*LDV + 64*LDV) * 2 + 2 * 64 * 4 * 4)

__global__ __launch_bounds__(256, 2) void attn_kernel(const __half* __restrict__ qkv,
                                                      __half* __restrict__ yH) {
    extern __shared__ char smc[];
    __half* Qs = (__half*)smc;
    __half* Ks = Qs + 64 * LDQK;
    __half* Vt = Ks + SP * LDQK;
    __half* Pm = Vt + 64 * LDV;
    float*  redA = (float*)(Pm + 64 * LDV);
    float*  redB = redA + 64 * 4;

    int h = blockIdx.x, b = blockIdx.y;
    int tid = threadIdx.x, wid = tid >> 5, lane = tid & 31;
    int gid = lane >> 2, tig = lane & 3;
    int wm = wid >> 2, wn = wid & 3;

    const __half* base = qkv + (size_t)(b * SEQ) * (3 * DMODEL) + h * DHEAD;

    for (int idx = tid; idx < SP * 32; idx += 256) {
        int t = idx >> 5, p = idx & 31;
        uint32_t kv = 0;
        if (t < SEQ) kv = *(const uint32_t*)(base + (size_t)t * (3 * DMODEL) + DMODEL + 2 * p);
        *(uint32_t*)(Ks + t * LDQK + 2 * p) = kv;
    }
    for (int idx = tid; idx < SP * 16; idx += 256) {
        int t = idx >> 4, dq = idx & 15;
        int d = dq * 4;
        __half v[4] = {__float2half(0.f), __float2half(0.f), __float2half(0.f), __float2half(0.f)};
        if (t < SEQ) *(uint2*)v = *(const uint2*)(base + (size_t)t * (3 * DMODEL) + 2 * DMODEL + d);
        Vt[(d + 0) * LDV + t] = v[0];
        Vt[(d + 1) * LDV + t] = v[1];
        Vt[(d + 2) * LDV + t] = v[2];
        Vt[(d + 3) * LDV + t] = v[3];
    }
    __syncthreads();

    for (int q0 = 0; q0 < SP; q0 += 64) {
        for (int idx = tid; idx < 64 * 32; idx += 256) {
            int rl = idx >> 5, p = idx & 31;
            int t = q0 + rl;
            uint32_t qv = 0;
            if (t < SEQ) {
                __half2 q2 = *(const __half2*)(base + (size_t)t * (3 * DMODEL) + 2 * p);
                float2 qf = __half22float2(q2);
                __half2 qs = __floats2half2_rn(qf.x * 0.125f, qf.y * 0.125f);
                qv = *(uint32_t*)&qs;
            }
            *(uint32_t*)(Qs + rl * LDQK + 2 * p) = qv;
        }
        __syncthreads();

        float c[2][7][4];
#pragma unroll
        for (int mi = 0; mi < 2; mi++)
#pragma unroll
            for (int ni = 0; ni < 7; ni++)
#pragma unroll
                for (int k = 0; k < 4; k++) c[mi][ni][k] = 0.0f;
#pragma unroll
        for (int ks = 0; ks < 4; ks++) {
            int kk = ks * 16 + tig * 2;
            uint32_t a[2][4], bf[7][2];
#pragma unroll
            for (int mi = 0; mi < 2; mi++) {
                const __half* ap = Qs + (wm * 32 + mi * 16 + gid) * LDQK + kk;
                a[mi][0] = *(const uint32_t*)(ap);
                a[mi][1] = *(const uint32_t*)(ap + 8 * LDQK);
                a[mi][2] = *(const uint32_t*)(ap + 8);
                a[mi][3] = *(const uint32_t*)(ap + 8 * LDQK + 8);
            }
#pragma unroll
            for (int ni = 0; ni < 7; ni++) {
                const __half* bp = Ks + (wn * 56 + ni * 8 + gid) * LDQK + kk;
                bf[ni][0] = *(const uint32_t*)(bp);
                bf[ni][1] = *(const uint32_t*)(bp + 8);
            }
#pragma unroll
            for (int mi = 0; mi < 2; mi++)
#pragma unroll
                for (int ni = 0; ni < 7; ni++)
                    mma_f16f32(c[mi][ni][0], c[mi][ni][1], c[mi][ni][2], c[mi][ni][3],
                               a[mi][0], a[mi][1], a[mi][2], a[mi][3], bf[ni][0], bf[ni][1]);
        }

#pragma unroll
        for (int ni = 0; ni < 7; ni++) {
            int col = wn * 56 + ni * 8 + 2 * tig;
            if (col >= SEQ) { c[0][ni][0] = c[0][ni][2] = c[1][ni][0] = c[1][ni][2] = -1e30f; }
            if (col + 1 >= SEQ) { c[0][ni][1] = c[0][ni][3] = c[1][ni][1] = c[1][ni][3] = -1e30f; }
        }

#pragma unroll
        for (int mi = 0; mi < 2; mi++) {
            float m0 = -1e30f, m1 = -1e30f;
#pragma unroll
            for (int ni = 0; ni < 7; ni++) {
                m0 = fmaxf(m0, fmaxf(c[mi][ni][0], c[mi][ni][1]));
                m1 = fmaxf(m1, fmaxf(c[mi][ni][2], c[mi][ni][3]));
            }
#pragma unroll
            for (int o = 1; o <= 2; o <<= 1) {
                m0 = fmaxf(m0, __shfl_xor_sync(0xffffffffu, m0, o));
                m1 = fmaxf(m1, __shfl_xor_sync(0xffffffffu, m1, o));
            }
            if (tig == 0) {
                int rr = wm * 32 + mi * 16 + gid;
                redA[rr * 4 + wn] = m0;
                redA[(rr + 8) * 4 + wn] = m1;
            }
        }
        __syncthreads();

#pragma unroll
        for (int mi = 0; mi < 2; mi++) {
            int rr = wm * 32 + mi * 16 + gid;
            float4 ra = *(const float4*)(redA + rr * 4);
            float4 rb = *(const float4*)(redA + (rr + 8) * 4);
            float m0 = fmaxf(fmaxf(ra.x, ra.y), fmaxf(ra.z, ra.w));
            float m1 = fmaxf(fmaxf(rb.x, rb.y), fmaxf(rb.z, rb.w));
            float s0 = 0.0f, s1 = 0.0f;
#pragma unroll
            for (int ni = 0; ni < 7; ni++) {
                float e0 = __expf(c[mi][ni][0] - m0);
                float e1 = __expf(c[mi][ni][1] - m0);
                float e2 = __expf(c[mi][ni][2] - m1);
                float e3 = __expf(c[mi][ni][3] - m1);
                c[mi][ni][0] = e0; c[mi][ni][1] = e1; c[mi][ni][2] = e2; c[mi][ni][3] = e3;
                s0 += e0 + e1; s1 += e2 + e3;
            }
#pragma unroll
            for (int o = 1; o <= 2; o <<= 1) {
                s0 += __shfl_xor_sync(0xffffffffu, s0, o);
                s1 += __shfl_xor_sync(0xffffffffu, s1, o);
            }
            if (tig == 0) {
                redB[rr * 4 + wn] = s0;
                redB[(rr + 8) * 4 + wn] = s1;
            }
        }
        __syncthreads();

#pragma unroll
        for (int mi = 0; mi < 2; mi++) {
            int rr = wm * 32 + mi * 16 + gid;
            float4 ra = *(const float4*)(redB + rr * 4);
            float4 rb = *(const float4*)(redB + (rr + 8) * 4);
            float i0 = 1.0f / (ra.x + ra.y + ra.z + ra.w);
            float i1 = 1.0f / (rb.x + rb.y + rb.z + rb.w);
#pragma unroll
            for (int ni = 0; ni < 7; ni++) {
                int col = wn * 56 + ni * 8 + 2 * tig;
                __half2 p0 = __floats2half2_rn(c[mi][ni][0] * i0, c[mi][ni][1] * i0);
                __half2 p1 = __floats2half2_rn(c[mi][ni][2] * i1, c[mi][ni][3] * i1);
                *(__half2*)(Pm + rr * LDV + col) = p0;
                *(__half2*)(Pm + (rr + 8) * LDV + col) = p1;
            }
        }
        __syncthreads();

        float o[2][2][4];
#pragma unroll
        for (int mi = 0; mi < 2; mi++)
#pragma unroll
            for (int ni = 0; ni < 2; ni++)
#pragma unroll
                for (int k = 0; k < 4; k++) o[mi][ni][k] = 0.0f;
#pragma unroll
        for (int ks = 0; ks < 14; ks++) {
            int kk = ks * 16 + tig * 2;
            uint32_t a[2][4], bf[2][2];
#pragma unroll
            for (int mi = 0; mi < 2; mi++) {
                const __half* ap = Pm + (wm * 32 + mi * 16 + gid) * LDV + kk;
                a[mi][0] = *(const uint32_t*)(ap);
                a[mi][1] = *(const uint32_t*)(ap + 8 * LDV);
                a[mi][2] = *(const uint32_t*)(ap + 8);
                a[mi][3] = *(const uint32_t*)(ap + 8 * LDV + 8);
            }
#pragma unroll
            for (int ni = 0; ni < 2; ni++) {
                const __half* bp = Vt + (wn * 16 + ni * 8 + gid) * LDV + kk;
                bf[ni][0] = *(const uint32_t*)(bp);
                bf[ni][1] = *(const uint32_t*)(bp + 8);
            }
#pragma unroll
            for (int mi = 0; mi < 2; mi++)
#pragma unroll
                for (int ni = 0; ni < 2; ni++)
                    mma_f16f32(o[mi][ni][0], o[mi][ni][1], o[mi][ni][2], o[mi][ni][3],
                               a[mi][0], a[mi][1], a[mi][2], a[mi][3], bf[ni][0], bf[ni][1]);
        }
#pragma unroll
        for (int mi = 0; mi < 2; mi++) {
#pragma unroll
            for (int half_ = 0; half_ < 2; half_++) {
                int q = q0 + wm * 32 + mi * 16 + gid + half_ * 8;
                if (q >= SEQ) continue;
#pragma unroll
                for (int ni = 0; ni < 2; ni++) {
                    int d = wn * 16 + ni * 8 + 2 * tig;
                    union { __half h[2]; uint32_t u; } P2;
                    P2.h[0] = __float2half_rn(o[mi][ni][half_ * 2 + 0]);
                    P2.h[1] = __float2half_rn(o[mi][ni][half_ * 2 + 1]);
                    *(uint32_t*)(yH + (size_t)(b * SEQ + q) * DMODEL + h * DHEAD + d) = P2.u;
                }
            }
        }
        __syncthreads();
    }
}

// ---- weight convert+transpose: 64x64 tiles, vectorized ----
__global__ __launch_bounds__(256) void wconv_kernel(const float* __restrict__ W,
                                                    __half* __restrict__ out,
                                                    int K, int N) {
    __shared__ float t[64][65];
    W   += (size_t)blockIdx.z * K * N;
    out += (size_t)blockIdx.z * N * K;
    int k0 = blockIdx.y * 64, n0 = blockIdx.x * 64;
    int tid = threadIdx.x;
#pragma unroll
    for (int i = 0; i < 4; i++) {
        int idx = tid + i * 256;
        int r = idx >> 4, c4 = (idx & 15) * 4;
        float4 v = *(const float4*)(W + (size_t)(k0 + r) * N + n0 + c4);
        t[r][c4 + 0] = v.x; t[r][c4 + 1] = v.y; t[r][c4 + 2] = v.z; t[r][c4 + 3] = v.w;
    }
    __syncthreads();
#pragma unroll
    for (int i = 0; i < 4; i++) {
        int idx = tid + i * 256;
        int n = idx >> 4, kq = (idx & 15) * 4;
        __half2 h01 = __floats2half2_rn(t[kq + 0][n], t[kq + 1][n]);
        __half2 h23 = __floats2half2_rn(t[kq + 2][n], t[kq + 3][n]);
        uint2 u;
        u.x = *(uint32_t*)&h01;
        u.y = *(uint32_t*)&h23;
        *(uint2*)(out + (size_t)(n0 + n) * K + k0 + kq) = u;
    }
}

// ---- patch extraction ----
__global__ __launch_bounds__(256) void patch_kernel(const float* __restrict__ img,
                                                    __half* __restrict__ out) {
    int idx = blockIdx.x * 256 + threadIdx.x;
    if (idx >= M_PAT * DMODEL) return;
    int i = idx % DMODEL, row = idx / DMODEL;
    int p = row % NTOK, b = row / NTOK;
    int c = i >> 8, rem = i & 255, iy = rem >> 4, ix = rem & 15;
    int py = p / 14, px = p % 14;
    float v = img[(((size_t)(b*3 + c) * 224) + py*16 + iy) * 224 + px*16 + ix];
    out[idx] = __float2half_rn(v);
}

// ---- embed ----
__global__ __launch_bounds__(256) void embed_kernel(const float* __restrict__ tok,
                                                    const float* __restrict__ v_class,
                                                    float* __restrict__ x) {
    int idx = blockIdx.x * 256 + threadIdx.x;
    if (idx >= M_ALL * DMODEL) return;
    int d = idx % DMODEL, r = idx / DMODEL;
    int s = r % SEQ, b = r / SEQ;
    float t = (s == 0) ? v_class[d] : tok[(size_t)(b * NTOK + s - 1) * DMODEL + d];
    float ang = (float)s * __expf((float)d * (-9.210340371976184f / (float)DMODEL));
    x[idx] = t + (((d & 1) == 0) ? sinf(ang) : cosf(ang));
}

// ---- LayerNorm: warp per row ----
__global__ __launch_bounds__(256) void ln_kernel(const float* __restrict__ x,
                                                 const float* __restrict__ gamma,
                                                 const float* __restrict__ beta,
                                                 __half* __restrict__ outH) {
    int warp = threadIdx.x >> 5, lane = threadIdx.x & 31;
    int row = blockIdx.x * 8 + warp;
    const float4* xr = (const float4*)(x + (size_t)row * DMODEL);
    float4 v[6];
    float sum = 0.0f;
#pragma unroll
    for (int j = 0; j < 6; j++) {
        v[j] = xr[lane + 32 * j];
        sum += v[j].x + v[j].y + v[j].z + v[j].w;
    }
#pragma unroll
    for (int o = 16; o > 0; o >>= 1) sum += __shfl_xor_sync(0xffffffffu, sum, o);
    float mean = sum * (1.0f / DMODEL);
    float var = 0.0f;
#pragma unroll
    for (int j = 0; j < 6; j++) {
        float a = v[j].x - mean, b = v[j].y - mean, c = v[j].z - mean, d = v[j].w - mean;
        var += a*a + b*b + c*c + d*d;
    }
#pragma unroll
    for (int o = 16; o > 0; o >>= 1) var += __shfl_xor_sync(0xffffffffu, var, o);
    float rstd = rsqrtf(var * (1.0f / DMODEL) + 1e-5f);

    const float4* gr = (const float4*)gamma;
    const float4* br = (const float4*)beta;
    uint2* orow = (uint2*)(outH + (size_t)row * DMODEL);
#pragma unroll
    for (int j = 0; j < 6; j++) {
        float4 g = gr[lane + 32 * j], bb = br[lane + 32 * j];
        float o0 = (v[j].x - mean) * rstd * g.x + bb.x;
        float o1 = (v[j].y - mean) * rstd * g.y + bb.y;
        float o2 = (v[j].z - mean) * rstd * g.z + bb.z;
        float o3 = (v[j].w - mean) * rstd * g.w + bb.w;
        __half2 h01 = __floats2half2_rn(o0, o1);
        __half2 h23 = __floats2half2_rn(o2, o3);
        uint2 u;
        u.x = *(uint32_t*)&h01;
        u.y = *(uint32_t*)&h23;
        orow[lane + 32 * j] = u;
    }
}

// ---- KAN head ----
__global__ __launch_bounds__(256) void head_kernel(const float* __restrict__ x,
                                                   const float* __restrict__ amp,
                                                   float* __restrict__ logits) {
    __shared__ float sines[4 * DMODEL];
    int b = blockIdx.x, tid = threadIdx.x;
    const float* xr = x + (size_t)b * SEQ * DMODEL;
    const float PI = 3.14159265358979323846f;
    for (int i = tid; i < DMODEL; i += 256) {
        float xv = xr[i], ph = (float)i * (PI / (float)DMODEL);
#pragma unroll
        for (int g = 0; g < 4; g++) sines[g*DMODEL + i] = sinf(xv * (float)(g+1) + ph);
    }
    __syncthreads();
    int warp = tid >> 5, lane = tid & 31;
    int o = blockIdx.y * 8 + warp;
    if (o < NOUT) {
        const float* ar = amp + (size_t)o * 4 * DMODEL;
        float acc = 0.0f;
        for (int i = lane; i < 4*DMODEL; i += 32) acc = fmaf(sines[i], ar[i], acc);
#pragma unroll
        for (int of = 16; of > 0; of >>= 1) acc += __shfl_xor_sync(0xffffffffu, acc, of);
        if (lane == 0) logits[(size_t)b*NOUT + o] = acc * (1.0f / 55.42562584220407f);
    }
}

// ---- softmax ----
__global__ __launch_bounds__(256) void softmax_kernel(const float* __restrict__ logits,
                                                      float* __restrict__ out) {
    int b = blockIdx.x, tid = threadIdx.x;
    const float* lr = logits + (size_t)b * NOUT;
    __shared__ float red[256];
    float m = -1e30f;
    for (int i = tid; i < NOUT; i += 256) m = fmaxf(m, lr[i]);
    red[tid] = m; __syncthreads();
    for (int o = 128; o > 0; o >>= 1) { if (tid < o) red[tid] = fmaxf(red[tid], red[tid+o]); __syncthreads(); }
    m = red[0]; __syncthreads();
    float s = 0.0f;
    for (int i = tid; i < NOUT; i += 256) s += expf(lr[i] - m);
    red[tid] = s; __syncthreads();
    for (int o = 128; o > 0; o >>= 1) { if (tid < o) red[tid] += red[tid+o]; __syncthreads(); }
    float inv = 1.0f / red[0];
    for (int i = tid; i < NOUT; i += 256) out[(size_t)b*NOUT + i] = expf(lr[i] - m) * inv;
}

// ---- launch ----
extern "C" void kernel_launch(void* const* d_in, const int* in_sizes, int n_in,
                              void* d_out, int out_size) {
    (void)in_sizes; (void)n_in; (void)out_size;
    const float* images    = (const float*)d_in[0];
    const float* v_class   = (const float*)d_in[1];
    const float* W_map     = (const float*)d_in[2];
    const float* b_map     = (const float*)d_in[3];
    const float* ln1_scale = (const float*)d_in[4];
    const float* ln1_bias  = (const float*)d_in[5];
    const float* Wqkv      = (const float*)d_in[6];
    const float* bqkv      = (const float*)d_in[7];
    const float* Wo        = (const float*)d_in[8];
    const float* bo        = (const float*)d_in[9];
    const float* ln2_scale = (const float*)d_in[10];
    const float* ln2_bias  = (const float*)d_in[11];
    const float* Wmlp1     = (const float*)d_in[12];
    const float* bmlp1     = (const float*)d_in[13];
    const float* Wmlp2     = (const float*)d_in[14];
    const float* bmlp2     = (const float*)d_in[15];
    const float* kan_amp   = (const float*)d_in[16];
    float* out = (float*)d_out;

    void *p0,*p1,*p2,*p3,*p4,*p5,*p6,*p7,*p8,*p9,*p10,*p11,*p12;
    cudaGetSymbolAddress(&p0, g_patch_h); cudaGetSymbolAddress(&p1, g_tok);
    cudaGetSymbolAddress(&p2, g_x);       cudaGetSymbolAddress(&p3, g_h_h);
    cudaGetSymbolAddress(&p4, g_qkv_h);   cudaGetSymbolAddress(&p5, g_y_h);
    cudaGetSymbolAddress(&p6, g_ff_h);    cudaGetSymbolAddress(&p7, g_logits);
    cudaGetSymbolAddress(&p8, g_wmap_t);  cudaGetSymbolAddress(&p9, g_wqkv_t);
    cudaGetSymbolAddress(&p10, g_wo_t);   cudaGetSymbolAddress(&p11, g_wm1_t);
    cudaGetSymbolAddress(&p12, g_wm2_t);
    __half* patch_h = (__half*)p0;
    float* tok = (float*)p1;
    float* x   = (float*)p2;
    __half* h_h = (__half*)p3;
    __half* qkv_h = (__half*)p4;
    __half* y_h = (__half*)p5;
    __half* ff_h = (__half*)p6;
    float* logits = (float*)p7;
    __half* wmap_t = (__half*)p8;
    __half* wqkv_t = (__half*)p9;
    __half* wo_t   = (__half*)p10;
    __half* wm1_t  = (__half*)p11;
    __half* wm2_t  = (__half*)p12;

    cudaFuncSetAttribute(attn_kernel, cudaFuncAttributeMaxDynamicSharedMemorySize, (int)ATTN_SMEM);
    cudaFuncSetAttribute(mma_gemm_kernel, cudaFuncAttributeMaxDynamicSharedMemorySize, GEMM_SMEM);

    wconv_kernel<<<dim3(DMODEL/64, DMODEL/64, 1), 256>>>(W_map, wmap_t, DMODEL, DMODEL);
    wconv_kernel<<<dim3(3*DMODEL/64, DMODEL/64, NBLK), 256>>>(Wqkv, wqkv_t, DMODEL, 3*DMODEL);
    wconv_kernel<<<dim3(DMODEL/64, DMODEL/64, NBLK), 256>>>(Wo, wo_t, DMODEL, DMODEL);
    wconv_kernel<<<dim3(FFDIM/64, DMODEL/64, NBLK), 256>>>(Wmlp1, wm1_t, DMODEL, FFDIM);
    wconv_kernel<<<dim3(DMODEL/64, FFDIM/64, NBLK), 256>>>(Wmlp2, wm2_t, FFDIM, DMODEL);

    patch_kernel<<<(M_PAT*DMODEL + 255)/256, 256>>>(images, patch_h);
    mma_gemm_kernel<<<dim3(DMODEL/128, M_PAT/128), 256, GEMM_SMEM>>>(
        patch_h, wmap_t, b_map, nullptr, tok, nullptr, M_PAT, DMODEL, DMODEL, 0);
    embed_kernel<<<(M_ALL*DMODEL + 255)/256, 256>>>(tok, v_class, x);

    for (int blk = 0; blk < NBLK; blk++) {
        ln_kernel<<<M_ALL/8, 256>>>(x, ln1_scale + (size_t)blk*DMODEL, ln1_bias + (size_t)blk*DMODEL, h_h);
        mma_gemm_kernel<<<dim3(3*DMODEL/128, MTILES), 256, GEMM_SMEM>>>(
            h_h, wqkv_t + (size_t)blk*3*DMODEL*DMODEL, bqkv + (size_t)blk*3*DMODEL,
            nullptr, nullptr, qkv_h, M_ALL, 3*DMODEL, DMODEL, 0);
        attn_kernel<<<dim3(NHEAD, BATCH), 256, ATTN_SMEM>>>(qkv_h, y_h);
        mma_gemm_kernel<<<dim3(DMODEL/128, MTILES), 256, GEMM_SMEM>>>(
            y_h, wo_t + (size_t)blk*DMODEL*DMODEL, bo + (size_t)blk*DMODEL,
            x, x, nullptr, M_ALL, DMODEL, DMODEL, 0);
        ln_kernel<<<M_ALL/8, 256>>>(x, ln2_scale + (size_t)blk*DMODEL, ln2_bias + (size_t)blk*DMODEL, h_h);
        mma_gemm_kernel<<<dim3(FFDIM/128, MTILES), 256, GEMM_SMEM>>>(
            h_h, wm1_t + (size_t)blk*FFDIM*DMODEL, bmlp1 + (size_t)blk*FFDIM,
            nullptr, nullptr, ff_h, M_ALL, FFDIM, DMODEL, 1);
        mma_gemm_kernel<<<dim3(DMODEL/128, MTILES), 256, GEMM_SMEM>>>(
            ff_h, wm2_t + (size_t)blk*DMODEL*FFDIM, bmlp2 + (size_t)blk*DMODEL,
            x, x, nullptr, M_ALL, DMODEL, FFDIM, 0);
    }

    head_kernel<<<dim3(BATCH, 125), 256>>>(x, kan_amp, logits);
    softmax_kernel<<<BATCH, 256>>>(logits, out);
}